// round 3
// baseline (speedup 1.0000x reference)
#include <cuda_runtime.h>
#include <math.h>

// ---------------- problem constants ----------------
#define Bz    64
#define LQ    52
#define Dm    512
#define NH    8
#define DKh   64
#define NPIXc 196
#define ENCc  2048
#define FFc   2048
#define NLc   6
#define MROW  (Bz*LQ)       // 3328
#define EROW  (Bz*NPIXc)    // 12544
#define VOC   32000

// ---------------- device scratch ----------------
__device__ float g_x[MROW*Dm];
__device__ float g_y[MROW*Dm];
__device__ float g_q[MROW*Dm];
__device__ float g_k[EROW*Dm];
__device__ float g_v[EROW*Dm];
__device__ float g_ctx[MROW*Dm];
__device__ float g_h[MROW*FFc];
__device__ int   g_order[Bz];
__device__ int   g_caps[MROW];

// ---------------- SGEMM: 128x128x8, 8x8 per thread ----------------
#define BM 128
#define BN 128
#define BK 8
#define TM 8
#define TN 8

template<bool TRANSB, bool RELU, bool HASBIAS>
__global__ __launch_bounds__(256)
void sgemm_kernel(const float* __restrict__ A, const float* __restrict__ B,
                  const float* __restrict__ bias, float* __restrict__ C,
                  int M, int N, int K) {
    __shared__ float As[BK][BM];
    __shared__ float Bs[BK][BN];
    const int bx = blockIdx.x;            // N tile
    const int by = blockIdx.y;            // M tile
    const int tid = threadIdx.x;          // 256
    const int tr = tid >> 4;              // 0..15
    const int tc = tid & 15;              // 0..15

    const float* Ab = A + (size_t)by * BM * K;
    float acc[TM][TN];
    #pragma unroll
    for (int i = 0; i < TM; i++)
        #pragma unroll
        for (int j = 0; j < TN; j++) acc[i][j] = 0.f;

    const int a_r = tid >> 1;             // 0..127
    const int a_c = (tid & 1) * 4;        // 0 or 4
    const int b_r = tid >> 5;             // 0..7
    const int b_c = (tid & 31) * 4;       // 0..124

    for (int k0 = 0; k0 < K; k0 += BK) {
        float4 av = *(const float4*)(Ab + (size_t)a_r * K + k0 + a_c);
        As[a_c+0][a_r] = av.x; As[a_c+1][a_r] = av.y;
        As[a_c+2][a_r] = av.z; As[a_c+3][a_r] = av.w;
        if (!TRANSB) {
            float4 bv = *(const float4*)(B + (size_t)(k0 + b_r) * N + (size_t)bx * BN + b_c);
            *(float4*)&Bs[b_r][b_c] = bv;
        } else {
            // B stored [N, K] row-major
            float4 bv = *(const float4*)(B + (size_t)(bx * BN + a_r) * K + k0 + a_c);
            Bs[a_c+0][a_r] = bv.x; Bs[a_c+1][a_r] = bv.y;
            Bs[a_c+2][a_r] = bv.z; Bs[a_c+3][a_r] = bv.w;
        }
        __syncthreads();
        #pragma unroll
        for (int kk = 0; kk < BK; kk++) {
            float rm[TM], rn[TN];
            *(float4*)&rm[0] = *(const float4*)&As[kk][tr*TM];
            *(float4*)&rm[4] = *(const float4*)&As[kk][tr*TM+4];
            *(float4*)&rn[0] = *(const float4*)&Bs[kk][tc*TN];
            *(float4*)&rn[4] = *(const float4*)&Bs[kk][tc*TN+4];
            #pragma unroll
            for (int i = 0; i < TM; i++)
                #pragma unroll
                for (int j = 0; j < TN; j++)
                    acc[i][j] += rm[i] * rn[j];
        }
        __syncthreads();
    }

    #pragma unroll
    for (int i = 0; i < TM; i++) {
        const size_t m = (size_t)by * BM + tr * TM + i;
        #pragma unroll
        for (int j = 0; j < TN; j += 4) {
            const int n = bx * BN + tc * TN + j;
            float4 v;
            v.x = acc[i][j+0]; v.y = acc[i][j+1]; v.z = acc[i][j+2]; v.w = acc[i][j+3];
            if (HASBIAS) {
                v.x += bias[n+0]; v.y += bias[n+1]; v.z += bias[n+2]; v.w += bias[n+3];
            }
            if (RELU) {
                v.x = fmaxf(v.x, 0.f); v.y = fmaxf(v.y, 0.f);
                v.z = fmaxf(v.z, 0.f); v.w = fmaxf(v.w, 0.f);
            }
            *(float4*)(C + m * N + n) = v;
        }
    }
}

// ---------------- stable descending argsort (B=64) ----------------
__global__ void sort_kernel(const int* __restrict__ lens, int* __restrict__ order) {
    __shared__ int l[Bz];
    int b = threadIdx.x;
    l[b] = lens[b];
    __syncthreads();
    int myl = l[b], rank = 0;
    #pragma unroll
    for (int j = 0; j < Bz; j++)
        rank += (l[j] > myl) || (l[j] == myl && j < b);
    order[rank] = b;
}

__global__ void gather_caps_kernel(const int* __restrict__ caps, const int* __restrict__ order,
                                   int* __restrict__ out) {
    int idx = blockIdx.x * 256 + threadIdx.x;
    if (idx >= MROW) return;
    int b = idx / LQ, t = idx % LQ;
    out[idx] = caps[order[b] * LQ + t];
}

// ---------------- embedding ----------------
__global__ void embed_kernel(const int* __restrict__ caps, const float* __restrict__ tgt,
                             const float* __restrict__ pos, float* __restrict__ x) {
    int idx = blockIdx.x * 256 + threadIdx.x;
    if (idx >= MROW * Dm) return;
    int d = idx & (Dm - 1);
    int rt = idx >> 9;
    int t = rt % LQ;
    int cap = caps[rt];
    x[idx] = tgt[(size_t)cap * Dm + d] + pos[t * Dm + d];
}

// ---------------- self attention (fused, K/V in smem) ----------------
__global__ __launch_bounds__(64)
void self_attn_kernel(const float* __restrict__ Q, const float* __restrict__ Km,
                      const float* __restrict__ Vm, const int* __restrict__ caps,
                      float* __restrict__ ctx) {
    int b = blockIdx.x >> 3;
    int h = blockIdx.x & 7;
    int tid = threadIdx.x;  // 64
    __shared__ float Ks[LQ][DKh], Vs[LQ][DKh];
    __shared__ float qrow[DKh], p[LQ], red[64];
    __shared__ int pad[LQ];
    for (int i = tid; i < LQ * DKh; i += 64) {
        int t = i >> 6, d = i & 63;
        size_t src = (size_t)(b * LQ + t) * Dm + h * DKh + d;
        Ks[t][d] = Km[src];
        Vs[t][d] = Vm[src];
    }
    for (int t = tid; t < LQ; t += 64) pad[t] = (caps[b * LQ + t] == 0);
    __syncthreads();

    for (int q = 0; q < LQ; q++) {
        qrow[tid] = Q[(size_t)(b * LQ + q) * Dm + h * DKh + tid];
        __syncthreads();
        float s = -3.0e38f;
        if (tid < LQ) {
            float a = 0.f;
            #pragma unroll
            for (int d = 0; d < DKh; d++) a += qrow[d] * Ks[tid][d];
            s = a * 0.125f;
            if (tid > q || pad[tid]) s = -1e9f;
        }
        red[tid] = s; __syncthreads();
        #pragma unroll
        for (int st = 32; st > 0; st >>= 1) {
            if (tid < st) red[tid] = fmaxf(red[tid], red[tid + st]);
            __syncthreads();
        }
        float mx = red[0]; __syncthreads();
        float e = (tid < LQ) ? expf(s - mx) : 0.f;
        if (tid < LQ) p[tid] = e;
        red[tid] = e; __syncthreads();
        #pragma unroll
        for (int st = 32; st > 0; st >>= 1) {
            if (tid < st) red[tid] += red[tid + st];
            __syncthreads();
        }
        float inv = 1.f / red[0];
        __syncthreads();
        float a = 0.f;
        for (int k = 0; k < LQ; k++) a += p[k] * Vs[k][tid];
        ctx[(size_t)(b * LQ + q) * Dm + h * DKh + tid] = a * inv;
        __syncthreads();
    }
}

// ---------------- cross attention (fused, dynamic smem ~101KB) ----------------
extern __shared__ float csm[];
__global__ __launch_bounds__(256)
void cross_attn_kernel(const float* __restrict__ Q, const float* __restrict__ Kc,
                       const float* __restrict__ Vc, const int* __restrict__ order,
                       float* __restrict__ ctx) {
    float* Ks = csm;                       // NPIXc*DKh
    float* Vs = Ks + NPIXc * DKh;          // NPIXc*DKh
    float* qrow = Vs + NPIXc * DKh;        // DKh
    float* p = qrow + DKh;                 // NPIXc
    __shared__ float red[256];
    int b = blockIdx.x >> 3;
    int h = blockIdx.x & 7;
    int tid = threadIdx.x;
    int ob = order[b];
    for (int i = tid; i < NPIXc * DKh; i += 256) {
        int t = i >> 6, d = i & 63;
        size_t src = (size_t)(ob * NPIXc + t) * Dm + h * DKh + d;
        Ks[i] = Kc[src];
        Vs[i] = Vc[src];
    }
    __syncthreads();

    for (int q = 0; q < LQ; q++) {
        if (tid < DKh) qrow[tid] = Q[(size_t)(b * LQ + q) * Dm + h * DKh + tid];
        __syncthreads();
        float s = -3.0e38f;
        if (tid < NPIXc) {
            float a = 0.f;
            #pragma unroll
            for (int d = 0; d < DKh; d++) a += qrow[d] * Ks[tid * DKh + d];
            s = a * 0.125f;
        }
        red[tid] = s; __syncthreads();
        #pragma unroll
        for (int st = 128; st > 0; st >>= 1) {
            if (tid < st) red[tid] = fmaxf(red[tid], red[tid + st]);
            __syncthreads();
        }
        float mx = red[0]; __syncthreads();
        float e = (tid < NPIXc) ? expf(s - mx) : 0.f;
        if (tid < NPIXc) p[tid] = e;
        red[tid] = e; __syncthreads();
        #pragma unroll
        for (int st = 128; st > 0; st >>= 1) {
            if (tid < st) red[tid] += red[tid + st];
            __syncthreads();
        }
        float inv = 1.f / red[0];
        __syncthreads();
        int part = tid >> 6, d = tid & 63;
        float a = 0.f;
        for (int k = part; k < NPIXc; k += 4) a += p[k] * Vs[k * DKh + d];
        red[tid] = a; __syncthreads();
        if (part == 0) {
            float r = red[d] + red[64 + d] + red[128 + d] + red[192 + d];
            ctx[(size_t)(b * LQ + q) * Dm + h * DKh + d] = r * inv;
        }
        __syncthreads();
    }
}

// ---------------- LayerNorm(residual + bias) ----------------
__global__ __launch_bounds__(256)
void ln_residual_kernel(const float* __restrict__ y, const float* __restrict__ bias,
                        const float* __restrict__ xin, float* __restrict__ xout) {
    int r = blockIdx.x, tid = threadIdx.x;
    __shared__ float red[256];
    size_t base = (size_t)r * Dm;
    float v0 = y[base + tid]       + bias[tid]       + xin[base + tid];
    float v1 = y[base + 256 + tid] + bias[256 + tid] + xin[base + 256 + tid];
    red[tid] = v0 + v1; __syncthreads();
    #pragma unroll
    for (int st = 128; st > 0; st >>= 1) {
        if (tid < st) red[tid] += red[tid + st];
        __syncthreads();
    }
    float m = red[0] * (1.f / Dm);
    __syncthreads();
    float d0 = v0 - m, d1 = v1 - m;
    red[tid] = d0 * d0 + d1 * d1; __syncthreads();
    #pragma unroll
    for (int st = 128; st > 0; st >>= 1) {
        if (tid < st) red[tid] += red[tid + st];
        __syncthreads();
    }
    float inv = rsqrtf(red[0] * (1.f / Dm) + 1e-5f);
    xout[base + tid]       = d0 * inv;
    xout[base + 256 + tid] = d1 * inv;
}

// ---------------- host side ----------------
extern "C" void kernel_launch(void* const* d_in, const int* in_sizes, int n_in,
                              void* d_out, int out_size) {
    const float* encoder_out = (const float*)d_in[0];
    const int*   captions    = (const int*)d_in[1];
    const int*   lengths     = (const int*)d_in[2];
    const float* tgt_emb     = (const float*)d_in[3];
    const float* pos_emb     = (const float*)d_in[4];
    const float* sWq = (const float*)d_in[5];  const float* sbq = (const float*)d_in[6];
    const float* sWk = (const float*)d_in[7];  const float* sbk = (const float*)d_in[8];
    const float* sWv = (const float*)d_in[9];  const float* sbv = (const float*)d_in[10];
    const float* sWo = (const float*)d_in[11]; const float* sbo = (const float*)d_in[12];
    const float* eWq = (const float*)d_in[13]; const float* ebq = (const float*)d_in[14];
    const float* eWk = (const float*)d_in[15]; const float* ebk = (const float*)d_in[16];
    const float* eWv = (const float*)d_in[17]; const float* ebv = (const float*)d_in[18];
    const float* eWo = (const float*)d_in[19]; const float* ebo = (const float*)d_in[20];
    const float* fW1 = (const float*)d_in[21]; const float* fb1 = (const float*)d_in[22];
    const float* fW2 = (const float*)d_in[23]; const float* fb2 = (const float*)d_in[24];
    const float* pW  = (const float*)d_in[25];
    float* out = (float*)d_out;

    float *x, *y, *q, *k, *v, *ctx, *h;
    int *order, *caps;
    cudaGetSymbolAddress((void**)&x, g_x);
    cudaGetSymbolAddress((void**)&y, g_y);
    cudaGetSymbolAddress((void**)&q, g_q);
    cudaGetSymbolAddress((void**)&k, g_k);
    cudaGetSymbolAddress((void**)&v, g_v);
    cudaGetSymbolAddress((void**)&ctx, g_ctx);
    cudaGetSymbolAddress((void**)&h, g_h);
    cudaGetSymbolAddress((void**)&order, g_order);
    cudaGetSymbolAddress((void**)&caps, g_caps);

    const int CROSS_SMEM = (NPIXc * DKh * 2 + DKh + NPIXc) * sizeof(float);
    cudaFuncSetAttribute(cross_attn_kernel,
                         cudaFuncAttributeMaxDynamicSharedMemorySize, CROSS_SMEM);

    // prologue
    sort_kernel<<<1, Bz>>>(lengths, order);
    gather_caps_kernel<<<(MROW + 255) / 256, 256>>>(captions, order, caps);
    embed_kernel<<<(MROW * Dm + 255) / 256, 256>>>(caps, tgt_emb, pos_emb, x);

    dim3 gQKV(Dm / BN, MROW / BM);      // (4, 26)
    dim3 gENC(Dm / BN, EROW / BM);      // (4, 98)
    dim3 gFF1(FFc / BN, MROW / BM);     // (16, 26)
    dim3 gFF2(Dm / BN, MROW / BM);      // (4, 26)
    dim3 gPRJ(VOC / BN, MROW / BM);     // (250, 26)

    for (int l = 0; l < NLc; l++) {
        const float* Wq = sWq + (size_t)l * Dm * Dm;  const float* bq = sbq + l * Dm;
        const float* Wk = sWk + (size_t)l * Dm * Dm;  const float* bk = sbk + l * Dm;
        const float* Wv = sWv + (size_t)l * Dm * Dm;  const float* bv = sbv + l * Dm;
        const float* Wo = sWo + (size_t)l * Dm * Dm;  const float* bo = sbo + l * Dm;

        // ---- self attention ----
        sgemm_kernel<false, false, true><<<gQKV, 256>>>(x, Wq, bq, q, MROW, Dm, Dm);
        sgemm_kernel<false, false, true><<<gQKV, 256>>>(x, Wk, bk, k, MROW, Dm, Dm);
        sgemm_kernel<false, false, true><<<gQKV, 256>>>(x, Wv, bv, v, MROW, Dm, Dm);
        self_attn_kernel<<<Bz * NH, 64>>>(q, k, v, caps, ctx);
        sgemm_kernel<false, false, false><<<gQKV, 256>>>(ctx, Wo, nullptr, y, MROW, Dm, Dm);
        ln_residual_kernel<<<MROW, 256>>>(y, bo, x, x);

        // ---- cross attention (project UNSORTED encoder; permute via order) ----
        const float* cWq = eWq + (size_t)l * Dm * Dm;   const float* cbq = ebq + l * Dm;
        const float* cWk = eWk + (size_t)l * ENCc * Dm; const float* cbk = ebk + l * Dm;
        const float* cWv = eWv + (size_t)l * ENCc * Dm; const float* cbv = ebv + l * Dm;
        const float* cWo = eWo + (size_t)l * Dm * Dm;   const float* cbo = ebo + l * Dm;

        sgemm_kernel<false, false, true><<<gQKV, 256>>>(x, cWq, cbq, q, MROW, Dm, Dm);
        sgemm_kernel<false, false, true><<<gENC, 256>>>(encoder_out, cWk, cbk, k, EROW, Dm, ENCc);
        sgemm_kernel<false, false, true><<<gENC, 256>>>(encoder_out, cWv, cbv, v, EROW, Dm, ENCc);
        cross_attn_kernel<<<Bz * NH, 256, CROSS_SMEM>>>(q, k, v, order, ctx);
        sgemm_kernel<false, false, false><<<gQKV, 256>>>(ctx, cWo, nullptr, y, MROW, Dm, Dm);
        ln_residual_kernel<<<MROW, 256>>>(y, cbo, x, x);

        // ---- FFN ----
        const float* W1 = fW1 + (size_t)l * Dm * FFc; const float* b1 = fb1 + l * FFc;
        const float* W2 = fW2 + (size_t)l * FFc * Dm; const float* b2 = fb2 + l * Dm;
        sgemm_kernel<false, true, true><<<gFF1, 256>>>(x, W1, b1, h, MROW, FFc, Dm);
        sgemm_kernel<false, false, false><<<gFF2, 256>>>(h, W2, nullptr, y, MROW, Dm, FFc);
        ln_residual_kernel<<<MROW, 256>>>(y, b2, x, x);
    }

    // ---- vocab projection: out = x @ proj_W^T  (NT) ----
    sgemm_kernel<true, false, false><<<gPRJ, 256>>>(x, pW, nullptr, out, MROW, VOC, Dm);
}

// round 5
// speedup vs baseline: 2.8627x; 2.8627x over previous
#include <cuda_runtime.h>
#include <cuda_bf16.h>
#include <math.h>
#include <stdint.h>

// ---------------- problem constants ----------------
#define Bz    64
#define LQ    52
#define Dm    512
#define NH    8
#define DKh   64
#define NPIXc 196
#define ENCc  2048
#define FFc   2048
#define NLc   6
#define MROW  (Bz*LQ)       // 3328
#define EROW  (Bz*NPIXc)    // 12544
#define VOC   32000

// ---------------- fp32 scratch ----------------
__device__ float g_x[MROW*Dm];
__device__ float g_y[MROW*Dm];
__device__ float g_q[MROW*Dm];
__device__ float g_qkv[MROW*3*Dm];
__device__ float g_kv[EROW*2*Dm];
__device__ float g_ctx[MROW*Dm];
__device__ float g_h[MROW*FFc];
__device__ int   g_order[Bz];
__device__ int   g_caps[MROW];

// ---------------- bf16 (ushort) scratch: activations ----------------
__device__ unsigned short g_ahi[MROW*FFc];
__device__ unsigned short g_alo[MROW*FFc];
__device__ unsigned short g_ehi[EROW*ENCc];
__device__ unsigned short g_elo[EROW*ENCc];

// ---------------- bf16 scratch: transposed weights [N,K] ----------------
__device__ unsigned short g_wsqkv_h[NLc*3*Dm*Dm],  g_wsqkv_l[NLc*3*Dm*Dm];
__device__ unsigned short g_wso_h[NLc*Dm*Dm],      g_wso_l[NLc*Dm*Dm];
__device__ unsigned short g_weq_h[NLc*Dm*Dm],      g_weq_l[NLc*Dm*Dm];
__device__ unsigned short g_wekv_h[NLc*2*Dm*ENCc], g_wekv_l[NLc*2*Dm*ENCc];
__device__ unsigned short g_weo_h[NLc*Dm*Dm],      g_weo_l[NLc*Dm*Dm];
__device__ unsigned short g_wf1_h[NLc*FFc*Dm],     g_wf1_l[NLc*FFc*Dm];
__device__ unsigned short g_wf2_h[NLc*Dm*FFc],     g_wf2_l[NLc*Dm*FFc];
__device__ unsigned short g_wpj_h[VOC*Dm],         g_wpj_l[VOC*Dm];
__device__ float g_bqkv[NLc*3*Dm];
__device__ float g_bkv[NLc*2*Dm];

extern __shared__ float csm[];

// ---------------- cp.async / mma helpers ----------------
__device__ __forceinline__ uint32_t smem_u32(const void* p) {
    uint32_t a;
    asm("{ .reg .u64 t; cvta.to.shared.u64 t, %1; cvt.u32.u64 %0, t; }" : "=r"(a) : "l"(p));
    return a;
}
__device__ __forceinline__ void cpa16(uint32_t s, const void* g) {
    asm volatile("cp.async.cg.shared.global [%0], [%1], 16;" :: "r"(s), "l"(g));
}
#define CP_COMMIT() asm volatile("cp.async.commit_group;" ::: "memory")
#define CP_WAIT0()  asm volatile("cp.async.wait_group 0;" ::: "memory")
#define CP_WAIT1()  asm volatile("cp.async.wait_group 1;" ::: "memory")

#define MMA16816(c, a, b) \
    asm volatile("mma.sync.aligned.m16n8k16.row.col.f32.bf16.bf16.f32 " \
        "{%0,%1,%2,%3}, {%4,%5,%6,%7}, {%8,%9}, {%0,%1,%2,%3};" \
        : "+f"((c)[0]), "+f"((c)[1]), "+f"((c)[2]), "+f"((c)[3]) \
        : "r"((a)[0]), "r"((a)[1]), "r"((a)[2]), "r"((a)[3]), \
          "r"((b)[0]), "r"((b)[1]))

// ============ HMMA bf16x3 GEMM: C[M,N] = A[M,K] * Bt[N,K]^T + bias ============
// CTA tile BMt x 128, K-chunks of 32. cp.async double buffer.
// SMEM row = 32 bf16 (64B) + 16B pad -> 80B stride (20 banks, conflict-free LDS.32).
template<int BMt, bool RELU, bool HASBIAS>
__global__ __launch_bounds__(256, 1)
void mgemm_kernel(const unsigned short* __restrict__ Ahi, const unsigned short* __restrict__ Alo,
                  const unsigned short* __restrict__ Bhi, const unsigned short* __restrict__ Blo,
                  const float* __restrict__ bias, float* __restrict__ C,
                  int M, int N, int K) {
    constexpr int BN = 128;
    constexpr int NWM = BMt / 32;          // warp rows (4 or 2)
    constexpr int NWN = 8 / NWM;           // warp cols (2 or 4)
    constexpr int NTN = BN / NWN;          // warp n-tile (64 or 32)
    constexpr int NF  = NTN / 8;           // n-frags (8 or 4)
    constexpr int ROWB = 80;
    constexpr int ASZ = BMt * ROWB;
    constexpr int BSZ = BN * ROWB;
    constexpr int STAGE = 2 * ASZ + 2 * BSZ;

    char* sm = (char*)csm;
    const int tid = threadIdx.x;
    const int wid = tid >> 5, lane = tid & 31;
    const int wm = wid / NWN, wn = wid % NWN;
    const int gr = lane >> 2, ck = lane & 3;       // ck in element-pairs
    const int m0 = blockIdx.y * BMt;
    const int n0 = blockIdx.x * BN;

    float acc[2][NF][4];
    #pragma unroll
    for (int mt = 0; mt < 2; mt++)
        #pragma unroll
        for (int nf = 0; nf < NF; nf++)
            #pragma unroll
            for (int j = 0; j < 4; j++) acc[mt][nf][j] = 0.f;

    const uint32_t smb = smem_u32(sm);

    auto load_stage = [&](int s, int k0) {
        const uint32_t sb = smb + s * STAGE;
        #pragma unroll
        for (int p = 0; p < BMt * 4 / 256; p++) {
            int id = tid + p * 256;
            int row = id >> 2, cc = id & 3;
            uint32_t so = row * ROWB + cc * 16;
            const size_t go = (size_t)(m0 + row) * K + k0 + cc * 8;
            cpa16(sb + so,        Ahi + go);
            cpa16(sb + ASZ + so,  Alo + go);
        }
        #pragma unroll
        for (int p = 0; p < 2; p++) {
            int id = tid + p * 256;
            int row = id >> 2, cc = id & 3;
            uint32_t so = row * ROWB + cc * 16;
            const size_t go = (size_t)(n0 + row) * K + k0 + cc * 8;
            cpa16(sb + 2*ASZ + so,       Bhi + go);
            cpa16(sb + 2*ASZ + BSZ + so, Blo + go);
        }
    };

    auto compute = [&](int s) {
        const char* base = sm + s * STAGE;
        const char* sAh = base;
        const char* sAl = base + ASZ;
        const char* sBh = base + 2 * ASZ;
        const char* sBl = base + 2 * ASZ + BSZ;
        #pragma unroll
        for (int ks = 0; ks < 2; ks++) {
            const int cby = ks * 32 + ck * 4;    // byte offset of k-pair
            uint32_t ah[2][4], al[2][4], bh[NF][2], bl[NF][2];
            #pragma unroll
            for (int mt = 0; mt < 2; mt++) {
                const int r = wm * 32 + mt * 16 + gr;
                ah[mt][0] = *(const uint32_t*)(sAh + r * ROWB + cby);
                ah[mt][1] = *(const uint32_t*)(sAh + (r + 8) * ROWB + cby);
                ah[mt][2] = *(const uint32_t*)(sAh + r * ROWB + cby + 16);
                ah[mt][3] = *(const uint32_t*)(sAh + (r + 8) * ROWB + cby + 16);
                al[mt][0] = *(const uint32_t*)(sAl + r * ROWB + cby);
                al[mt][1] = *(const uint32_t*)(sAl + (r + 8) * ROWB + cby);
                al[mt][2] = *(const uint32_t*)(sAl + r * ROWB + cby + 16);
                al[mt][3] = *(const uint32_t*)(sAl + (r + 8) * ROWB + cby + 16);
            }
            #pragma unroll
            for (int nf = 0; nf < NF; nf++) {
                const int n = wn * NTN + nf * 8 + gr;
                bh[nf][0] = *(const uint32_t*)(sBh + n * ROWB + cby);
                bh[nf][1] = *(const uint32_t*)(sBh + n * ROWB + cby + 16);
                bl[nf][0] = *(const uint32_t*)(sBl + n * ROWB + cby);
                bl[nf][1] = *(const uint32_t*)(sBl + n * ROWB + cby + 16);
            }
            #pragma unroll
            for (int mt = 0; mt < 2; mt++)
                #pragma unroll
                for (int nf = 0; nf < NF; nf++)
                    MMA16816(acc[mt][nf], ah[mt], bh[nf]);
            #pragma unroll
            for (int mt = 0; mt < 2; mt++)
                #pragma unroll
                for (int nf = 0; nf < NF; nf++)
                    MMA16816(acc[mt][nf], ah[mt], bl[nf]);
            #pragma unroll
            for (int mt = 0; mt < 2; mt++)
                #pragma unroll
                for (int nf = 0; nf < NF; nf++)
                    MMA16816(acc[mt][nf], al[mt], bh[nf]);
        }
    };

    load_stage(0, 0);
    CP_COMMIT();
    const int chunks = K >> 5;
    for (int c = 0; c < chunks; c++) {
        if (c + 1 < chunks) {
            load_stage((c + 1) & 1, (c + 1) << 5);
            CP_COMMIT();
            CP_WAIT1();
        } else {
            CP_WAIT0();
        }
        __syncthreads();
        compute(c & 1);
        __syncthreads();
    }

    // epilogue: registers -> gmem
    #pragma unroll
    for (int mt = 0; mt < 2; mt++) {
        const int r = m0 + wm * 32 + mt * 16 + gr;
        #pragma unroll
        for (int nf = 0; nf < NF; nf++) {
            const int cc = n0 + wn * NTN + nf * 8 + ck * 2;
            float v0 = acc[mt][nf][0], v1 = acc[mt][nf][1];
            float v2 = acc[mt][nf][2], v3 = acc[mt][nf][3];
            if (HASBIAS) {
                float b0 = bias[cc], b1 = bias[cc + 1];
                v0 += b0; v1 += b1; v2 += b0; v3 += b1;
            }
            if (RELU) {
                v0 = fmaxf(v0, 0.f); v1 = fmaxf(v1, 0.f);
                v2 = fmaxf(v2, 0.f); v3 = fmaxf(v3, 0.f);
            }
            float2 w0; w0.x = v0; w0.y = v1;
            float2 w1; w1.x = v2; w1.y = v3;
            *(float2*)(C + (size_t)r * N + cc)       = w0;
            *(float2*)(C + (size_t)(r + 8) * N + cc) = w1;
        }
    }
}

#define SMEM_128 (2 * (2*128*80 + 2*128*80))   // 81920
#define SMEM_64  (2 * (2*64*80  + 2*128*80))   // 61440

// ================= bf16 split helpers =================
__device__ __forceinline__ void bsplit(float x, unsigned short& h, unsigned short& l) {
    __nv_bfloat16 hb = __float2bfloat16(x);
    float r = x - __bfloat162float(hb);
    __nv_bfloat16 lb = __float2bfloat16(r);
    h = __bfloat16_as_ushort(hb);
    l = __bfloat16_as_ushort(lb);
}

__global__ void split_kernel(const float* __restrict__ in, unsigned short* __restrict__ hi,
                             unsigned short* __restrict__ lo, int n4) {
    int i = blockIdx.x * 256 + threadIdx.x;
    if (i >= n4) return;
    float4 v = ((const float4*)in)[i];
    unsigned short h0,h1,h2,h3,l0,l1,l2,l3;
    bsplit(v.x,h0,l0); bsplit(v.y,h1,l1); bsplit(v.z,h2,l2); bsplit(v.w,h3,l3);
    uint2 hv, lv;
    hv.x = (uint32_t)h0 | ((uint32_t)h1 << 16); hv.y = (uint32_t)h2 | ((uint32_t)h3 << 16);
    lv.x = (uint32_t)l0 | ((uint32_t)l1 << 16); lv.y = (uint32_t)l2 | ((uint32_t)l3 << 16);
    *(uint2*)(hi + 4*(size_t)i) = hv;
    *(uint2*)(lo + 4*(size_t)i) = lv;
}

// transpose + split: src W[K,N] row-major -> dst[N,K] hi/lo
__global__ void tsplit_kernel(const float* __restrict__ W, unsigned short* __restrict__ hi,
                              unsigned short* __restrict__ lo, int K, int N) {
    __shared__ float t[32][33];
    const int nb = blockIdx.x * 32, kb = blockIdx.y * 32;
    const int tx = threadIdx.x, ty = threadIdx.y;
    for (int i = ty; i < 32; i += 8)
        t[i][tx] = W[(size_t)(kb + i) * N + nb + tx];
    __syncthreads();
    for (int i = ty; i < 32; i += 8) {
        float x = t[tx][i];
        unsigned short h, l;
        bsplit(x, h, l);
        size_t o = (size_t)(nb + i) * K + kb + tx;
        hi[o] = h; lo[o] = l;
    }
}

__global__ void biascat3_kernel(const float* a, const float* b, const float* c, float* out) {
    int i = blockIdx.x * 256 + threadIdx.x;
    if (i >= NLc * 3 * Dm) return;
    int l = i / (3 * Dm), r = i % (3 * Dm);
    int w = r / Dm, j = r % Dm;
    const float* s = (w == 0) ? a : (w == 1) ? b : c;
    out[i] = s[l * Dm + j];
}
__global__ void biascat2_kernel(const float* a, const float* b, float* out) {
    int i = blockIdx.x * 256 + threadIdx.x;
    if (i >= NLc * 2 * Dm) return;
    int l = i / (2 * Dm), r = i % (2 * Dm);
    int w = r / Dm, j = r % Dm;
    const float* s = (w == 0) ? a : b;
    out[i] = s[l * Dm + j];
}

// ---------------- stable descending argsort (B=64) ----------------
__global__ void sort_kernel(const int* __restrict__ lens, int* __restrict__ order) {
    __shared__ int l[Bz];
    int b = threadIdx.x;
    l[b] = lens[b];
    __syncthreads();
    int myl = l[b], rank = 0;
    #pragma unroll
    for (int j = 0; j < Bz; j++)
        rank += (l[j] > myl) || (l[j] == myl && j < b);
    order[rank] = b;
}

__global__ void gather_caps_kernel(const int* __restrict__ caps, const int* __restrict__ order,
                                   int* __restrict__ out) {
    int idx = blockIdx.x * 256 + threadIdx.x;
    if (idx >= MROW) return;
    int b = idx / LQ, t = idx % LQ;
    out[idx] = caps[order[b] * LQ + t];
}

__global__ void embed_kernel(const int* __restrict__ caps, const float* __restrict__ tgt,
                             const float* __restrict__ pos, float* __restrict__ x) {
    int idx = blockIdx.x * 256 + threadIdx.x;
    if (idx >= MROW * Dm) return;
    int d = idx & (Dm - 1);
    int rt = idx >> 9;
    int t = rt % LQ;
    int cap = caps[rt];
    x[idx] = tgt[(size_t)cap * Dm + d] + pos[t * Dm + d];
}

// ---------------- self attention (reads fused QKV, stride 1536) ----------------
__global__ __launch_bounds__(64)
void self_attn_kernel(const float* __restrict__ qkv, const int* __restrict__ caps,
                      float* __restrict__ ctx) {
    int b = blockIdx.x >> 3;
    int h = blockIdx.x & 7;
    int tid = threadIdx.x;  // 64
    __shared__ float Ks[LQ][DKh], Vs[LQ][DKh];
    __shared__ float qrow[DKh], p[LQ], red[64];
    __shared__ int pad[LQ];
    for (int i = tid; i < LQ * DKh; i += 64) {
        int t = i >> 6, d = i & 63;
        size_t src = (size_t)(b * LQ + t) * (3 * Dm) + h * DKh + d;
        Ks[t][d] = qkv[src + Dm];
        Vs[t][d] = qkv[src + 2 * Dm];
    }
    for (int t = tid; t < LQ; t += 64) pad[t] = (caps[b * LQ + t] == 0);
    __syncthreads();

    for (int q = 0; q < LQ; q++) {
        qrow[tid] = qkv[(size_t)(b * LQ + q) * (3 * Dm) + h * DKh + tid];
        __syncthreads();
        float s = -3.0e38f;
        if (tid < LQ) {
            float a = 0.f;
            #pragma unroll
            for (int d = 0; d < DKh; d++) a += qrow[d] * Ks[tid][d];
            s = a * 0.125f;
            if (tid > q || pad[tid]) s = -1e9f;
        }
        red[tid] = s; __syncthreads();
        #pragma unroll
        for (int st = 32; st > 0; st >>= 1) {
            if (tid < st) red[tid] = fmaxf(red[tid], red[tid + st]);
            __syncthreads();
        }
        float mx = red[0]; __syncthreads();
        float e = (tid < LQ) ? expf(s - mx) : 0.f;
        if (tid < LQ) p[tid] = e;
        red[tid] = e; __syncthreads();
        #pragma unroll
        for (int st = 32; st > 0; st >>= 1) {
            if (tid < st) red[tid] += red[tid + st];
            __syncthreads();
        }
        float inv = 1.f / red[0];
        __syncthreads();
        float a = 0.f;
        for (int k = 0; k < LQ; k++) a += p[k] * Vs[k][tid];
        ctx[(size_t)(b * LQ + q) * Dm + h * DKh + tid] = a * inv;
        __syncthreads();
    }
}

// ---------------- cross attention (Q stride 512, KV fused stride 1024) ----------------
__global__ __launch_bounds__(256)
void cross_attn_kernel(const float* __restrict__ Q, const float* __restrict__ KV,
                       const int* __restrict__ order, float* __restrict__ ctx) {
    float* Ks = csm;                       // NPIXc*DKh
    float* Vs = Ks + NPIXc * DKh;
    float* qrow = Vs + NPIXc * DKh;        // DKh
    float* p = qrow + DKh;                 // NPIXc
    __shared__ float red[256];
    int b = blockIdx.x >> 3;
    int h = blockIdx.x & 7;
    int tid = threadIdx.x;
    int ob = order[b];
    for (int i = tid; i < NPIXc * DKh; i += 256) {
        int t = i >> 6, d = i & 63;
        size_t src = (size_t)(ob * NPIXc + t) * (2 * Dm) + h * DKh + d;
        Ks[i] = KV[src];
        Vs[i] = KV[src + Dm];
    }
    __syncthreads();

    for (int q = 0; q < LQ; q++) {
        if (tid < DKh) qrow[tid] = Q[(size_t)(b * LQ + q) * Dm + h * DKh + tid];
        __syncthreads();
        float s = -3.0e38f;
        if (tid < NPIXc) {
            float a = 0.f;
            #pragma unroll
            for (int d = 0; d < DKh; d++) a += qrow[d] * Ks[tid * DKh + d];
            s = a * 0.125f;
        }
        red[tid] = s; __syncthreads();
        #pragma unroll
        for (int st = 128; st > 0; st >>= 1) {
            if (tid < st) red[tid] = fmaxf(red[tid], red[tid + st]);
            __syncthreads();
        }
        float mx = red[0]; __syncthreads();
        float e = (tid < NPIXc) ? expf(s - mx) : 0.f;
        if (tid < NPIXc) p[tid] = e;
        red[tid] = e; __syncthreads();
        #pragma unroll
        for (int st = 128; st > 0; st >>= 1) {
            if (tid < st) red[tid] += red[tid + st];
            __syncthreads();
        }
        float inv = 1.f / red[0];
        __syncthreads();
        int part = tid >> 6, d = tid & 63;
        float a = 0.f;
        for (int k = part; k < NPIXc; k += 4) a += p[k] * Vs[k * DKh + d];
        red[tid] = a; __syncthreads();
        if (part == 0) {
            float r = red[d] + red[64 + d] + red[128 + d] + red[192 + d];
            ctx[(size_t)(b * LQ + q) * Dm + h * DKh + d] = r * inv;
        }
        __syncthreads();
    }
}

// ---------------- LayerNorm(residual + bias) ----------------
__global__ __launch_bounds__(256)
void ln_residual_kernel(const float* __restrict__ y, const float* __restrict__ bias,
                        const float* __restrict__ xin, float* __restrict__ xout) {
    int r = blockIdx.x, tid = threadIdx.x;
    __shared__ float red[256];
    size_t base = (size_t)r * Dm;
    float v0 = y[base + tid]       + bias[tid]       + xin[base + tid];
    float v1 = y[base + 256 + tid] + bias[256 + tid] + xin[base + 256 + tid];
    red[tid] = v0 + v1; __syncthreads();
    #pragma unroll
    for (int st = 128; st > 0; st >>= 1) {
        if (tid < st) red[tid] += red[tid + st];
        __syncthreads();
    }
    float m = red[0] * (1.f / Dm);
    __syncthreads();
    float d0 = v0 - m, d1 = v1 - m;
    red[tid] = d0 * d0 + d1 * d1; __syncthreads();
    #pragma unroll
    for (int st = 128; st > 0; st >>= 1) {
        if (tid < st) red[tid] += red[tid + st];
        __syncthreads();
    }
    float inv = rsqrtf(red[0] * (1.f / Dm) + 1e-5f);
    xout[base + tid]       = d0 * inv;
    xout[base + 256 + tid] = d1 * inv;
}

// ---------------- host side ----------------
static inline void launch_split(const float* in, unsigned short* hi, unsigned short* lo, size_t n) {
    int n4 = (int)(n / 4);
    split_kernel<<<(n4 + 255) / 256, 256>>>(in, hi, lo, n4);
}

extern "C" void kernel_launch(void* const* d_in, const int* in_sizes, int n_in,
                              void* d_out, int out_size) {
    const float* encoder_out = (const float*)d_in[0];
    const int*   captions    = (const int*)d_in[1];
    const int*   lengths     = (const int*)d_in[2];
    const float* tgt_emb     = (const float*)d_in[3];
    const float* pos_emb     = (const float*)d_in[4];
    const float* sWq = (const float*)d_in[5];  const float* sbq = (const float*)d_in[6];
    const float* sWk = (const float*)d_in[7];  const float* sbk = (const float*)d_in[8];
    const float* sWv = (const float*)d_in[9];  const float* sbv = (const float*)d_in[10];
    const float* sWo = (const float*)d_in[11]; const float* sbo = (const float*)d_in[12];
    const float* eWq = (const float*)d_in[13]; const float* ebq = (const float*)d_in[14];
    const float* eWk = (const float*)d_in[15]; const float* ebk = (const float*)d_in[16];
    const float* eWv = (const float*)d_in[17]; const float* ebv = (const float*)d_in[18];
    const float* eWo = (const float*)d_in[19]; const float* ebo = (const float*)d_in[20];
    const float* fW1 = (const float*)d_in[21]; const float* fb1 = (const float*)d_in[22];
    const float* fW2 = (const float*)d_in[23]; const float* fb2 = (const float*)d_in[24];
    const float* pW  = (const float*)d_in[25];
    float* out = (float*)d_out;

    float *x, *y, *q, *qkv, *kv, *ctx, *h, *bqkv, *bkv;
    int *order, *caps;
    unsigned short *ahi, *alo, *ehi, *elo;
    unsigned short *wsqkv_h, *wsqkv_l, *wso_h, *wso_l, *weq_h, *weq_l;
    unsigned short *wekv_h, *wekv_l, *weo_h, *weo_l, *wf1_h, *wf1_l, *wf2_h, *wf2_l, *wpj_h, *wpj_l;
    cudaGetSymbolAddress((void**)&x, g_x);       cudaGetSymbolAddress((void**)&y, g_y);
    cudaGetSymbolAddress((void**)&q, g_q);       cudaGetSymbolAddress((void**)&qkv, g_qkv);
    cudaGetSymbolAddress((void**)&kv, g_kv);     cudaGetSymbolAddress((void**)&ctx, g_ctx);
    cudaGetSymbolAddress((void**)&h, g_h);
    cudaGetSymbolAddress((void**)&order, g_order); cudaGetSymbolAddress((void**)&caps, g_caps);
    cudaGetSymbolAddress((void**)&ahi, g_ahi);   cudaGetSymbolAddress((void**)&alo, g_alo);
    cudaGetSymbolAddress((void**)&ehi, g_ehi);   cudaGetSymbolAddress((void**)&elo, g_elo);
    cudaGetSymbolAddress((void**)&wsqkv_h, g_wsqkv_h); cudaGetSymbolAddress((void**)&wsqkv_l, g_wsqkv_l);
    cudaGetSymbolAddress((void**)&wso_h, g_wso_h);     cudaGetSymbolAddress((void**)&wso_l, g_wso_l);
    cudaGetSymbolAddress((void**)&weq_h, g_weq_h);     cudaGetSymbolAddress((void**)&weq_l, g_weq_l);
    cudaGetSymbolAddress((void**)&wekv_h, g_wekv_h);   cudaGetSymbolAddress((void**)&wekv_l, g_wekv_l);
    cudaGetSymbolAddress((void**)&weo_h, g_weo_h);     cudaGetSymbolAddress((void**)&weo_l, g_weo_l);
    cudaGetSymbolAddress((void**)&wf1_h, g_wf1_h);     cudaGetSymbolAddress((void**)&wf1_l, g_wf1_l);
    cudaGetSymbolAddress((void**)&wf2_h, g_wf2_h);     cudaGetSymbolAddress((void**)&wf2_l, g_wf2_l);
    cudaGetSymbolAddress((void**)&wpj_h, g_wpj_h);     cudaGetSymbolAddress((void**)&wpj_l, g_wpj_l);
    cudaGetSymbolAddress((void**)&bqkv, g_bqkv);       cudaGetSymbolAddress((void**)&bkv, g_bkv);

    const int CROSS_SMEM = (NPIXc * DKh * 2 + DKh + NPIXc) * sizeof(float);
    cudaFuncSetAttribute(cross_attn_kernel, cudaFuncAttributeMaxDynamicSharedMemorySize, CROSS_SMEM);
    cudaFuncSetAttribute(mgemm_kernel<128, false, true>,  cudaFuncAttributeMaxDynamicSharedMemorySize, SMEM_128);
    cudaFuncSetAttribute(mgemm_kernel<128, true,  true>,  cudaFuncAttributeMaxDynamicSharedMemorySize, SMEM_128);
    cudaFuncSetAttribute(mgemm_kernel<128, false, false>, cudaFuncAttributeMaxDynamicSharedMemorySize, SMEM_128);
    cudaFuncSetAttribute(mgemm_kernel<64,  false, true>,  cudaFuncAttributeMaxDynamicSharedMemorySize, SMEM_64);
    cudaFuncSetAttribute(mgemm_kernel<64,  false, false>, cudaFuncAttributeMaxDynamicSharedMemorySize, SMEM_64);

    // ---- weight prep: transpose + bf16 split ----
    const dim3 tsb(32, 8);
    for (int l = 0; l < NLc; l++) {
        const size_t DD = (size_t)Dm * Dm;
        tsplit_kernel<<<dim3(Dm/32, Dm/32), tsb>>>(sWq + l*DD, wsqkv_h + l*3*DD + 0*DD, wsqkv_l + l*3*DD + 0*DD, Dm, Dm);
        tsplit_kernel<<<dim3(Dm/32, Dm/32), tsb>>>(sWk + l*DD, wsqkv_h + l*3*DD + 1*DD, wsqkv_l + l*3*DD + 1*DD, Dm, Dm);
        tsplit_kernel<<<dim3(Dm/32, Dm/32), tsb>>>(sWv + l*DD, wsqkv_h + l*3*DD + 2*DD, wsqkv_l + l*3*DD + 2*DD, Dm, Dm);
        tsplit_kernel<<<dim3(Dm/32, Dm/32), tsb>>>(sWo + l*DD, wso_h + l*DD, wso_l + l*DD, Dm, Dm);
        tsplit_kernel<<<dim3(Dm/32, Dm/32), tsb>>>(eWq + l*DD, weq_h + l*DD, weq_l + l*DD, Dm, Dm);
        const size_t ED = (size_t)ENCc * Dm;
        tsplit_kernel<<<dim3(Dm/32, ENCc/32), tsb>>>(eWk + l*ED, wekv_h + l*2*ED + 0,  wekv_l + l*2*ED + 0,  ENCc, Dm);
        tsplit_kernel<<<dim3(Dm/32, ENCc/32), tsb>>>(eWv + l*ED, wekv_h + l*2*ED + ED, wekv_l + l*2*ED + ED, ENCc, Dm);
        tsplit_kernel<<<dim3(Dm/32, Dm/32), tsb>>>(eWo + l*DD, weo_h + l*DD, weo_l + l*DD, Dm, Dm);
        tsplit_kernel<<<dim3(FFc/32, Dm/32),  tsb>>>(fW1 + l*ED, wf1_h + l*ED, wf1_l + l*ED, Dm, FFc);
        tsplit_kernel<<<dim3(Dm/32, FFc/32),  tsb>>>(fW2 + l*ED, wf2_h + l*ED, wf2_l + l*ED, FFc, Dm);
    }
    launch_split(pW, wpj_h, wpj_l, (size_t)VOC * Dm);
    biascat3_kernel<<<(NLc*3*Dm + 255)/256, 256>>>(sbq, sbk, sbv, bqkv);
    biascat2_kernel<<<(NLc*2*Dm + 255)/256, 256>>>(ebk, ebv, bkv);

    // ---- prologue ----
    sort_kernel<<<1, Bz>>>(lengths, order);
    gather_caps_kernel<<<(MROW + 255) / 256, 256>>>(captions, order, caps);
    embed_kernel<<<(MROW * Dm + 255) / 256, 256>>>(caps, tgt_emb, pos_emb, x);
    launch_split(encoder_out, ehi, elo, (size_t)EROW * ENCc);

    const dim3 gQKV(12, 26);    // M=3328, N=1536, BM=128
    const dim3 gD64(4, 52);     // M=3328, N=512,  BM=64
    const dim3 gKV(8, 98);      // M=12544, N=1024, BM=128
    const dim3 gFF1(16, 26);    // N=2048, BM=128
    const dim3 gPRJ(250, 26);   // N=32000, BM=128

    for (int l = 0; l < NLc; l++) {
        const size_t DD = (size_t)Dm * Dm, ED = (size_t)ENCc * Dm;

        // ---- self attention ----
        launch_split(x, ahi, alo, (size_t)MROW * Dm);
        mgemm_kernel<128, false, true><<<gQKV, 256, SMEM_128>>>(ahi, alo,
            wsqkv_h + l*3*DD, wsqkv_l + l*3*DD, bqkv + l*3*Dm, qkv, MROW, 3*Dm, Dm);
        self_attn_kernel<<<Bz * NH, 64>>>(qkv, caps, ctx);
        launch_split(ctx, ahi, alo, (size_t)MROW * Dm);
        mgemm_kernel<64, false, false><<<gD64, 256, SMEM_64>>>(ahi, alo,
            wso_h + l*DD, wso_l + l*DD, nullptr, y, MROW, Dm, Dm);
        ln_residual_kernel<<<MROW, 256>>>(y, sbo + l*Dm, x, x);

        // ---- cross attention ----
        launch_split(x, ahi, alo, (size_t)MROW * Dm);
        mgemm_kernel<64, false, true><<<gD64, 256, SMEM_64>>>(ahi, alo,
            weq_h + l*DD, weq_l + l*DD, ebq + l*Dm, q, MROW, Dm, Dm);
        mgemm_kernel<128, false, true><<<gKV, 256, SMEM_128>>>(ehi, elo,
            wekv_h + l*2*ED, wekv_l + l*2*ED, bkv + l*2*Dm, kv, EROW, 2*Dm, ENCc);
        cross_attn_kernel<<<Bz * NH, 256, CROSS_SMEM>>>(q, kv, order, ctx);
        launch_split(ctx, ahi, alo, (size_t)MROW * Dm);
        mgemm_kernel<64, false, false><<<gD64, 256, SMEM_64>>>(ahi, alo,
            weo_h + l*DD, weo_l + l*DD, nullptr, y, MROW, Dm, Dm);
        ln_residual_kernel<<<MROW, 256>>>(y, ebo + l*Dm, x, x);

        // ---- FFN ----
        launch_split(x, ahi, alo, (size_t)MROW * Dm);
        mgemm_kernel<128, true, true><<<gFF1, 256, SMEM_128>>>(ahi, alo,
            wf1_h + l*ED, wf1_l + l*ED, fb1 + l*FFc, h, MROW, FFc, Dm);
        launch_split(h, ahi, alo, (size_t)MROW * FFc);
        mgemm_kernel<64, false, false><<<gD64, 256, SMEM_64>>>(ahi, alo,
            wf2_h + l*ED, wf2_l + l*ED, nullptr, y, MROW, Dm, FFc);
        ln_residual_kernel<<<MROW, 256>>>(y, fb2 + l*Dm, x, x);
    }

    // ---- vocab projection ----
    launch_split(x, ahi, alo, (size_t)MROW * Dm);
    mgemm_kernel<128, false, false><<<gPRJ, 256, SMEM_128>>>(ahi, alo,
        wpj_h, wpj_l, nullptr, out, MROW, VOC, Dm);
}

// round 6
// speedup vs baseline: 5.0630x; 1.7686x over previous
#include <cuda_runtime.h>
#include <cuda_bf16.h>
#include <math.h>
#include <stdint.h>

// ---------------- problem constants ----------------
#define Bz    64
#define LQ    52
#define Dm    512
#define NH    8
#define DKh   64
#define NPIXc 196
#define ENCc  2048
#define FFc   2048
#define NLc   6
#define MROW  (Bz*LQ)       // 3328
#define EROW  (Bz*NPIXc)    // 12544
#define VOC   32000

// ---------------- fp32 scratch ----------------
__device__ float g_x[MROW*Dm];
__device__ float g_y[MROW*Dm];
__device__ float g_q[MROW*Dm];
__device__ float g_qkv[MROW*3*Dm];
__device__ float g_kv[EROW*2*Dm];
__device__ int   g_order[Bz];
__device__ int   g_caps[MROW];

// ---------------- bf16 (ushort) scratch: activations ----------------
__device__ unsigned short g_ahi[MROW*Dm],  g_alo[MROW*Dm];    // x / final LN split
__device__ unsigned short g_chi[MROW*Dm],  g_clo[MROW*Dm];    // attention ctx split
__device__ unsigned short g_hhi[MROW*FFc], g_hlo[MROW*FFc];   // FF1 output split
__device__ unsigned short g_ehi[EROW*ENCc], g_elo[EROW*ENCc]; // encoder split

// ---------------- bf16 scratch: transposed weights [N,K] ----------------
__device__ unsigned short g_wsqkv_h[NLc*3*Dm*Dm],  g_wsqkv_l[NLc*3*Dm*Dm];
__device__ unsigned short g_wso_h[NLc*Dm*Dm],      g_wso_l[NLc*Dm*Dm];
__device__ unsigned short g_weq_h[NLc*Dm*Dm],      g_weq_l[NLc*Dm*Dm];
__device__ unsigned short g_wekv_h[NLc*2*Dm*ENCc], g_wekv_l[NLc*2*Dm*ENCc];
__device__ unsigned short g_weo_h[NLc*Dm*Dm],      g_weo_l[NLc*Dm*Dm];
__device__ unsigned short g_wf1_h[NLc*FFc*Dm],     g_wf1_l[NLc*FFc*Dm];
__device__ unsigned short g_wf2_h[NLc*Dm*FFc],     g_wf2_l[NLc*Dm*FFc];
__device__ unsigned short g_wpj_h[VOC*Dm],         g_wpj_l[VOC*Dm];
__device__ float g_bqkv[NLc*3*Dm];
__device__ float g_bkv[NLc*2*Dm];

extern __shared__ float csm[];

// ---------------- helpers ----------------
__device__ __forceinline__ uint32_t smem_u32(const void* p) {
    uint32_t a;
    asm("{ .reg .u64 t; cvta.to.shared.u64 t, %1; cvt.u32.u64 %0, t; }" : "=r"(a) : "l"(p));
    return a;
}
__device__ __forceinline__ void cpa16(uint32_t s, const void* g) {
    asm volatile("cp.async.cg.shared.global [%0], [%1], 16;" :: "r"(s), "l"(g));
}
#define CP_COMMIT() asm volatile("cp.async.commit_group;" ::: "memory")
#define CP_WAIT0()  asm volatile("cp.async.wait_group 0;" ::: "memory")
#define CP_WAIT1()  asm volatile("cp.async.wait_group 1;" ::: "memory")

#define MMA16816(c, a, b) \
    asm volatile("mma.sync.aligned.m16n8k16.row.col.f32.bf16.bf16.f32 " \
        "{%0,%1,%2,%3}, {%4,%5,%6,%7}, {%8,%9}, {%0,%1,%2,%3};" \
        : "+f"((c)[0]), "+f"((c)[1]), "+f"((c)[2]), "+f"((c)[3]) \
        : "r"((a)[0]), "r"((a)[1]), "r"((a)[2]), "r"((a)[3]), \
          "r"((b)[0]), "r"((b)[1]))

__device__ __forceinline__ void bsplit(float x, unsigned short& h, unsigned short& l) {
    __nv_bfloat16 hb = __float2bfloat16(x);
    float r = x - __bfloat162float(hb);
    __nv_bfloat16 lb = __float2bfloat16(r);
    h = __bfloat16_as_ushort(hb);
    l = __bfloat16_as_ushort(lb);
}

// ============ HMMA bf16x3 GEMM: C[M,N] = A[M,K] * Bt[N,K]^T + bias ============
template<int BMt, bool RELU, bool HASBIAS, bool SPLIT>
__global__ __launch_bounds__(256, 2)
void mgemm_kernel(const unsigned short* __restrict__ Ahi, const unsigned short* __restrict__ Alo,
                  const unsigned short* __restrict__ Bhi, const unsigned short* __restrict__ Blo,
                  const float* __restrict__ bias, float* __restrict__ C,
                  unsigned short* __restrict__ Chi, unsigned short* __restrict__ Clo,
                  int M, int N, int K) {
    constexpr int BN = 128;
    constexpr int NWM = BMt / 32;
    constexpr int NWN = 8 / NWM;
    constexpr int NTN = BN / NWN;
    constexpr int NF  = NTN / 8;
    constexpr int ROWB = 80;
    constexpr int ASZ = BMt * ROWB;
    constexpr int BSZ = BN * ROWB;
    constexpr int STAGE = 2 * ASZ + 2 * BSZ;

    char* sm = (char*)csm;
    const int tid = threadIdx.x;
    const int wid = tid >> 5, lane = tid & 31;
    const int wm = wid / NWN, wn = wid % NWN;
    const int gr = lane >> 2, ck = lane & 3;
    const int m0 = blockIdx.y * BMt;
    const int n0 = blockIdx.x * BN;

    float acc[2][NF][4];
    #pragma unroll
    for (int mt = 0; mt < 2; mt++)
        #pragma unroll
        for (int nf = 0; nf < NF; nf++)
            #pragma unroll
            for (int j = 0; j < 4; j++) acc[mt][nf][j] = 0.f;

    const uint32_t smb = smem_u32(sm);

    auto load_stage = [&](int s, int k0) {
        const uint32_t sb = smb + s * STAGE;
        #pragma unroll
        for (int p = 0; p < BMt * 4 / 256; p++) {
            int id = tid + p * 256;
            int row = id >> 2, cc = id & 3;
            uint32_t so = row * ROWB + cc * 16;
            const size_t go = (size_t)(m0 + row) * K + k0 + cc * 8;
            cpa16(sb + so,        Ahi + go);
            cpa16(sb + ASZ + so,  Alo + go);
        }
        #pragma unroll
        for (int p = 0; p < 2; p++) {
            int id = tid + p * 256;
            int row = id >> 2, cc = id & 3;
            uint32_t so = row * ROWB + cc * 16;
            const size_t go = (size_t)(n0 + row) * K + k0 + cc * 8;
            cpa16(sb + 2*ASZ + so,       Bhi + go);
            cpa16(sb + 2*ASZ + BSZ + so, Blo + go);
        }
    };

    auto compute = [&](int s) {
        const char* base = sm + s * STAGE;
        const char* sAh = base;
        const char* sAl = base + ASZ;
        const char* sBh = base + 2 * ASZ;
        const char* sBl = base + 2 * ASZ + BSZ;
        #pragma unroll
        for (int ks = 0; ks < 2; ks++) {
            const int cby = ks * 32 + ck * 4;
            uint32_t ah[2][4], al[2][4], bh[NF][2], bl[NF][2];
            #pragma unroll
            for (int mt = 0; mt < 2; mt++) {
                const int r = wm * 32 + mt * 16 + gr;
                ah[mt][0] = *(const uint32_t*)(sAh + r * ROWB + cby);
                ah[mt][1] = *(const uint32_t*)(sAh + (r + 8) * ROWB + cby);
                ah[mt][2] = *(const uint32_t*)(sAh + r * ROWB + cby + 16);
                ah[mt][3] = *(const uint32_t*)(sAh + (r + 8) * ROWB + cby + 16);
                al[mt][0] = *(const uint32_t*)(sAl + r * ROWB + cby);
                al[mt][1] = *(const uint32_t*)(sAl + (r + 8) * ROWB + cby);
                al[mt][2] = *(const uint32_t*)(sAl + r * ROWB + cby + 16);
                al[mt][3] = *(const uint32_t*)(sAl + (r + 8) * ROWB + cby + 16);
            }
            #pragma unroll
            for (int nf = 0; nf < NF; nf++) {
                const int n = wn * NTN + nf * 8 + gr;
                bh[nf][0] = *(const uint32_t*)(sBh + n * ROWB + cby);
                bh[nf][1] = *(const uint32_t*)(sBh + n * ROWB + cby + 16);
                bl[nf][0] = *(const uint32_t*)(sBl + n * ROWB + cby);
                bl[nf][1] = *(const uint32_t*)(sBl + n * ROWB + cby + 16);
            }
            #pragma unroll
            for (int mt = 0; mt < 2; mt++)
                #pragma unroll
                for (int nf = 0; nf < NF; nf++)
                    MMA16816(acc[mt][nf], ah[mt], bh[nf]);
            #pragma unroll
            for (int mt = 0; mt < 2; mt++)
                #pragma unroll
                for (int nf = 0; nf < NF; nf++)
                    MMA16816(acc[mt][nf], ah[mt], bl[nf]);
            #pragma unroll
            for (int mt = 0; mt < 2; mt++)
                #pragma unroll
                for (int nf = 0; nf < NF; nf++)
                    MMA16816(acc[mt][nf], al[mt], bh[nf]);
        }
    };

    load_stage(0, 0);
    CP_COMMIT();
    const int chunks = K >> 5;
    for (int c = 0; c < chunks; c++) {
        if (c + 1 < chunks) {
            load_stage((c + 1) & 1, (c + 1) << 5);
            CP_COMMIT();
            CP_WAIT1();
        } else {
            CP_WAIT0();
        }
        __syncthreads();
        compute(c & 1);
        __syncthreads();
    }

    #pragma unroll
    for (int mt = 0; mt < 2; mt++) {
        const int r = m0 + wm * 32 + mt * 16 + gr;
        #pragma unroll
        for (int nf = 0; nf < NF; nf++) {
            const int cc = n0 + wn * NTN + nf * 8 + ck * 2;
            float v0 = acc[mt][nf][0], v1 = acc[mt][nf][1];
            float v2 = acc[mt][nf][2], v3 = acc[mt][nf][3];
            if (HASBIAS) {
                float b0 = bias[cc], b1 = bias[cc + 1];
                v0 += b0; v1 += b1; v2 += b0; v3 += b1;
            }
            if (RELU) {
                v0 = fmaxf(v0, 0.f); v1 = fmaxf(v1, 0.f);
                v2 = fmaxf(v2, 0.f); v3 = fmaxf(v3, 0.f);
            }
            if (SPLIT) {
                unsigned short h0,l0,h1,l1,h2,l2,h3,l3;
                bsplit(v0,h0,l0); bsplit(v1,h1,l1);
                bsplit(v2,h2,l2); bsplit(v3,h3,l3);
                ((uint32_t*)Chi)[((size_t)r * N + cc) >> 1]       = (uint32_t)h0 | ((uint32_t)h1 << 16);
                ((uint32_t*)Clo)[((size_t)r * N + cc) >> 1]       = (uint32_t)l0 | ((uint32_t)l1 << 16);
                ((uint32_t*)Chi)[((size_t)(r + 8) * N + cc) >> 1] = (uint32_t)h2 | ((uint32_t)h3 << 16);
                ((uint32_t*)Clo)[((size_t)(r + 8) * N + cc) >> 1] = (uint32_t)l2 | ((uint32_t)l3 << 16);
            } else {
                float2 w0; w0.x = v0; w0.y = v1;
                float2 w1; w1.x = v2; w1.y = v3;
                *(float2*)(C + (size_t)r * N + cc)       = w0;
                *(float2*)(C + (size_t)(r + 8) * N + cc) = w1;
            }
        }
    }
}

#define SMEM_128 (2 * (2*128*80 + 2*128*80))   // 81920
#define SMEM_64  (2 * (2*64*80  + 2*128*80))   // 61440

// ================= split (flat) =================
__global__ void split_kernel(const float* __restrict__ in, unsigned short* __restrict__ hi,
                             unsigned short* __restrict__ lo, int n4) {
    int i = blockIdx.x * 256 + threadIdx.x;
    if (i >= n4) return;
    float4 v = ((const float4*)in)[i];
    unsigned short h0,h1,h2,h3,l0,l1,l2,l3;
    bsplit(v.x,h0,l0); bsplit(v.y,h1,l1); bsplit(v.z,h2,l2); bsplit(v.w,h3,l3);
    uint2 hv, lv;
    hv.x = (uint32_t)h0 | ((uint32_t)h1 << 16); hv.y = (uint32_t)h2 | ((uint32_t)h3 << 16);
    lv.x = (uint32_t)l0 | ((uint32_t)l1 << 16); lv.y = (uint32_t)l2 | ((uint32_t)l3 << 16);
    *(uint2*)(hi + 4*(size_t)i) = hv;
    *(uint2*)(lo + 4*(size_t)i) = lv;
}

// ===== transpose+split, batched over layers (grid.z), 128B-coalesced writes =====
// src W[K,N] row-major -> dst[N,K] hi/lo. Tile: K64 x N32.
__global__ void tsplit_kernel(const float* __restrict__ W, unsigned short* __restrict__ hi,
                              unsigned short* __restrict__ lo, int K, int N,
                              size_t sstride, size_t dstride) {
    __shared__ float t[64][33];
    const int z = blockIdx.z;
    W  += (size_t)z * sstride;
    hi += (size_t)z * dstride;
    lo += (size_t)z * dstride;
    const int nb = blockIdx.x * 32, kb = blockIdx.y * 64;
    const int tx = threadIdx.x, ty = threadIdx.y;
    for (int r = ty; r < 64; r += 8)
        t[r][tx] = W[(size_t)(kb + r) * N + nb + tx];
    __syncthreads();
    for (int n = ty; n < 32; n += 8) {
        float x0 = t[2*tx][n], x1 = t[2*tx + 1][n];
        unsigned short h0,l0,h1,l1;
        bsplit(x0,h0,l0); bsplit(x1,h1,l1);
        size_t o = (((size_t)(nb + n) * K + kb) >> 1) + tx;
        ((uint32_t*)hi)[o] = (uint32_t)h0 | ((uint32_t)h1 << 16);
        ((uint32_t*)lo)[o] = (uint32_t)l0 | ((uint32_t)l1 << 16);
    }
}

__global__ void biascat3_kernel(const float* a, const float* b, const float* c, float* out) {
    int i = blockIdx.x * 256 + threadIdx.x;
    if (i >= NLc * 3 * Dm) return;
    int l = i / (3 * Dm), r = i % (3 * Dm);
    int w = r / Dm, j = r % Dm;
    const float* s = (w == 0) ? a : (w == 1) ? b : c;
    out[i] = s[l * Dm + j];
}
__global__ void biascat2_kernel(const float* a, const float* b, float* out) {
    int i = blockIdx.x * 256 + threadIdx.x;
    if (i >= NLc * 2 * Dm) return;
    int l = i / (2 * Dm), r = i % (2 * Dm);
    int w = r / Dm, j = r % Dm;
    const float* s = (w == 0) ? a : b;
    out[i] = s[l * Dm + j];
}

// ---------------- sort / gather / embed ----------------
__global__ void sort_kernel(const int* __restrict__ lens, int* __restrict__ order) {
    __shared__ int l[Bz];
    int b = threadIdx.x;
    l[b] = lens[b];
    __syncthreads();
    int myl = l[b], rank = 0;
    #pragma unroll
    for (int j = 0; j < Bz; j++)
        rank += (l[j] > myl) || (l[j] == myl && j < b);
    order[rank] = b;
}

__global__ void gather_caps_kernel(const int* __restrict__ caps, const int* __restrict__ order,
                                   int* __restrict__ out) {
    int idx = blockIdx.x * 256 + threadIdx.x;
    if (idx >= MROW) return;
    int b = idx / LQ, t = idx % LQ;
    out[idx] = caps[order[b] * LQ + t];
}

__global__ void embed_kernel(const int* __restrict__ caps, const float* __restrict__ tgt,
                             const float* __restrict__ pos, float* __restrict__ x,
                             unsigned short* __restrict__ hi, unsigned short* __restrict__ lo) {
    int idx = blockIdx.x * 256 + threadIdx.x;
    if (idx >= MROW * Dm) return;
    int d = idx & (Dm - 1);
    int rt = idx >> 9;
    int t = rt % LQ;
    int cap = caps[rt];
    float v = tgt[(size_t)cap * Dm + d] + pos[t * Dm + d];
    x[idx] = v;
    unsigned short h, l;
    bsplit(v, h, l);
    hi[idx] = h; lo[idx] = l;
}

// ---------------- self attention: warp-per-query, conflict-free smem ----------------
__global__ __launch_bounds__(256)
void self_attn_kernel(const float* __restrict__ qkv, const int* __restrict__ caps,
                      unsigned short* __restrict__ chi, unsigned short* __restrict__ clo) {
    __shared__ float Ks[64][65];
    __shared__ float Vs[64][64];
    __shared__ float ps[8][LQ];
    __shared__ int pad[64];
    const int b = blockIdx.x >> 3;
    const int h = blockIdx.x & 7;
    const int tid = threadIdx.x;
    const int lane = tid & 31, w = tid >> 5;

    for (int i = tid; i < 64 * 64; i += 256) {
        int t = i >> 6, d = i & 63;
        if (t < LQ) {
            size_t src = (size_t)(b * LQ + t) * (3 * Dm) + h * DKh + d;
            Ks[t][d] = qkv[src + Dm];
            Vs[t][d] = qkv[src + 2 * Dm];
        } else {
            Ks[t][d] = 0.f; Vs[t][d] = 0.f;
        }
    }
    if (tid < 64) pad[tid] = (tid < LQ) ? (caps[b * LQ + tid] == 0) : 1;
    __syncthreads();

    for (int q = w; q < LQ; q += 8) {
        const float* qp = qkv + (size_t)(b * LQ + q) * (3 * Dm) + h * DKh;
        float q0 = qp[lane], q1 = qp[lane + 32];
        float a0 = 0.f, a1 = 0.f;
        #pragma unroll
        for (int d = 0; d < 64; d++) {
            float qv = (d < 32) ? __shfl_sync(0xffffffffu, q0, d)
                                : __shfl_sync(0xffffffffu, q1, d - 32);
            a0 += qv * Ks[lane][d];
            a1 += qv * Ks[lane + 32][d];
        }
        const int k1 = lane + 32;
        float s0 = (lane > q || pad[lane]) ? -1e9f : a0 * 0.125f;
        float s1 = (k1 >= LQ) ? -1e30f : ((k1 > q || pad[k1]) ? -1e9f : a1 * 0.125f);
        float m = fmaxf(s0, s1);
        #pragma unroll
        for (int o = 16; o > 0; o >>= 1) m = fmaxf(m, __shfl_xor_sync(0xffffffffu, m, o));
        float e0 = __expf(s0 - m);
        float e1 = __expf(s1 - m);
        float sum = e0 + e1;
        #pragma unroll
        for (int o = 16; o > 0; o >>= 1) sum += __shfl_xor_sync(0xffffffffu, sum, o);
        float inv = 1.f / sum;
        ps[w][lane] = e0;
        if (k1 < LQ) ps[w][k1] = e1;
        __syncwarp();
        float c0 = 0.f, c1 = 0.f;
        #pragma unroll 4
        for (int k = 0; k < LQ; k++) {
            float p = ps[w][k];
            c0 += p * Vs[k][lane];
            c1 += p * Vs[k][lane + 32];
        }
        size_t base = (size_t)(b * LQ + q) * Dm + h * DKh;
        unsigned short hh, ll;
        bsplit(c0 * inv, hh, ll);
        chi[base + lane] = hh; clo[base + lane] = ll;
        bsplit(c1 * inv, hh, ll);
        chi[base + lane + 32] = hh; clo[base + lane + 32] = ll;
        __syncwarp();
    }
}

// ---------------- cross attention: warp handles 2 queries, shared V sweep ----------------
#define KS_STR 68
__global__ __launch_bounds__(256)
void cross_attn_kernel(const float* __restrict__ Q, const float* __restrict__ KV,
                       const int* __restrict__ order,
                       unsigned short* __restrict__ chi, unsigned short* __restrict__ clo) {
    float* Ks = csm;                             // 196*68
    float* Vs = Ks + NPIXc * KS_STR;             // 196*64
    float* ps = Vs + NPIXc * DKh;                // 16*196
    const int b = blockIdx.x >> 3;
    const int h = blockIdx.x & 7;
    const int tid = threadIdx.x;
    const int lane = tid & 31, w = tid >> 5;
    const int ob = order[b];

    for (int i = tid; i < NPIXc * DKh; i += 256) {
        int t = i >> 6, d = i & 63;
        size_t src = (size_t)(ob * NPIXc + t) * (2 * Dm) + h * DKh + d;
        Ks[t * KS_STR + d] = KV[src];
        Vs[t * DKh + d]    = KV[src + Dm];
    }
    __syncthreads();

    for (int qi = w; qi < LQ / 2; qi += 8) {
        const int q0 = 2 * qi;
        const float* qp = Q + (size_t)(b * LQ + q0) * Dm + h * DKh;
        float qa0 = qp[lane], qb0 = qp[lane + 32];
        float qa1 = qp[Dm + lane], qb1 = qp[Dm + lane + 32];

        float s0[7], s1[7];
        #pragma unroll
        for (int kk = 0; kk < 7; kk++) { s0[kk] = 0.f; s1[kk] = 0.f; }

        #pragma unroll
        for (int d4 = 0; d4 < 16; d4++) {
            float qv0[4], qv1[4];
            #pragma unroll
            for (int j = 0; j < 4; j++) {
                int d = 4 * d4 + j;
                qv0[j] = (d < 32) ? __shfl_sync(0xffffffffu, qa0, d)
                                  : __shfl_sync(0xffffffffu, qb0, d - 32);
                qv1[j] = (d < 32) ? __shfl_sync(0xffffffffu, qa1, d)
                                  : __shfl_sync(0xffffffffu, qb1, d - 32);
            }
            #pragma unroll
            for (int kk = 0; kk < 7; kk++) {
                const int key = kk * 32 + lane;
                float4 kv4 = *(const float4*)(Ks + key * KS_STR + 4 * d4);
                s0[kk] += qv0[0]*kv4.x + qv0[1]*kv4.y + qv0[2]*kv4.z + qv0[3]*kv4.w;
                s1[kk] += qv1[0]*kv4.x + qv1[1]*kv4.y + qv1[2]*kv4.z + qv1[3]*kv4.w;
            }
        }
        float m0 = -1e30f, m1 = -1e30f;
        #pragma unroll
        for (int kk = 0; kk < 7; kk++) {
            const int key = kk * 32 + lane;
            s0[kk] = (key < NPIXc) ? s0[kk] * 0.125f : -1e30f;
            s1[kk] = (key < NPIXc) ? s1[kk] * 0.125f : -1e30f;
            m0 = fmaxf(m0, s0[kk]); m1 = fmaxf(m1, s1[kk]);
        }
        #pragma unroll
        for (int o = 16; o > 0; o >>= 1) {
            m0 = fmaxf(m0, __shfl_xor_sync(0xffffffffu, m0, o));
            m1 = fmaxf(m1, __shfl_xor_sync(0xffffffffu, m1, o));
        }
        float sum0 = 0.f, sum1 = 0.f;
        #pragma unroll
        for (int kk = 0; kk < 7; kk++) {
            const int key = kk * 32 + lane;
            float e0 = __expf(s0[kk] - m0);
            float e1 = __expf(s1[kk] - m1);
            sum0 += e0; sum1 += e1;
            if (key < NPIXc) {
                ps[(2 * w) * NPIXc + key]     = e0;
                ps[(2 * w + 1) * NPIXc + key] = e1;
            }
        }
        #pragma unroll
        for (int o = 16; o > 0; o >>= 1) {
            sum0 += __shfl_xor_sync(0xffffffffu, sum0, o);
            sum1 += __shfl_xor_sync(0xffffffffu, sum1, o);
        }
        float inv0 = 1.f / sum0, inv1 = 1.f / sum1;
        __syncwarp();

        float c00 = 0.f, c01 = 0.f, c10 = 0.f, c11 = 0.f;
        const float* p0p = ps + (2 * w) * NPIXc;
        const float* p1p = ps + (2 * w + 1) * NPIXc;
        #pragma unroll 4
        for (int k = 0; k < NPIXc; k++) {
            float2 vv = *(const float2*)(Vs + k * DKh + 2 * lane);
            float p0 = p0p[k], p1 = p1p[k];
            c00 += p0 * vv.x; c01 += p0 * vv.y;
            c10 += p1 * vv.x; c11 += p1 * vv.y;
        }
        size_t base = (size_t)(b * LQ + q0) * Dm + h * DKh + 2 * lane;
        unsigned short h0,l0,h1,l1;
        bsplit(c00 * inv0, h0, l0); bsplit(c01 * inv0, h1, l1);
        ((uint32_t*)chi)[base >> 1] = (uint32_t)h0 | ((uint32_t)h1 << 16);
        ((uint32_t*)clo)[base >> 1] = (uint32_t)l0 | ((uint32_t)l1 << 16);
        bsplit(c10 * inv1, h0, l0); bsplit(c11 * inv1, h1, l1);
        ((uint32_t*)chi)[(base + Dm) >> 1] = (uint32_t)h0 | ((uint32_t)h1 << 16);
        ((uint32_t*)clo)[(base + Dm) >> 1] = (uint32_t)l0 | ((uint32_t)l1 << 16);
        __syncwarp();
    }
}
#define CROSS_SMEM ((NPIXc*KS_STR + NPIXc*DKh + 16*NPIXc) * (int)sizeof(float))

// ---------------- LayerNorm(residual + bias), emits fp32 + bf16 split ----------------
__global__ __launch_bounds__(256)
void ln_residual_kernel(const float* __restrict__ y, const float* __restrict__ bias,
                        const float* __restrict__ xin, float* __restrict__ xout,
                        unsigned short* __restrict__ hi, unsigned short* __restrict__ lo) {
    int r = blockIdx.x, tid = threadIdx.x;
    __shared__ float red[256];
    size_t base = (size_t)r * Dm;
    float v0 = y[base + tid]       + bias[tid]       + xin[base + tid];
    float v1 = y[base + 256 + tid] + bias[256 + tid] + xin[base + 256 + tid];
    red[tid] = v0 + v1; __syncthreads();
    #pragma unroll
    for (int st = 128; st > 0; st >>= 1) {
        if (tid < st) red[tid] += red[tid + st];
        __syncthreads();
    }
    float m = red[0] * (1.f / Dm);
    __syncthreads();
    float d0 = v0 - m, d1 = v1 - m;
    red[tid] = d0 * d0 + d1 * d1; __syncthreads();
    #pragma unroll
    for (int st = 128; st > 0; st >>= 1) {
        if (tid < st) red[tid] += red[tid + st];
        __syncthreads();
    }
    float inv = rsqrtf(red[0] * (1.f / Dm) + 1e-5f);
    float o0 = d0 * inv, o1 = d1 * inv;
    xout[base + tid]       = o0;
    xout[base + 256 + tid] = o1;
    unsigned short h, l;
    bsplit(o0, h, l); hi[base + tid] = h;       lo[base + tid] = l;
    bsplit(o1, h, l); hi[base + 256 + tid] = h; lo[base + 256 + tid] = l;
}

// ---------------- host side ----------------
extern "C" void kernel_launch(void* const* d_in, const int* in_sizes, int n_in,
                              void* d_out, int out_size) {
    const float* encoder_out = (const float*)d_in[0];
    const int*   captions    = (const int*)d_in[1];
    const int*   lengths     = (const int*)d_in[2];
    const float* tgt_emb     = (const float*)d_in[3];
    const float* pos_emb     = (const float*)d_in[4];
    const float* sWq = (const float*)d_in[5];  const float* sbq = (const float*)d_in[6];
    const float* sWk = (const float*)d_in[7];  const float* sbk = (const float*)d_in[8];
    const float* sWv = (const float*)d_in[9];  const float* sbv = (const float*)d_in[10];
    const float* sWo = (const float*)d_in[11]; const float* sbo = (const float*)d_in[12];
    const float* eWq = (const float*)d_in[13]; const float* ebq = (const float*)d_in[14];
    const float* eWk = (const float*)d_in[15]; const float* ebk = (const float*)d_in[16];
    const float* eWv = (const float*)d_in[17]; const float* ebv = (const float*)d_in[18];
    const float* eWo = (const float*)d_in[19]; const float* ebo = (const float*)d_in[20];
    const float* fW1 = (const float*)d_in[21]; const float* fb1 = (const float*)d_in[22];
    const float* fW2 = (const float*)d_in[23]; const float* fb2 = (const float*)d_in[24];
    const float* pW  = (const float*)d_in[25];
    float* out = (float*)d_out;

    float *x, *y, *q, *qkv, *kv, *bqkv, *bkv;
    int *order, *caps;
    unsigned short *ahi, *alo, *chi, *clo, *hhi, *hlo, *ehi, *elo;
    unsigned short *wsqkv_h, *wsqkv_l, *wso_h, *wso_l, *weq_h, *weq_l;
    unsigned short *wekv_h, *wekv_l, *weo_h, *weo_l, *wf1_h, *wf1_l, *wf2_h, *wf2_l, *wpj_h, *wpj_l;
    cudaGetSymbolAddress((void**)&x, g_x);       cudaGetSymbolAddress((void**)&y, g_y);
    cudaGetSymbolAddress((void**)&q, g_q);       cudaGetSymbolAddress((void**)&qkv, g_qkv);
    cudaGetSymbolAddress((void**)&kv, g_kv);
    cudaGetSymbolAddress((void**)&order, g_order); cudaGetSymbolAddress((void**)&caps, g_caps);
    cudaGetSymbolAddress((void**)&ahi, g_ahi);   cudaGetSymbolAddress((void**)&alo, g_alo);
    cudaGetSymbolAddress((void**)&chi, g_chi);   cudaGetSymbolAddress((void**)&clo, g_clo);
    cudaGetSymbolAddress((void**)&hhi, g_hhi);   cudaGetSymbolAddress((void**)&hlo, g_hlo);
    cudaGetSymbolAddress((void**)&ehi, g_ehi);   cudaGetSymbolAddress((void**)&elo, g_elo);
    cudaGetSymbolAddress((void**)&wsqkv_h, g_wsqkv_h); cudaGetSymbolAddress((void**)&wsqkv_l, g_wsqkv_l);
    cudaGetSymbolAddress((void**)&wso_h, g_wso_h);     cudaGetSymbolAddress((void**)&wso_l, g_wso_l);
    cudaGetSymbolAddress((void**)&weq_h, g_weq_h);     cudaGetSymbolAddress((void**)&weq_l, g_weq_l);
    cudaGetSymbolAddress((void**)&wekv_h, g_wekv_h);   cudaGetSymbolAddress((void**)&wekv_l, g_wekv_l);
    cudaGetSymbolAddress((void**)&weo_h, g_weo_h);     cudaGetSymbolAddress((void**)&weo_l, g_weo_l);
    cudaGetSymbolAddress((void**)&wf1_h, g_wf1_h);     cudaGetSymbolAddress((void**)&wf1_l, g_wf1_l);
    cudaGetSymbolAddress((void**)&wf2_h, g_wf2_h);     cudaGetSymbolAddress((void**)&wf2_l, g_wf2_l);
    cudaGetSymbolAddress((void**)&wpj_h, g_wpj_h);     cudaGetSymbolAddress((void**)&wpj_l, g_wpj_l);
    cudaGetSymbolAddress((void**)&bqkv, g_bqkv);       cudaGetSymbolAddress((void**)&bkv, g_bkv);

    cudaFuncSetAttribute(cross_attn_kernel, cudaFuncAttributeMaxDynamicSharedMemorySize, CROSS_SMEM);
    cudaFuncSetAttribute(mgemm_kernel<128, false, true,  false>, cudaFuncAttributeMaxDynamicSharedMemorySize, SMEM_128);
    cudaFuncSetAttribute(mgemm_kernel<128, true,  true,  true>,  cudaFuncAttributeMaxDynamicSharedMemorySize, SMEM_128);
    cudaFuncSetAttribute(mgemm_kernel<128, false, false, false>, cudaFuncAttributeMaxDynamicSharedMemorySize, SMEM_128);
    cudaFuncSetAttribute(mgemm_kernel<64,  false, true,  false>, cudaFuncAttributeMaxDynamicSharedMemorySize, SMEM_64);
    cudaFuncSetAttribute(mgemm_kernel<64,  false, false, false>, cudaFuncAttributeMaxDynamicSharedMemorySize, SMEM_64);

    // ---- weight prep: transpose + bf16 split, batched over layers ----
    const size_t DD = (size_t)Dm * Dm, ED = (size_t)ENCc * Dm;
    const dim3 tsb(32, 8);
    const dim3 gdd(Dm/32, Dm/64, NLc);
    tsplit_kernel<<<gdd, tsb>>>(sWq, wsqkv_h,        wsqkv_l,        Dm, Dm, DD, 3*DD);
    tsplit_kernel<<<gdd, tsb>>>(sWk, wsqkv_h + DD,   wsqkv_l + DD,   Dm, Dm, DD, 3*DD);
    tsplit_kernel<<<gdd, tsb>>>(sWv, wsqkv_h + 2*DD, wsqkv_l + 2*DD, Dm, Dm, DD, 3*DD);
    tsplit_kernel<<<gdd, tsb>>>(sWo, wso_h, wso_l, Dm, Dm, DD, DD);
    tsplit_kernel<<<gdd, tsb>>>(eWq, weq_h, weq_l, Dm, Dm, DD, DD);
    tsplit_kernel<<<gdd, tsb>>>(eWo, weo_h, weo_l, Dm, Dm, DD, DD);
    const dim3 gek(Dm/32, ENCc/64, NLc);
    tsplit_kernel<<<gek, tsb>>>(eWk, wekv_h,      wekv_l,      ENCc, Dm, ED, 2*ED);
    tsplit_kernel<<<gek, tsb>>>(eWv, wekv_h + ED, wekv_l + ED, ENCc, Dm, ED, 2*ED);
    tsplit_kernel<<<dim3(FFc/32, Dm/64, NLc), tsb>>>(fW1, wf1_h, wf1_l, Dm, FFc, ED, ED);
    tsplit_kernel<<<dim3(Dm/32, FFc/64, NLc), tsb>>>(fW2, wf2_h, wf2_l, FFc, Dm, ED, ED);
    split_kernel<<<((VOC*Dm/4) + 255)/256, 256>>>(pW, wpj_h, wpj_l, VOC*Dm/4);
    biascat3_kernel<<<(NLc*3*Dm + 255)/256, 256>>>(sbq, sbk, sbv, bqkv);
    biascat2_kernel<<<(NLc*2*Dm + 255)/256, 256>>>(ebk, ebv, bkv);

    // ---- prologue ----
    sort_kernel<<<1, Bz>>>(lengths, order);
    gather_caps_kernel<<<(MROW + 255) / 256, 256>>>(captions, order, caps);
    embed_kernel<<<(MROW * Dm + 255) / 256, 256>>>(caps, tgt_emb, pos_emb, x, ahi, alo);
    split_kernel<<<(((size_t)EROW*ENCc/4) + 255)/256, 256>>>(encoder_out, ehi, elo, EROW*ENCc/4);

    const dim3 gQKV(12, 26);    // M=3328, N=1536, BM=128
    const dim3 gD64(4, 52);     // M=3328, N=512,  BM=64
    const dim3 gKV(8, 98);      // M=12544, N=1024, BM=128
    const dim3 gFF1(16, 26);    // N=2048, BM=128
    const dim3 gPRJ(250, 26);   // N=32000, BM=128

    for (int l = 0; l < NLc; l++) {
        // ---- self attention ----
        mgemm_kernel<128, false, true, false><<<gQKV, 256, SMEM_128>>>(ahi, alo,
            wsqkv_h + l*3*DD, wsqkv_l + l*3*DD, bqkv + l*3*Dm, qkv, nullptr, nullptr, MROW, 3*Dm, Dm);
        self_attn_kernel<<<Bz * NH, 256>>>(qkv, caps, chi, clo);
        mgemm_kernel<64, false, false, false><<<gD64, 256, SMEM_64>>>(chi, clo,
            wso_h + l*DD, wso_l + l*DD, nullptr, y, nullptr, nullptr, MROW, Dm, Dm);
        ln_residual_kernel<<<MROW, 256>>>(y, sbo + l*Dm, x, x, ahi, alo);

        // ---- cross attention ----
        mgemm_kernel<64, false, true, false><<<gD64, 256, SMEM_64>>>(ahi, alo,
            weq_h + l*DD, weq_l + l*DD, ebq + l*Dm, q, nullptr, nullptr, MROW, Dm, Dm);
        mgemm_kernel<128, false, true, false><<<gKV, 256, SMEM_128>>>(ehi, elo,
            wekv_h + l*2*ED, wekv_l + l*2*ED, bkv + l*2*Dm, kv, nullptr, nullptr, EROW, 2*Dm, ENCc);
        cross_attn_kernel<<<Bz * NH, 256, CROSS_SMEM>>>(q, kv, order, chi, clo);
        mgemm_kernel<64, false, false, false><<<gD64, 256, SMEM_64>>>(chi, clo,
            weo_h + l*DD, weo_l + l*DD, nullptr, y, nullptr, nullptr, MROW, Dm, Dm);
        ln_residual_kernel<<<MROW, 256>>>(y, ebo + l*Dm, x, x, ahi, alo);

        // ---- FFN ----
        mgemm_kernel<128, true, true, true><<<gFF1, 256, SMEM_128>>>(ahi, alo,
            wf1_h + l*ED, wf1_l + l*ED, fb1 + l*FFc, nullptr, hhi, hlo, MROW, FFc, Dm);
        mgemm_kernel<64, false, false, false><<<gD64, 256, SMEM_64>>>(hhi, hlo,
            wf2_h + l*ED, wf2_l + l*ED, nullptr, y, nullptr, nullptr, MROW, Dm, FFc);
        ln_residual_kernel<<<MROW, 256>>>(y, fb2 + l*Dm, x, x, ahi, alo);
    }

    // ---- vocab projection ----
    mgemm_kernel<128, false, false, false><<<gPRJ, 256, SMEM_128>>>(ahi, alo,
        wpj_h, wpj_l, nullptr, out, nullptr, nullptr, MROW, VOC, Dm);
}

// round 7
// speedup vs baseline: 5.4779x; 1.0819x over previous
#include <cuda_runtime.h>
#include <cuda_bf16.h>
#include <math.h>
#include <stdint.h>

// ---------------- problem constants ----------------
#define Bz    64
#define LQ    52
#define Dm    512
#define NH    8
#define DKh   64
#define NPIXc 196
#define ENCc  2048
#define FFc   2048
#define NLc   6
#define MROW  (Bz*LQ)       // 3328
#define EROW  (Bz*NPIXc)    // 12544
#define VOC   32000

// ---------------- fp32 scratch ----------------
__device__ float g_x[MROW*Dm];
__device__ float g_y[MROW*Dm];
__device__ float g_q[MROW*Dm];
__device__ float g_qkv[MROW*3*Dm];
__device__ float g_kv[EROW*2*Dm];
__device__ int   g_order[Bz];
__device__ int   g_caps[MROW];

// ---------------- bf16 (ushort) scratch: activations ----------------
__device__ unsigned short g_ahi[MROW*Dm],  g_alo[MROW*Dm];
__device__ unsigned short g_chi[MROW*Dm],  g_clo[MROW*Dm];
__device__ unsigned short g_hhi[MROW*FFc], g_hlo[MROW*FFc];
__device__ unsigned short g_ehi[EROW*ENCc], g_elo[EROW*ENCc];

// ---------------- bf16 scratch: transposed weights [N,K] ----------------
__device__ unsigned short g_wsqkv_h[NLc*3*Dm*Dm],  g_wsqkv_l[NLc*3*Dm*Dm];
__device__ unsigned short g_wso_h[NLc*Dm*Dm],      g_wso_l[NLc*Dm*Dm];
__device__ unsigned short g_weq_h[NLc*Dm*Dm],      g_weq_l[NLc*Dm*Dm];
__device__ unsigned short g_wekv_h[NLc*2*Dm*ENCc], g_wekv_l[NLc*2*Dm*ENCc];
__device__ unsigned short g_weo_h[NLc*Dm*Dm],      g_weo_l[NLc*Dm*Dm];
__device__ unsigned short g_wf1_h[NLc*FFc*Dm],     g_wf1_l[NLc*FFc*Dm];
__device__ unsigned short g_wf2_h[NLc*Dm*FFc],     g_wf2_l[NLc*Dm*FFc];
__device__ unsigned short g_wpj_h[VOC*Dm],         g_wpj_l[VOC*Dm];
__device__ float g_bqkv[NLc*3*Dm];
__device__ float g_bkv[NLc*2*Dm];

extern __shared__ float csm[];

// ---------------- helpers ----------------
__device__ __forceinline__ uint32_t smem_u32(const void* p) {
    uint32_t a;
    asm("{ .reg .u64 t; cvta.to.shared.u64 t, %1; cvt.u32.u64 %0, t; }" : "=r"(a) : "l"(p));
    return a;
}
__device__ __forceinline__ void cpa16(uint32_t s, const void* g) {
    asm volatile("cp.async.cg.shared.global [%0], [%1], 16;" :: "r"(s), "l"(g));
}
#define CP_COMMIT() asm volatile("cp.async.commit_group;" ::: "memory")
#define CP_WAIT0()  asm volatile("cp.async.wait_group 0;" ::: "memory")
#define CP_WAIT1()  asm volatile("cp.async.wait_group 1;" ::: "memory")

#define MMA16816(c, a, b) \
    asm volatile("mma.sync.aligned.m16n8k16.row.col.f32.bf16.bf16.f32 " \
        "{%0,%1,%2,%3}, {%4,%5,%6,%7}, {%8,%9}, {%0,%1,%2,%3};" \
        : "+f"((c)[0]), "+f"((c)[1]), "+f"((c)[2]), "+f"((c)[3]) \
        : "r"((a)[0]), "r"((a)[1]), "r"((a)[2]), "r"((a)[3]), \
          "r"((b)[0]), "r"((b)[1]))

#define LDSM4(r0, r1, r2, r3, addr) \
    asm volatile("ldmatrix.sync.aligned.m8n8.x4.shared.b16 {%0,%1,%2,%3}, [%4];" \
        : "=r"(r0), "=r"(r1), "=r"(r2), "=r"(r3) : "r"(addr))

__device__ __forceinline__ void bsplit(float x, unsigned short& h, unsigned short& l) {
    __nv_bfloat16 hb = __float2bfloat16(x);
    float r = x - __bfloat162float(hb);
    __nv_bfloat16 lb = __float2bfloat16(r);
    h = __bfloat16_as_ushort(hb);
    l = __bfloat16_as_ushort(lb);
}

// ============ HMMA bf16x3 GEMM: C[M,N] = A[M,K] * Bt[N,K]^T + bias ============
// ldmatrix.x4 fragment loads; 80B smem row stride (conflict-free).
template<int BMt, bool RELU, bool HASBIAS, bool SPLIT>
__global__ __launch_bounds__(256, 2)
void mgemm_kernel(const unsigned short* __restrict__ Ahi, const unsigned short* __restrict__ Alo,
                  const unsigned short* __restrict__ Bhi, const unsigned short* __restrict__ Blo,
                  const float* __restrict__ bias, float* __restrict__ C,
                  unsigned short* __restrict__ Chi, unsigned short* __restrict__ Clo,
                  int M, int N, int K) {
    constexpr int BN = 128;
    constexpr int NWM = BMt / 32;
    constexpr int NWN = 8 / NWM;
    constexpr int NTN = BN / NWN;
    constexpr int NF  = NTN / 8;
    constexpr int ROWB = 80;
    constexpr int ASZ = BMt * ROWB;
    constexpr int BSZ = BN * ROWB;
    constexpr int STAGE = 2 * ASZ + 2 * BSZ;

    char* sm = (char*)csm;
    const int tid = threadIdx.x;
    const int wid = tid >> 5, lane = tid & 31;
    const int wm = wid / NWN, wn = wid % NWN;
    const int gr = lane >> 2, ck = lane & 3;
    const int m0 = blockIdx.y * BMt;
    const int n0 = blockIdx.x * BN;

    float acc[2][NF][4];
    #pragma unroll
    for (int mt = 0; mt < 2; mt++)
        #pragma unroll
        for (int nf = 0; nf < NF; nf++)
            #pragma unroll
            for (int j = 0; j < 4; j++) acc[mt][nf][j] = 0.f;

    const uint32_t smb = smem_u32(sm);

    // ldmatrix per-lane base offsets
    uint32_t aoff[2], boff[NF / 2];
    #pragma unroll
    for (int mt = 0; mt < 2; mt++)
        aoff[mt] = (uint32_t)(wm * 32 + mt * 16 + (lane & 15)) * ROWB + (lane & 16);
    #pragma unroll
    for (int p = 0; p < NF / 2; p++)
        boff[p] = (uint32_t)(wn * NTN + p * 16 + (lane & 7) + ((lane & 16) >> 1)) * ROWB
                  + ((lane & 8) << 1);

    auto load_stage = [&](int s, int k0) {
        const uint32_t sb = smb + s * STAGE;
        #pragma unroll
        for (int p = 0; p < BMt * 4 / 256; p++) {
            int id = tid + p * 256;
            int row = id >> 2, cc = id & 3;
            uint32_t so = row * ROWB + cc * 16;
            const size_t go = (size_t)(m0 + row) * K + k0 + cc * 8;
            cpa16(sb + so,        Ahi + go);
            cpa16(sb + ASZ + so,  Alo + go);
        }
        #pragma unroll
        for (int p = 0; p < 2; p++) {
            int id = tid + p * 256;
            int row = id >> 2, cc = id & 3;
            uint32_t so = row * ROWB + cc * 16;
            const size_t go = (size_t)(n0 + row) * K + k0 + cc * 8;
            cpa16(sb + 2*ASZ + so,       Bhi + go);
            cpa16(sb + 2*ASZ + BSZ + so, Blo + go);
        }
    };

    auto compute = [&](int s) {
        const uint32_t base = smb + s * STAGE;
        #pragma unroll
        for (int ks = 0; ks < 2; ks++) {
            const uint32_t kb = ks * 32;
            uint32_t ah[2][4], al[2][4], bh[NF][2], bl[NF][2];
            #pragma unroll
            for (int mt = 0; mt < 2; mt++) {
                LDSM4(ah[mt][0], ah[mt][1], ah[mt][2], ah[mt][3], base + aoff[mt] + kb);
                LDSM4(al[mt][0], al[mt][1], al[mt][2], al[mt][3], base + ASZ + aoff[mt] + kb);
            }
            #pragma unroll
            for (int p = 0; p < NF / 2; p++) {
                LDSM4(bh[2*p][0], bh[2*p][1], bh[2*p+1][0], bh[2*p+1][1],
                      base + 2*ASZ + boff[p] + kb);
                LDSM4(bl[2*p][0], bl[2*p][1], bl[2*p+1][0], bl[2*p+1][1],
                      base + 2*ASZ + BSZ + boff[p] + kb);
            }
            #pragma unroll
            for (int mt = 0; mt < 2; mt++)
                #pragma unroll
                for (int nf = 0; nf < NF; nf++)
                    MMA16816(acc[mt][nf], ah[mt], bh[nf]);
            #pragma unroll
            for (int mt = 0; mt < 2; mt++)
                #pragma unroll
                for (int nf = 0; nf < NF; nf++)
                    MMA16816(acc[mt][nf], ah[mt], bl[nf]);
            #pragma unroll
            for (int mt = 0; mt < 2; mt++)
                #pragma unroll
                for (int nf = 0; nf < NF; nf++)
                    MMA16816(acc[mt][nf], al[mt], bh[nf]);
        }
    };

    load_stage(0, 0);
    CP_COMMIT();
    const int chunks = K >> 5;
    for (int c = 0; c < chunks; c++) {
        if (c + 1 < chunks) {
            load_stage((c + 1) & 1, (c + 1) << 5);
            CP_COMMIT();
            CP_WAIT1();
        } else {
            CP_WAIT0();
        }
        __syncthreads();
        compute(c & 1);
        __syncthreads();
    }

    #pragma unroll
    for (int mt = 0; mt < 2; mt++) {
        const int r = m0 + wm * 32 + mt * 16 + gr;
        #pragma unroll
        for (int nf = 0; nf < NF; nf++) {
            const int cc = n0 + wn * NTN + nf * 8 + ck * 2;
            float v0 = acc[mt][nf][0], v1 = acc[mt][nf][1];
            float v2 = acc[mt][nf][2], v3 = acc[mt][nf][3];
            if (HASBIAS) {
                float b0 = bias[cc], b1 = bias[cc + 1];
                v0 += b0; v1 += b1; v2 += b0; v3 += b1;
            }
            if (RELU) {
                v0 = fmaxf(v0, 0.f); v1 = fmaxf(v1, 0.f);
                v2 = fmaxf(v2, 0.f); v3 = fmaxf(v3, 0.f);
            }
            if (SPLIT) {
                unsigned short h0,l0,h1,l1,h2,l2,h3,l3;
                bsplit(v0,h0,l0); bsplit(v1,h1,l1);
                bsplit(v2,h2,l2); bsplit(v3,h3,l3);
                ((uint32_t*)Chi)[((size_t)r * N + cc) >> 1]       = (uint32_t)h0 | ((uint32_t)h1 << 16);
                ((uint32_t*)Clo)[((size_t)r * N + cc) >> 1]       = (uint32_t)l0 | ((uint32_t)l1 << 16);
                ((uint32_t*)Chi)[((size_t)(r + 8) * N + cc) >> 1] = (uint32_t)h2 | ((uint32_t)h3 << 16);
                ((uint32_t*)Clo)[((size_t)(r + 8) * N + cc) >> 1] = (uint32_t)l2 | ((uint32_t)l3 << 16);
            } else {
                float2 w0; w0.x = v0; w0.y = v1;
                float2 w1; w1.x = v2; w1.y = v3;
                *(float2*)(C + (size_t)r * N + cc)       = w0;
                *(float2*)(C + (size_t)(r + 8) * N + cc) = w1;
            }
        }
    }
}

#define SMEM_128 (2 * (2*128*80 + 2*128*80))   // 81920
#define SMEM_64  (2 * (2*64*80  + 2*128*80))   // 61440

// ================= split (flat) =================
__global__ void split_kernel(const float* __restrict__ in, unsigned short* __restrict__ hi,
                             unsigned short* __restrict__ lo, int n4) {
    int i = blockIdx.x * 256 + threadIdx.x;
    if (i >= n4) return;
    float4 v = ((const float4*)in)[i];
    unsigned short h0,h1,h2,h3,l0,l1,l2,l3;
    bsplit(v.x,h0,l0); bsplit(v.y,h1,l1); bsplit(v.z,h2,l2); bsplit(v.w,h3,l3);
    uint2 hv, lv;
    hv.x = (uint32_t)h0 | ((uint32_t)h1 << 16); hv.y = (uint32_t)h2 | ((uint32_t)h3 << 16);
    lv.x = (uint32_t)l0 | ((uint32_t)l1 << 16); lv.y = (uint32_t)l2 | ((uint32_t)l3 << 16);
    *(uint2*)(hi + 4*(size_t)i) = hv;
    *(uint2*)(lo + 4*(size_t)i) = lv;
}

// ===== transpose+split, batched over layers (grid.z) =====
__global__ void tsplit_kernel(const float* __restrict__ W, unsigned short* __restrict__ hi,
                              unsigned short* __restrict__ lo, int K, int N,
                              size_t sstride, size_t dstride) {
    __shared__ float t[64][33];
    const int z = blockIdx.z;
    W  += (size_t)z * sstride;
    hi += (size_t)z * dstride;
    lo += (size_t)z * dstride;
    const int nb = blockIdx.x * 32, kb = blockIdx.y * 64;
    const int tx = threadIdx.x, ty = threadIdx.y;
    for (int r = ty; r < 64; r += 8)
        t[r][tx] = W[(size_t)(kb + r) * N + nb + tx];
    __syncthreads();
    for (int n = ty; n < 32; n += 8) {
        float x0 = t[2*tx][n], x1 = t[2*tx + 1][n];
        unsigned short h0,l0,h1,l1;
        bsplit(x0,h0,l0); bsplit(x1,h1,l1);
        size_t o = (((size_t)(nb + n) * K + kb) >> 1) + tx;
        ((uint32_t*)hi)[o] = (uint32_t)h0 | ((uint32_t)h1 << 16);
        ((uint32_t*)lo)[o] = (uint32_t)l0 | ((uint32_t)l1 << 16);
    }
}

__global__ void biascat3_kernel(const float* a, const float* b, const float* c, float* out) {
    int i = blockIdx.x * 256 + threadIdx.x;
    if (i >= NLc * 3 * Dm) return;
    int l = i / (3 * Dm), r = i % (3 * Dm);
    int w = r / Dm, j = r % Dm;
    const float* s = (w == 0) ? a : (w == 1) ? b : c;
    out[i] = s[l * Dm + j];
}
__global__ void biascat2_kernel(const float* a, const float* b, float* out) {
    int i = blockIdx.x * 256 + threadIdx.x;
    if (i >= NLc * 2 * Dm) return;
    int l = i / (2 * Dm), r = i % (2 * Dm);
    int w = r / Dm, j = r % Dm;
    const float* s = (w == 0) ? a : b;
    out[i] = s[l * Dm + j];
}

// ---------------- sort / gather / embed ----------------
__global__ void sort_kernel(const int* __restrict__ lens, int* __restrict__ order) {
    __shared__ int l[Bz];
    int b = threadIdx.x;
    l[b] = lens[b];
    __syncthreads();
    int myl = l[b], rank = 0;
    #pragma unroll
    for (int j = 0; j < Bz; j++)
        rank += (l[j] > myl) || (l[j] == myl && j < b);
    order[rank] = b;
}

__global__ void gather_caps_kernel(const int* __restrict__ caps, const int* __restrict__ order,
                                   int* __restrict__ out) {
    int idx = blockIdx.x * 256 + threadIdx.x;
    if (idx >= MROW) return;
    int b = idx / LQ, t = idx % LQ;
    out[idx] = caps[order[b] * LQ + t];
}

__global__ void embed_kernel(const int* __restrict__ caps, const float* __restrict__ tgt,
                             const float* __restrict__ pos, float* __restrict__ x,
                             unsigned short* __restrict__ hi, unsigned short* __restrict__ lo) {
    int idx = blockIdx.x * 256 + threadIdx.x;
    if (idx >= MROW * Dm) return;
    int d = idx & (Dm - 1);
    int rt = idx >> 9;
    int t = rt % LQ;
    int cap = caps[rt];
    float v = tgt[(size_t)cap * Dm + d] + pos[t * Dm + d];
    x[idx] = v;
    unsigned short h, l;
    bsplit(v, h, l);
    hi[idx] = h; lo[idx] = l;
}

// ---------------- self attention ----------------
__global__ __launch_bounds__(256)
void self_attn_kernel(const float* __restrict__ qkv, const int* __restrict__ caps,
                      unsigned short* __restrict__ chi, unsigned short* __restrict__ clo) {
    __shared__ float Ks[64][65];
    __shared__ float Vs[64][64];
    __shared__ float ps[8][LQ];
    __shared__ int pad[64];
    const int b = blockIdx.x >> 3;
    const int h = blockIdx.x & 7;
    const int tid = threadIdx.x;
    const int lane = tid & 31, w = tid >> 5;

    for (int i = tid; i < 64 * 64; i += 256) {
        int t = i >> 6, d = i & 63;
        if (t < LQ) {
            size_t src = (size_t)(b * LQ + t) * (3 * Dm) + h * DKh + d;
            Ks[t][d] = qkv[src + Dm];
            Vs[t][d] = qkv[src + 2 * Dm];
        } else {
            Ks[t][d] = 0.f; Vs[t][d] = 0.f;
        }
    }
    if (tid < 64) pad[tid] = (tid < LQ) ? (caps[b * LQ + tid] == 0) : 1;
    __syncthreads();

    for (int q = w; q < LQ; q += 8) {
        const float* qp = qkv + (size_t)(b * LQ + q) * (3 * Dm) + h * DKh;
        float q0 = qp[lane], q1 = qp[lane + 32];
        float a0 = 0.f, a1 = 0.f;
        #pragma unroll
        for (int d = 0; d < 64; d++) {
            float qv = (d < 32) ? __shfl_sync(0xffffffffu, q0, d)
                                : __shfl_sync(0xffffffffu, q1, d - 32);
            a0 += qv * Ks[lane][d];
            a1 += qv * Ks[lane + 32][d];
        }
        const int k1 = lane + 32;
        float s0 = (lane > q || pad[lane]) ? -1e9f : a0 * 0.125f;
        float s1 = (k1 >= LQ) ? -1e30f : ((k1 > q || pad[k1]) ? -1e9f : a1 * 0.125f);
        float m = fmaxf(s0, s1);
        #pragma unroll
        for (int o = 16; o > 0; o >>= 1) m = fmaxf(m, __shfl_xor_sync(0xffffffffu, m, o));
        float e0 = __expf(s0 - m);
        float e1 = __expf(s1 - m);
        float sum = e0 + e1;
        #pragma unroll
        for (int o = 16; o > 0; o >>= 1) sum += __shfl_xor_sync(0xffffffffu, sum, o);
        float inv = 1.f / sum;
        ps[w][lane] = e0;
        if (k1 < LQ) ps[w][k1] = e1;
        __syncwarp();
        float c0 = 0.f, c1 = 0.f;
        #pragma unroll 4
        for (int k = 0; k < LQ; k++) {
            float p = ps[w][k];
            c0 += p * Vs[k][lane];
            c1 += p * Vs[k][lane + 32];
        }
        size_t base = (size_t)(b * LQ + q) * Dm + h * DKh;
        unsigned short hh, ll;
        bsplit(c0 * inv, hh, ll);
        chi[base + lane] = hh; clo[base + lane] = ll;
        bsplit(c1 * inv, hh, ll);
        chi[base + lane + 32] = hh; clo[base + lane + 32] = ll;
        __syncwarp();
    }
}

// ---------------- cross attention ----------------
#define KS_STR 68
__global__ __launch_bounds__(256)
void cross_attn_kernel(const float* __restrict__ Q, const float* __restrict__ KV,
                       const int* __restrict__ order,
                       unsigned short* __restrict__ chi, unsigned short* __restrict__ clo) {
    float* Ks = csm;
    float* Vs = Ks + NPIXc * KS_STR;
    float* ps = Vs + NPIXc * DKh;
    const int b = blockIdx.x >> 3;
    const int h = blockIdx.x & 7;
    const int tid = threadIdx.x;
    const int lane = tid & 31, w = tid >> 5;
    const int ob = order[b];

    for (int i = tid; i < NPIXc * DKh; i += 256) {
        int t = i >> 6, d = i & 63;
        size_t src = (size_t)(ob * NPIXc + t) * (2 * Dm) + h * DKh + d;
        Ks[t * KS_STR + d] = KV[src];
        Vs[t * DKh + d]    = KV[src + Dm];
    }
    __syncthreads();

    for (int qi = w; qi < LQ / 2; qi += 8) {
        const int q0 = 2 * qi;
        const float* qp = Q + (size_t)(b * LQ + q0) * Dm + h * DKh;
        float qa0 = qp[lane], qb0 = qp[lane + 32];
        float qa1 = qp[Dm + lane], qb1 = qp[Dm + lane + 32];

        float s0[7], s1[7];
        #pragma unroll
        for (int kk = 0; kk < 7; kk++) { s0[kk] = 0.f; s1[kk] = 0.f; }

        #pragma unroll
        for (int d4 = 0; d4 < 16; d4++) {
            float qv0[4], qv1[4];
            #pragma unroll
            for (int j = 0; j < 4; j++) {
                int d = 4 * d4 + j;
                qv0[j] = (d < 32) ? __shfl_sync(0xffffffffu, qa0, d)
                                  : __shfl_sync(0xffffffffu, qb0, d - 32);
                qv1[j] = (d < 32) ? __shfl_sync(0xffffffffu, qa1, d)
                                  : __shfl_sync(0xffffffffu, qb1, d - 32);
            }
            #pragma unroll
            for (int kk = 0; kk < 7; kk++) {
                const int key = kk * 32 + lane;
                float4 kv4 = *(const float4*)(Ks + key * KS_STR + 4 * d4);
                s0[kk] += qv0[0]*kv4.x + qv0[1]*kv4.y + qv0[2]*kv4.z + qv0[3]*kv4.w;
                s1[kk] += qv1[0]*kv4.x + qv1[1]*kv4.y + qv1[2]*kv4.z + qv1[3]*kv4.w;
            }
        }
        float m0 = -1e30f, m1 = -1e30f;
        #pragma unroll
        for (int kk = 0; kk < 7; kk++) {
            const int key = kk * 32 + lane;
            s0[kk] = (key < NPIXc) ? s0[kk] * 0.125f : -1e30f;
            s1[kk] = (key < NPIXc) ? s1[kk] * 0.125f : -1e30f;
            m0 = fmaxf(m0, s0[kk]); m1 = fmaxf(m1, s1[kk]);
        }
        #pragma unroll
        for (int o = 16; o > 0; o >>= 1) {
            m0 = fmaxf(m0, __shfl_xor_sync(0xffffffffu, m0, o));
            m1 = fmaxf(m1, __shfl_xor_sync(0xffffffffu, m1, o));
        }
        float sum0 = 0.f, sum1 = 0.f;
        #pragma unroll
        for (int kk = 0; kk < 7; kk++) {
            const int key = kk * 32 + lane;
            float e0 = __expf(s0[kk] - m0);
            float e1 = __expf(s1[kk] - m1);
            sum0 += e0; sum1 += e1;
            if (key < NPIXc) {
                ps[(2 * w) * NPIXc + key]     = e0;
                ps[(2 * w + 1) * NPIXc + key] = e1;
            }
        }
        #pragma unroll
        for (int o = 16; o > 0; o >>= 1) {
            sum0 += __shfl_xor_sync(0xffffffffu, sum0, o);
            sum1 += __shfl_xor_sync(0xffffffffu, sum1, o);
        }
        float inv0 = 1.f / sum0, inv1 = 1.f / sum1;
        __syncwarp();

        float c00 = 0.f, c01 = 0.f, c10 = 0.f, c11 = 0.f;
        const float* p0p = ps + (2 * w) * NPIXc;
        const float* p1p = ps + (2 * w + 1) * NPIXc;
        #pragma unroll 4
        for (int k = 0; k < NPIXc; k++) {
            float2 vv = *(const float2*)(Vs + k * DKh + 2 * lane);
            float p0 = p0p[k], p1 = p1p[k];
            c00 += p0 * vv.x; c01 += p0 * vv.y;
            c10 += p1 * vv.x; c11 += p1 * vv.y;
        }
        size_t base = (size_t)(b * LQ + q0) * Dm + h * DKh + 2 * lane;
        unsigned short h0,l0,h1,l1;
        bsplit(c00 * inv0, h0, l0); bsplit(c01 * inv0, h1, l1);
        ((uint32_t*)chi)[base >> 1] = (uint32_t)h0 | ((uint32_t)h1 << 16);
        ((uint32_t*)clo)[base >> 1] = (uint32_t)l0 | ((uint32_t)l1 << 16);
        bsplit(c10 * inv1, h0, l0); bsplit(c11 * inv1, h1, l1);
        ((uint32_t*)chi)[(base + Dm) >> 1] = (uint32_t)h0 | ((uint32_t)h1 << 16);
        ((uint32_t*)clo)[(base + Dm) >> 1] = (uint32_t)l0 | ((uint32_t)l1 << 16);
        __syncwarp();
    }
}
#define CROSS_SMEM ((NPIXc*KS_STR + NPIXc*DKh + 16*NPIXc) * (int)sizeof(float))

// ---------------- LayerNorm(residual + bias), emits fp32 + bf16 split ----------------
__global__ __launch_bounds__(256)
void ln_residual_kernel(const float* __restrict__ y, const float* __restrict__ bias,
                        const float* __restrict__ xin, float* __restrict__ xout,
                        unsigned short* __restrict__ hi, unsigned short* __restrict__ lo) {
    int r = blockIdx.x, tid = threadIdx.x;
    __shared__ float red[256];
    size_t base = (size_t)r * Dm;
    float v0 = y[base + tid]       + bias[tid]       + xin[base + tid];
    float v1 = y[base + 256 + tid] + bias[256 + tid] + xin[base + 256 + tid];
    red[tid] = v0 + v1; __syncthreads();
    #pragma unroll
    for (int st = 128; st > 0; st >>= 1) {
        if (tid < st) red[tid] += red[tid + st];
        __syncthreads();
    }
    float m = red[0] * (1.f / Dm);
    __syncthreads();
    float d0 = v0 - m, d1 = v1 - m;
    red[tid] = d0 * d0 + d1 * d1; __syncthreads();
    #pragma unroll
    for (int st = 128; st > 0; st >>= 1) {
        if (tid < st) red[tid] += red[tid + st];
        __syncthreads();
    }
    float inv = rsqrtf(red[0] * (1.f / Dm) + 1e-5f);
    float o0 = d0 * inv, o1 = d1 * inv;
    xout[base + tid]       = o0;
    xout[base + 256 + tid] = o1;
    unsigned short h, l;
    bsplit(o0, h, l); hi[base + tid] = h;       lo[base + tid] = l;
    bsplit(o1, h, l); hi[base + 256 + tid] = h; lo[base + 256 + tid] = l;
}

// ---------------- host side ----------------
extern "C" void kernel_launch(void* const* d_in, const int* in_sizes, int n_in,
                              void* d_out, int out_size) {
    const float* encoder_out = (const float*)d_in[0];
    const int*   captions    = (const int*)d_in[1];
    const int*   lengths     = (const int*)d_in[2];
    const float* tgt_emb     = (const float*)d_in[3];
    const float* pos_emb     = (const float*)d_in[4];
    const float* sWq = (const float*)d_in[5];  const float* sbq = (const float*)d_in[6];
    const float* sWk = (const float*)d_in[7];  const float* sbk = (const float*)d_in[8];
    const float* sWv = (const float*)d_in[9];  const float* sbv = (const float*)d_in[10];
    const float* sWo = (const float*)d_in[11]; const float* sbo = (const float*)d_in[12];
    const float* eWq = (const float*)d_in[13]; const float* ebq = (const float*)d_in[14];
    const float* eWk = (const float*)d_in[15]; const float* ebk = (const float*)d_in[16];
    const float* eWv = (const float*)d_in[17]; const float* ebv = (const float*)d_in[18];
    const float* eWo = (const float*)d_in[19]; const float* ebo = (const float*)d_in[20];
    const float* fW1 = (const float*)d_in[21]; const float* fb1 = (const float*)d_in[22];
    const float* fW2 = (const float*)d_in[23]; const float* fb2 = (const float*)d_in[24];
    const float* pW  = (const float*)d_in[25];
    float* out = (float*)d_out;

    float *x, *y, *q, *qkv, *kv, *bqkv, *bkv;
    int *order, *caps;
    unsigned short *ahi, *alo, *chi, *clo, *hhi, *hlo, *ehi, *elo;
    unsigned short *wsqkv_h, *wsqkv_l, *wso_h, *wso_l, *weq_h, *weq_l;
    unsigned short *wekv_h, *wekv_l, *weo_h, *weo_l, *wf1_h, *wf1_l, *wf2_h, *wf2_l, *wpj_h, *wpj_l;
    cudaGetSymbolAddress((void**)&x, g_x);       cudaGetSymbolAddress((void**)&y, g_y);
    cudaGetSymbolAddress((void**)&q, g_q);       cudaGetSymbolAddress((void**)&qkv, g_qkv);
    cudaGetSymbolAddress((void**)&kv, g_kv);
    cudaGetSymbolAddress((void**)&order, g_order); cudaGetSymbolAddress((void**)&caps, g_caps);
    cudaGetSymbolAddress((void**)&ahi, g_ahi);   cudaGetSymbolAddress((void**)&alo, g_alo);
    cudaGetSymbolAddress((void**)&chi, g_chi);   cudaGetSymbolAddress((void**)&clo, g_clo);
    cudaGetSymbolAddress((void**)&hhi, g_hhi);   cudaGetSymbolAddress((void**)&hlo, g_hlo);
    cudaGetSymbolAddress((void**)&ehi, g_ehi);   cudaGetSymbolAddress((void**)&elo, g_elo);
    cudaGetSymbolAddress((void**)&wsqkv_h, g_wsqkv_h); cudaGetSymbolAddress((void**)&wsqkv_l, g_wsqkv_l);
    cudaGetSymbolAddress((void**)&wso_h, g_wso_h);     cudaGetSymbolAddress((void**)&wso_l, g_wso_l);
    cudaGetSymbolAddress((void**)&weq_h, g_weq_h);     cudaGetSymbolAddress((void**)&weq_l, g_weq_l);
    cudaGetSymbolAddress((void**)&wekv_h, g_wekv_h);   cudaGetSymbolAddress((void**)&wekv_l, g_wekv_l);
    cudaGetSymbolAddress((void**)&weo_h, g_weo_h);     cudaGetSymbolAddress((void**)&weo_l, g_weo_l);
    cudaGetSymbolAddress((void**)&wf1_h, g_wf1_h);     cudaGetSymbolAddress((void**)&wf1_l, g_wf1_l);
    cudaGetSymbolAddress((void**)&wf2_h, g_wf2_h);     cudaGetSymbolAddress((void**)&wf2_l, g_wf2_l);
    cudaGetSymbolAddress((void**)&wpj_h, g_wpj_h);     cudaGetSymbolAddress((void**)&wpj_l, g_wpj_l);
    cudaGetSymbolAddress((void**)&bqkv, g_bqkv);       cudaGetSymbolAddress((void**)&bkv, g_bkv);

    cudaFuncSetAttribute(cross_attn_kernel, cudaFuncAttributeMaxDynamicSharedMemorySize, CROSS_SMEM);
    cudaFuncSetAttribute(mgemm_kernel<128, false, true,  false>, cudaFuncAttributeMaxDynamicSharedMemorySize, SMEM_128);
    cudaFuncSetAttribute(mgemm_kernel<128, true,  true,  true>,  cudaFuncAttributeMaxDynamicSharedMemorySize, SMEM_128);
    cudaFuncSetAttribute(mgemm_kernel<128, false, false, false>, cudaFuncAttributeMaxDynamicSharedMemorySize, SMEM_128);
    cudaFuncSetAttribute(mgemm_kernel<64,  false, true,  false>, cudaFuncAttributeMaxDynamicSharedMemorySize, SMEM_64);
    cudaFuncSetAttribute(mgemm_kernel<64,  false, false, false>, cudaFuncAttributeMaxDynamicSharedMemorySize, SMEM_64);

    // ---- weight prep ----
    const size_t DD = (size_t)Dm * Dm, ED = (size_t)ENCc * Dm;
    const dim3 tsb(32, 8);
    const dim3 gdd(Dm/32, Dm/64, NLc);
    tsplit_kernel<<<gdd, tsb>>>(sWq, wsqkv_h,        wsqkv_l,        Dm, Dm, DD, 3*DD);
    tsplit_kernel<<<gdd, tsb>>>(sWk, wsqkv_h + DD,   wsqkv_l + DD,   Dm, Dm, DD, 3*DD);
    tsplit_kernel<<<gdd, tsb>>>(sWv, wsqkv_h + 2*DD, wsqkv_l + 2*DD, Dm, Dm, DD, 3*DD);
    tsplit_kernel<<<gdd, tsb>>>(sWo, wso_h, wso_l, Dm, Dm, DD, DD);
    tsplit_kernel<<<gdd, tsb>>>(eWq, weq_h, weq_l, Dm, Dm, DD, DD);
    tsplit_kernel<<<gdd, tsb>>>(eWo, weo_h, weo_l, Dm, Dm, DD, DD);
    const dim3 gek(Dm/32, ENCc/64, NLc);
    tsplit_kernel<<<gek, tsb>>>(eWk, wekv_h,      wekv_l,      ENCc, Dm, ED, 2*ED);
    tsplit_kernel<<<gek, tsb>>>(eWv, wekv_h + ED, wekv_l + ED, ENCc, Dm, ED, 2*ED);
    tsplit_kernel<<<dim3(FFc/32, Dm/64, NLc), tsb>>>(fW1, wf1_h, wf1_l, Dm, FFc, ED, ED);
    tsplit_kernel<<<dim3(Dm/32, FFc/64, NLc), tsb>>>(fW2, wf2_h, wf2_l, FFc, Dm, ED, ED);
    split_kernel<<<((VOC*Dm/4) + 255)/256, 256>>>(pW, wpj_h, wpj_l, VOC*Dm/4);
    biascat3_kernel<<<(NLc*3*Dm + 255)/256, 256>>>(sbq, sbk, sbv, bqkv);
    biascat2_kernel<<<(NLc*2*Dm + 255)/256, 256>>>(ebk, ebv, bkv);

    // ---- prologue ----
    sort_kernel<<<1, Bz>>>(lengths, order);
    gather_caps_kernel<<<(MROW + 255) / 256, 256>>>(captions, order, caps);
    embed_kernel<<<(MROW * Dm + 255) / 256, 256>>>(caps, tgt_emb, pos_emb, x, ahi, alo);
    split_kernel<<<(((size_t)EROW*ENCc/4) + 255)/256, 256>>>(encoder_out, ehi, elo, EROW*ENCc/4);

    const dim3 gQKV(12, 26);
    const dim3 gD64(4, 52);
    const dim3 gKV(8, 98);
    const dim3 gFF1(16, 26);
    const dim3 gPRJ(250, 26);

    for (int l = 0; l < NLc; l++) {
        // ---- self attention ----
        mgemm_kernel<128, false, true, false><<<gQKV, 256, SMEM_128>>>(ahi, alo,
            wsqkv_h + l*3*DD, wsqkv_l + l*3*DD, bqkv + l*3*Dm, qkv, nullptr, nullptr, MROW, 3*Dm, Dm);
        self_attn_kernel<<<Bz * NH, 256>>>(qkv, caps, chi, clo);
        mgemm_kernel<64, false, false, false><<<gD64, 256, SMEM_64>>>(chi, clo,
            wso_h + l*DD, wso_l + l*DD, nullptr, y, nullptr, nullptr, MROW, Dm, Dm);
        ln_residual_kernel<<<MROW, 256>>>(y, sbo + l*Dm, x, x, ahi, alo);

        // ---- cross attention ----
        mgemm_kernel<64, false, true, false><<<gD64, 256, SMEM_64>>>(ahi, alo,
            weq_h + l*DD, weq_l + l*DD, ebq + l*Dm, q, nullptr, nullptr, MROW, Dm, Dm);
        mgemm_kernel<128, false, true, false><<<gKV, 256, SMEM_128>>>(ehi, elo,
            wekv_h + l*2*ED, wekv_l + l*2*ED, bkv + l*2*Dm, kv, nullptr, nullptr, EROW, 2*Dm, ENCc);
        cross_attn_kernel<<<Bz * NH, 256, CROSS_SMEM>>>(q, kv, order, chi, clo);
        mgemm_kernel<64, false, false, false><<<gD64, 256, SMEM_64>>>(chi, clo,
            weo_h + l*DD, weo_l + l*DD, nullptr, y, nullptr, nullptr, MROW, Dm, Dm);
        ln_residual_kernel<<<MROW, 256>>>(y, ebo + l*Dm, x, x, ahi, alo);

        // ---- FFN ----
        mgemm_kernel<128, true, true, true><<<gFF1, 256, SMEM_128>>>(ahi, alo,
            wf1_h + l*ED, wf1_l + l*ED, fb1 + l*FFc, nullptr, hhi, hlo, MROW, FFc, Dm);
        mgemm_kernel<64, false, false, false><<<gD64, 256, SMEM_64>>>(hhi, hlo,
            wf2_h + l*ED, wf2_l + l*ED, nullptr, y, nullptr, nullptr, MROW, Dm, FFc);
        ln_residual_kernel<<<MROW, 256>>>(y, fb2 + l*Dm, x, x, ahi, alo);
    }

    // ---- vocab projection ----
    mgemm_kernel<128, false, false, false><<<gPRJ, 256, SMEM_128>>>(ahi, alo,
        wpj_h, wpj_l, nullptr, out, nullptr, nullptr, MROW, VOC, Dm);
}

// round 9
// speedup vs baseline: 7.8920x; 1.4407x over previous
#include <cuda_runtime.h>
#include <cuda_bf16.h>
#include <cuda_fp16.h>
#include <math.h>
#include <stdint.h>

// ---------------- problem constants ----------------
#define Bz    64
#define LQ    52
#define Dm    512
#define NH    8
#define DKh   64
#define NPIXc 196
#define ENCc  2048
#define FFc   2048
#define NLc   6
#define MROW  (Bz*LQ)       // 3328
#define EROW  (Bz*NPIXc)    // 12544
#define VOC   32000

// ---------------- fp32 scratch ----------------
__device__ float g_x[MROW*Dm];
__device__ float g_y[MROW*Dm];
__device__ float g_q[MROW*Dm];
__device__ float g_qkv[MROW*3*Dm];
__device__ float g_kv[EROW*2*Dm];
__device__ int   g_order[Bz];
__device__ int   g_caps[MROW];

// ---------------- bf16 (ushort) scratch: activations ----------------
__device__ unsigned short g_ahi[MROW*Dm],  g_alo[MROW*Dm];
__device__ unsigned short g_chi[MROW*Dm],  g_clo[MROW*Dm];
__device__ unsigned short g_hhi[MROW*FFc], g_hlo[MROW*FFc];

// ---------------- fp16 scratch (single precision-pass path) ----------------
__device__ unsigned short g_efp[EROW*ENCc];            // encoder fp16
__device__ unsigned short g_wekvf[NLc*2*Dm*ENCc];      // enc K/V weights fp16 [N,K]
__device__ unsigned short g_wpjf[VOC*Dm];              // vocab proj fp16 [N,K]
__device__ unsigned short g_xf[MROW*Dm];               // final x fp16

// ---------------- bf16 scratch: transposed weights [N,K] ----------------
__device__ unsigned short g_wsqkv_h[NLc*3*Dm*Dm],  g_wsqkv_l[NLc*3*Dm*Dm];
__device__ unsigned short g_wso_h[NLc*Dm*Dm],      g_wso_l[NLc*Dm*Dm];
__device__ unsigned short g_weq_h[NLc*Dm*Dm],      g_weq_l[NLc*Dm*Dm];
__device__ unsigned short g_weo_h[NLc*Dm*Dm],      g_weo_l[NLc*Dm*Dm];
__device__ unsigned short g_wf1_h[NLc*FFc*Dm],     g_wf1_l[NLc*FFc*Dm];
__device__ unsigned short g_wf2_h[NLc*Dm*FFc],     g_wf2_l[NLc*Dm*FFc];
__device__ float g_bqkv[NLc*3*Dm];
__device__ float g_bkv[NLc*2*Dm];

extern __shared__ float csm[];

// ---------------- helpers ----------------
__device__ __forceinline__ uint32_t smem_u32(const void* p) {
    uint32_t a;
    asm("{ .reg .u64 t; cvta.to.shared.u64 t, %1; cvt.u32.u64 %0, t; }" : "=r"(a) : "l"(p));
    return a;
}
__device__ __forceinline__ void cpa16(uint32_t s, const void* g) {
    asm volatile("cp.async.cg.shared.global [%0], [%1], 16;" :: "r"(s), "l"(g));
}
#define CP_COMMIT() asm volatile("cp.async.commit_group;" ::: "memory")
#define CP_WAIT0()  asm volatile("cp.async.wait_group 0;" ::: "memory")
#define CP_WAIT1()  asm volatile("cp.async.wait_group 1;" ::: "memory")

#define MMA16816(c, a, b) \
    asm volatile("mma.sync.aligned.m16n8k16.row.col.f32.bf16.bf16.f32 " \
        "{%0,%1,%2,%3}, {%4,%5,%6,%7}, {%8,%9}, {%0,%1,%2,%3};" \
        : "+f"((c)[0]), "+f"((c)[1]), "+f"((c)[2]), "+f"((c)[3]) \
        : "r"((a)[0]), "r"((a)[1]), "r"((a)[2]), "r"((a)[3]), \
          "r"((b)[0]), "r"((b)[1]))

#define MMAF16(c, a, b) \
    asm volatile("mma.sync.aligned.m16n8k16.row.col.f32.f16.f16.f32 " \
        "{%0,%1,%2,%3}, {%4,%5,%6,%7}, {%8,%9}, {%0,%1,%2,%3};" \
        : "+f"((c)[0]), "+f"((c)[1]), "+f"((c)[2]), "+f"((c)[3]) \
        : "r"((a)[0]), "r"((a)[1]), "r"((a)[2]), "r"((a)[3]), \
          "r"((b)[0]), "r"((b)[1]))

#define LDSM4(r0, r1, r2, r3, addr) \
    asm volatile("ldmatrix.sync.aligned.m8n8.x4.shared.b16 {%0,%1,%2,%3}, [%4];" \
        : "=r"(r0), "=r"(r1), "=r"(r2), "=r"(r3) : "r"(addr))

__device__ __forceinline__ void bsplit(float x, unsigned short& h, unsigned short& l) {
    __nv_bfloat16 hb = __float2bfloat16(x);
    float r = x - __bfloat162float(hb);
    __nv_bfloat16 lb = __float2bfloat16(r);
    h = __bfloat16_as_ushort(hb);
    l = __bfloat16_as_ushort(lb);
}

// ============ HMMA bf16x3 GEMM: C[M,N] = A[M,K] * Bt[N,K]^T + bias ============
template<int BMt, bool RELU, bool HASBIAS, bool SPLIT>
__global__ __launch_bounds__(256, 2)
void mgemm_kernel(const unsigned short* __restrict__ Ahi, const unsigned short* __restrict__ Alo,
                  const unsigned short* __restrict__ Bhi, const unsigned short* __restrict__ Blo,
                  const float* __restrict__ bias, float* __restrict__ C,
                  unsigned short* __restrict__ Chi, unsigned short* __restrict__ Clo,
                  int M, int N, int K) {
    constexpr int BN = 128;
    constexpr int NWM = BMt / 32;
    constexpr int NWN = 8 / NWM;
    constexpr int NTN = BN / NWN;
    constexpr int NF  = NTN / 8;
    constexpr int ROWB = 80;
    constexpr int ASZ = BMt * ROWB;
    constexpr int BSZ = BN * ROWB;
    constexpr int STAGE = 2 * ASZ + 2 * BSZ;

    char* sm = (char*)csm;
    const int tid = threadIdx.x;
    const int wid = tid >> 5, lane = tid & 31;
    const int wm = wid / NWN, wn = wid % NWN;
    const int gr = lane >> 2, ck = lane & 3;
    const int m0 = blockIdx.y * BMt;
    const int n0 = blockIdx.x * BN;

    float acc[2][NF][4];
    #pragma unroll
    for (int mt = 0; mt < 2; mt++)
        #pragma unroll
        for (int nf = 0; nf < NF; nf++)
            #pragma unroll
            for (int j = 0; j < 4; j++) acc[mt][nf][j] = 0.f;

    const uint32_t smb = smem_u32(sm);

    uint32_t aoff[2], boff[NF / 2];
    #pragma unroll
    for (int mt = 0; mt < 2; mt++)
        aoff[mt] = (uint32_t)(wm * 32 + mt * 16 + (lane & 15)) * ROWB + (lane & 16);
    #pragma unroll
    for (int p = 0; p < NF / 2; p++)
        boff[p] = (uint32_t)(wn * NTN + p * 16 + (lane & 7) + ((lane & 16) >> 1)) * ROWB
                  + ((lane & 8) << 1);

    auto load_stage = [&](int s, int k0) {
        const uint32_t sb = smb + s * STAGE;
        #pragma unroll
        for (int p = 0; p < BMt * 4 / 256; p++) {
            int id = tid + p * 256;
            int row = id >> 2, cc = id & 3;
            uint32_t so = row * ROWB + cc * 16;
            const size_t go = (size_t)(m0 + row) * K + k0 + cc * 8;
            cpa16(sb + so,        Ahi + go);
            cpa16(sb + ASZ + so,  Alo + go);
        }
        #pragma unroll
        for (int p = 0; p < 2; p++) {
            int id = tid + p * 256;
            int row = id >> 2, cc = id & 3;
            uint32_t so = row * ROWB + cc * 16;
            const size_t go = (size_t)(n0 + row) * K + k0 + cc * 8;
            cpa16(sb + 2*ASZ + so,       Bhi + go);
            cpa16(sb + 2*ASZ + BSZ + so, Blo + go);
        }
    };

    auto compute = [&](int s) {
        const uint32_t base = smb + s * STAGE;
        #pragma unroll
        for (int ks = 0; ks < 2; ks++) {
            const uint32_t kb = ks * 32;
            uint32_t ah[2][4], al[2][4], bh[NF][2], bl[NF][2];
            #pragma unroll
            for (int mt = 0; mt < 2; mt++) {
                LDSM4(ah[mt][0], ah[mt][1], ah[mt][2], ah[mt][3], base + aoff[mt] + kb);
                LDSM4(al[mt][0], al[mt][1], al[mt][2], al[mt][3], base + ASZ + aoff[mt] + kb);
            }
            #pragma unroll
            for (int p = 0; p < NF / 2; p++) {
                LDSM4(bh[2*p][0], bh[2*p][1], bh[2*p+1][0], bh[2*p+1][1],
                      base + 2*ASZ + boff[p] + kb);
                LDSM4(bl[2*p][0], bl[2*p][1], bl[2*p+1][0], bl[2*p+1][1],
                      base + 2*ASZ + BSZ + boff[p] + kb);
            }
            #pragma unroll
            for (int mt = 0; mt < 2; mt++)
                #pragma unroll
                for (int nf = 0; nf < NF; nf++)
                    MMA16816(acc[mt][nf], ah[mt], bh[nf]);
            #pragma unroll
            for (int mt = 0; mt < 2; mt++)
                #pragma unroll
                for (int nf = 0; nf < NF; nf++)
                    MMA16816(acc[mt][nf], ah[mt], bl[nf]);
            #pragma unroll
            for (int mt = 0; mt < 2; mt++)
                #pragma unroll
                for (int nf = 0; nf < NF; nf++)
                    MMA16816(acc[mt][nf], al[mt], bh[nf]);
        }
    };

    load_stage(0, 0);
    CP_COMMIT();
    const int chunks = K >> 5;
    for (int c = 0; c < chunks; c++) {
        if (c + 1 < chunks) {
            load_stage((c + 1) & 1, (c + 1) << 5);
            CP_COMMIT();
            CP_WAIT1();
        } else {
            CP_WAIT0();
        }
        __syncthreads();
        compute(c & 1);
        __syncthreads();
    }

    #pragma unroll
    for (int mt = 0; mt < 2; mt++) {
        const int r = m0 + wm * 32 + mt * 16 + gr;
        #pragma unroll
        for (int nf = 0; nf < NF; nf++) {
            const int cc = n0 + wn * NTN + nf * 8 + ck * 2;
            float v0 = acc[mt][nf][0], v1 = acc[mt][nf][1];
            float v2 = acc[mt][nf][2], v3 = acc[mt][nf][3];
            if (HASBIAS) {
                float b0 = bias[cc], b1 = bias[cc + 1];
                v0 += b0; v1 += b1; v2 += b0; v3 += b1;
            }
            if (RELU) {
                v0 = fmaxf(v0, 0.f); v1 = fmaxf(v1, 0.f);
                v2 = fmaxf(v2, 0.f); v3 = fmaxf(v3, 0.f);
            }
            if (SPLIT) {
                unsigned short h0,l0,h1,l1,h2,l2,h3,l3;
                bsplit(v0,h0,l0); bsplit(v1,h1,l1);
                bsplit(v2,h2,l2); bsplit(v3,h3,l3);
                ((uint32_t*)Chi)[((size_t)r * N + cc) >> 1]       = (uint32_t)h0 | ((uint32_t)h1 << 16);
                ((uint32_t*)Clo)[((size_t)r * N + cc) >> 1]       = (uint32_t)l0 | ((uint32_t)l1 << 16);
                ((uint32_t*)Chi)[((size_t)(r + 8) * N + cc) >> 1] = (uint32_t)h2 | ((uint32_t)h3 << 16);
                ((uint32_t*)Clo)[((size_t)(r + 8) * N + cc) >> 1] = (uint32_t)l2 | ((uint32_t)l3 << 16);
            } else {
                float2 w0; w0.x = v0; w0.y = v1;
                float2 w1; w1.x = v2; w1.y = v3;
                *(float2*)(C + (size_t)r * N + cc)       = w0;
                *(float2*)(C + (size_t)(r + 8) * N + cc) = w1;
            }
        }
    }
}

#define SMEM_128 (2 * (2*128*80 + 2*128*80))   // 81920
#define SMEM_64  (2 * (2*64*80  + 2*128*80))   // 61440

// ============ fp16 single-pass GEMM: C[M,N] = A[M,K] * Bt[N,K]^T + bias ============
template<bool HASBIAS>
__global__ __launch_bounds__(256, 2)
void hgemm_kernel(const unsigned short* __restrict__ A, const unsigned short* __restrict__ B,
                  const float* __restrict__ bias, float* __restrict__ C,
                  int M, int N, int K) {
    constexpr int BM = 128, BN = 128;
    constexpr int NTN = 64;              // 4x2 warp grid
    constexpr int NF  = 8;
    constexpr int ROWB = 80;
    constexpr int ASZ = BM * ROWB;
    constexpr int BSZ = BN * ROWB;
    constexpr int STAGE = ASZ + BSZ;     // 20480

    char* sm = (char*)csm;
    const int tid = threadIdx.x;
    const int wid = tid >> 5, lane = tid & 31;
    const int wm = wid >> 1, wn = wid & 1;
    const int gr = lane >> 2, ck = lane & 3;
    const int m0 = blockIdx.y * BM;
    const int n0 = blockIdx.x * BN;

    float acc[2][NF][4];
    #pragma unroll
    for (int mt = 0; mt < 2; mt++)
        #pragma unroll
        for (int nf = 0; nf < NF; nf++)
            #pragma unroll
            for (int j = 0; j < 4; j++) acc[mt][nf][j] = 0.f;

    const uint32_t smb = smem_u32(sm);

    uint32_t aoff[2], boff[NF / 2];
    #pragma unroll
    for (int mt = 0; mt < 2; mt++)
        aoff[mt] = (uint32_t)(wm * 32 + mt * 16 + (lane & 15)) * ROWB + (lane & 16);
    #pragma unroll
    for (int p = 0; p < NF / 2; p++)
        boff[p] = (uint32_t)(wn * NTN + p * 16 + (lane & 7) + ((lane & 16) >> 1)) * ROWB
                  + ((lane & 8) << 1);

    auto load_stage = [&](int s, int k0) {
        const uint32_t sb = smb + s * STAGE;
        #pragma unroll
        for (int p = 0; p < 2; p++) {
            int id = tid + p * 256;
            int row = id >> 2, cc = id & 3;
            uint32_t so = row * ROWB + cc * 16;
            cpa16(sb + so,       A + (size_t)(m0 + row) * K + k0 + cc * 8);
            cpa16(sb + ASZ + so, B + (size_t)(n0 + row) * K + k0 + cc * 8);
        }
    };

    auto compute = [&](int s) {
        const uint32_t base = smb + s * STAGE;
        #pragma unroll
        for (int ks = 0; ks < 2; ks++) {
            const uint32_t kb = ks * 32;
            uint32_t ah[2][4], bh[NF][2];
            #pragma unroll
            for (int mt = 0; mt < 2; mt++)
                LDSM4(ah[mt][0], ah[mt][1], ah[mt][2], ah[mt][3], base + aoff[mt] + kb);
            #pragma unroll
            for (int p = 0; p < NF / 2; p++)
                LDSM4(bh[2*p][0], bh[2*p][1], bh[2*p+1][0], bh[2*p+1][1],
                      base + ASZ + boff[p] + kb);
            #pragma unroll
            for (int mt = 0; mt < 2; mt++)
                #pragma unroll
                for (int nf = 0; nf < NF; nf++)
                    MMAF16(acc[mt][nf], ah[mt], bh[nf]);
        }
    };

    load_stage(0, 0);
    CP_COMMIT();
    const int chunks = K >> 5;
    for (int c = 0; c < chunks; c++) {
        if (c + 1 < chunks) {
            load_stage((c + 1) & 1, (c + 1) << 5);
            CP_COMMIT();
            CP_WAIT1();
        } else {
            CP_WAIT0();
        }
        __syncthreads();
        compute(c & 1);
        __syncthreads();
    }

    #pragma unroll
    for (int mt = 0; mt < 2; mt++) {
        const int r = m0 + wm * 32 + mt * 16 + gr;
        #pragma unroll
        for (int nf = 0; nf < NF; nf++) {
            const int cc = n0 + wn * NTN + nf * 8 + ck * 2;
            float v0 = acc[mt][nf][0], v1 = acc[mt][nf][1];
            float v2 = acc[mt][nf][2], v3 = acc[mt][nf][3];
            if (HASBIAS) {
                float b0 = bias[cc], b1 = bias[cc + 1];
                v0 += b0; v1 += b1; v2 += b0; v3 += b1;
            }
            float2 w0; w0.x = v0; w0.y = v1;
            float2 w1; w1.x = v2; w1.y = v3;
            *(float2*)(C + (size_t)r * N + cc)       = w0;
            *(float2*)(C + (size_t)(r + 8) * N + cc) = w1;
        }
    }
}
#define SMEM_H (2 * (128*80 + 128*80))   // 40960

// ================= converters =================
__global__ void cvt16_kernel(const float* __restrict__ in, unsigned short* __restrict__ out, int n4) {
    int i = blockIdx.x * 256 + threadIdx.x;
    if (i >= n4) return;
    float4 v = ((const float4*)in)[i];
    __half2 a = __floats2half2_rn(v.x, v.y);
    __half2 b = __floats2half2_rn(v.z, v.w);
    uint2 o;
    o.x = *(uint32_t*)&a; o.y = *(uint32_t*)&b;
    *(uint2*)(out + 4*(size_t)i) = o;
}

// transpose + fp16: src W[K,N] -> dst[N,K] fp16, batched over layers
__global__ void tcvt_kernel(const float* __restrict__ W, unsigned short* __restrict__ out,
                            int K, int N, size_t sstride, size_t dstride) {
    __shared__ float t[64][33];
    const int z = blockIdx.z;
    W   += (size_t)z * sstride;
    out += (size_t)z * dstride;
    const int nb = blockIdx.x * 32, kb = blockIdx.y * 64;
    const int tx = threadIdx.x, ty = threadIdx.y;
    for (int r = ty; r < 64; r += 8)
        t[r][tx] = W[(size_t)(kb + r) * N + nb + tx];
    __syncthreads();
    for (int n = ty; n < 32; n += 8) {
        __half2 hv = __floats2half2_rn(t[2*tx][n], t[2*tx + 1][n]);
        ((uint32_t*)out)[(((size_t)(nb + n) * K + kb) >> 1) + tx] = *(uint32_t*)&hv;
    }
}

// ===== transpose+split bf16, batched over layers =====
__global__ void tsplit_kernel(const float* __restrict__ W, unsigned short* __restrict__ hi,
                              unsigned short* __restrict__ lo, int K, int N,
                              size_t sstride, size_t dstride) {
    __shared__ float t[64][33];
    const int z = blockIdx.z;
    W  += (size_t)z * sstride;
    hi += (size_t)z * dstride;
    lo += (size_t)z * dstride;
    const int nb = blockIdx.x * 32, kb = blockIdx.y * 64;
    const int tx = threadIdx.x, ty = threadIdx.y;
    for (int r = ty; r < 64; r += 8)
        t[r][tx] = W[(size_t)(kb + r) * N + nb + tx];
    __syncthreads();
    for (int n = ty; n < 32; n += 8) {
        float x0 = t[2*tx][n], x1 = t[2*tx + 1][n];
        unsigned short h0,l0,h1,l1;
        bsplit(x0,h0,l0); bsplit(x1,h1,l1);
        size_t o = (((size_t)(nb + n) * K + kb) >> 1) + tx;
        ((uint32_t*)hi)[o] = (uint32_t)h0 | ((uint32_t)h1 << 16);
        ((uint32_t*)lo)[o] = (uint32_t)l0 | ((uint32_t)l1 << 16);
    }
}

__global__ void biascat3_kernel(const float* a, const float* b, const float* c, float* out) {
    int i = blockIdx.x * 256 + threadIdx.x;
    if (i >= NLc * 3 * Dm) return;
    int l = i / (3 * Dm), r = i % (3 * Dm);
    int w = r / Dm, j = r % Dm;
    const float* s = (w == 0) ? a : (w == 1) ? b : c;
    out[i] = s[l * Dm + j];
}
__global__ void biascat2_kernel(const float* a, const float* b, float* out) {
    int i = blockIdx.x * 256 + threadIdx.x;
    if (i >= NLc * 2 * Dm) return;
    int l = i / (2 * Dm), r = i % (2 * Dm);
    int w = r / Dm, j = r % Dm;
    const float* s = (w == 0) ? a : b;
    out[i] = s[l * Dm + j];
}

// ---------------- sort / gather / embed ----------------
__global__ void sort_kernel(const int* __restrict__ lens, int* __restrict__ order) {
    __shared__ int l[Bz];
    int b = threadIdx.x;
    l[b] = lens[b];
    __syncthreads();
    int myl = l[b], rank = 0;
    #pragma unroll
    for (int j = 0; j < Bz; j++)
        rank += (l[j] > myl) || (l[j] == myl && j < b);
    order[rank] = b;
}

__global__ void gather_caps_kernel(const int* __restrict__ caps, const int* __restrict__ order,
                                   int* __restrict__ out) {
    int idx = blockIdx.x * 256 + threadIdx.x;
    if (idx >= MROW) return;
    int b = idx / LQ, t = idx % LQ;
    out[idx] = caps[order[b] * LQ + t];
}

__global__ void embed_kernel(const int* __restrict__ caps, const float* __restrict__ tgt,
                             const float* __restrict__ pos, float* __restrict__ x,
                             unsigned short* __restrict__ hi, unsigned short* __restrict__ lo) {
    int idx = blockIdx.x * 256 + threadIdx.x;
    if (idx >= MROW * Dm) return;
    int d = idx & (Dm - 1);
    int rt = idx >> 9;
    int t = rt % LQ;
    int cap = caps[rt];
    float v = tgt[(size_t)cap * Dm + d] + pos[t * Dm + d];
    x[idx] = v;
    unsigned short h, l;
    bsplit(v, h, l);
    hi[idx] = h; lo[idx] = l;
}

// ---------------- self attention ----------------
__global__ __launch_bounds__(256)
void self_attn_kernel(const float* __restrict__ qkv, const int* __restrict__ caps,
                      unsigned short* __restrict__ chi, unsigned short* __restrict__ clo) {
    __shared__ float Ks[64][65];
    __shared__ float Vs[64][64];
    __shared__ float ps[8][LQ];
    __shared__ int pad[64];
    const int b = blockIdx.x >> 3;
    const int h = blockIdx.x & 7;
    const int tid = threadIdx.x;
    const int lane = tid & 31, w = tid >> 5;

    for (int i = tid; i < 64 * 64; i += 256) {
        int t = i >> 6, d = i & 63;
        if (t < LQ) {
            size_t src = (size_t)(b * LQ + t) * (3 * Dm) + h * DKh + d;
            Ks[t][d] = qkv[src + Dm];
            Vs[t][d] = qkv[src + 2 * Dm];
        } else {
            Ks[t][d] = 0.f; Vs[t][d] = 0.f;
        }
    }
    if (tid < 64) pad[tid] = (tid < LQ) ? (caps[b * LQ + tid] == 0) : 1;
    __syncthreads();

    for (int q = w; q < LQ; q += 8) {
        const float* qp = qkv + (size_t)(b * LQ + q) * (3 * Dm) + h * DKh;
        float q0 = qp[lane], q1 = qp[lane + 32];
        float a0 = 0.f, a1 = 0.f;
        #pragma unroll
        for (int d = 0; d < 64; d++) {
            float qv = (d < 32) ? __shfl_sync(0xffffffffu, q0, d)
                                : __shfl_sync(0xffffffffu, q1, d - 32);
            a0 += qv * Ks[lane][d];
            a1 += qv * Ks[lane + 32][d];
        }
        const int k1 = lane + 32;
        float s0 = (lane > q || pad[lane]) ? -1e9f : a0 * 0.125f;
        float s1 = (k1 >= LQ) ? -1e30f : ((k1 > q || pad[k1]) ? -1e9f : a1 * 0.125f);
        float m = fmaxf(s0, s1);
        #pragma unroll
        for (int o = 16; o > 0; o >>= 1) m = fmaxf(m, __shfl_xor_sync(0xffffffffu, m, o));
        float e0 = __expf(s0 - m);
        float e1 = __expf(s1 - m);
        float sum = e0 + e1;
        #pragma unroll
        for (int o = 16; o > 0; o >>= 1) sum += __shfl_xor_sync(0xffffffffu, sum, o);
        float inv = 1.f / sum;
        ps[w][lane] = e0;
        if (k1 < LQ) ps[w][k1] = e1;
        __syncwarp();
        float c0 = 0.f, c1 = 0.f;
        #pragma unroll 4
        for (int k = 0; k < LQ; k++) {
            float p = ps[w][k];
            c0 += p * Vs[k][lane];
            c1 += p * Vs[k][lane + 32];
        }
        size_t base = (size_t)(b * LQ + q) * Dm + h * DKh;
        unsigned short hh, ll;
        bsplit(c0 * inv, hh, ll);
        chi[base + lane] = hh; clo[base + lane] = ll;
        bsplit(c1 * inv, hh, ll);
        chi[base + lane + 32] = hh; clo[base + lane + 32] = ll;
        __syncwarp();
    }
}

// ---------------- cross attention ----------------
#define KS_STR 68
__global__ __launch_bounds__(256)
void cross_attn_kernel(const float* __restrict__ Q, const float* __restrict__ KV,
                       const int* __restrict__ order,
                       unsigned short* __restrict__ chi, unsigned short* __restrict__ clo) {
    float* Ks = csm;
    float* Vs = Ks + NPIXc * KS_STR;
    float* ps = Vs + NPIXc * DKh;
    const int b = blockIdx.x >> 3;
    const int h = blockIdx.x & 7;
    const int tid = threadIdx.x;
    const int lane = tid & 31, w = tid >> 5;
    const int ob = order[b];

    for (int i = tid; i < NPIXc * DKh; i += 256) {
        int t = i >> 6, d = i & 63;
        size_t src = (size_t)(ob * NPIXc + t) * (2 * Dm) + h * DKh + d;
        Ks[t * KS_STR + d] = KV[src];
        Vs[t * DKh + d]    = KV[src + Dm];
    }
    __syncthreads();

    for (int qi = w; qi < LQ / 2; qi += 8) {
        const int q0 = 2 * qi;
        const float* qp = Q + (size_t)(b * LQ + q0) * Dm + h * DKh;
        float qa0 = qp[lane], qb0 = qp[lane + 32];
        float qa1 = qp[Dm + lane], qb1 = qp[Dm + lane + 32];

        float s0[7], s1[7];
        #pragma unroll
        for (int kk = 0; kk < 7; kk++) { s0[kk] = 0.f; s1[kk] = 0.f; }

        #pragma unroll
        for (int d4 = 0; d4 < 16; d4++) {
            float qv0[4], qv1[4];
            #pragma unroll
            for (int j = 0; j < 4; j++) {
                int d = 4 * d4 + j;
                qv0[j] = (d < 32) ? __shfl_sync(0xffffffffu, qa0, d)
                                  : __shfl_sync(0xffffffffu, qb0, d - 32);
                qv1[j] = (d < 32) ? __shfl_sync(0xffffffffu, qa1, d)
                                  : __shfl_sync(0xffffffffu, qb1, d - 32);
            }
            #pragma unroll
            for (int kk = 0; kk < 7; kk++) {
                const int key = kk * 32 + lane;
                float4 kv4 = *(const float4*)(Ks + key * KS_STR + 4 * d4);
                s0[kk] += qv0[0]*kv4.x + qv0[1]*kv4.y + qv0[2]*kv4.z + qv0[3]*kv4.w;
                s1[kk] += qv1[0]*kv4.x + qv1[1]*kv4.y + qv1[2]*kv4.z + qv1[3]*kv4.w;
            }
        }
        float m0 = -1e30f, m1 = -1e30f;
        #pragma unroll
        for (int kk = 0; kk < 7; kk++) {
            const int key = kk * 32 + lane;
            s0[kk] = (key < NPIXc) ? s0[kk] * 0.125f : -1e30f;
            s1[kk] = (key < NPIXc) ? s1[kk] * 0.125f : -1e30f;
            m0 = fmaxf(m0, s0[kk]); m1 = fmaxf(m1, s1[kk]);
        }
        #pragma unroll
        for (int o = 16; o > 0; o >>= 1) {
            m0 = fmaxf(m0, __shfl_xor_sync(0xffffffffu, m0, o));
            m1 = fmaxf(m1, __shfl_xor_sync(0xffffffffu, m1, o));
        }
        float sum0 = 0.f, sum1 = 0.f;
        #pragma unroll
        for (int kk = 0; kk < 7; kk++) {
            const int key = kk * 32 + lane;
            float e0 = __expf(s0[kk] - m0);
            float e1 = __expf(s1[kk] - m1);
            sum0 += e0; sum1 += e1;
            if (key < NPIXc) {
                ps[(2 * w) * NPIXc + key]     = e0;
                ps[(2 * w + 1) * NPIXc + key] = e1;
            }
        }
        #pragma unroll
        for (int o = 16; o > 0; o >>= 1) {
            sum0 += __shfl_xor_sync(0xffffffffu, sum0, o);
            sum1 += __shfl_xor_sync(0xffffffffu, sum1, o);
        }
        float inv0 = 1.f / sum0, inv1 = 1.f / sum1;
        __syncwarp();

        float c00 = 0.f, c01 = 0.f, c10 = 0.f, c11 = 0.f;
        const float* p0p = ps + (2 * w) * NPIXc;
        const float* p1p = ps + (2 * w + 1) * NPIXc;
        #pragma unroll 4
        for (int k = 0; k < NPIXc; k++) {
            float2 vv = *(const float2*)(Vs + k * DKh + 2 * lane);
            float p0 = p0p[k], p1 = p1p[k];
            c00 += p0 * vv.x; c01 += p0 * vv.y;
            c10 += p1 * vv.x; c11 += p1 * vv.y;
        }
        size_t base = (size_t)(b * LQ + q0) * Dm + h * DKh + 2 * lane;
        unsigned short h0,l0,h1,l1;
        bsplit(c00 * inv0, h0, l0); bsplit(c01 * inv0, h1, l1);
        ((uint32_t*)chi)[base >> 1] = (uint32_t)h0 | ((uint32_t)h1 << 16);
        ((uint32_t*)clo)[base >> 1] = (uint32_t)l0 | ((uint32_t)l1 << 16);
        bsplit(c10 * inv1, h0, l0); bsplit(c11 * inv1, h1, l1);
        ((uint32_t*)chi)[(base + Dm) >> 1] = (uint32_t)h0 | ((uint32_t)h1 << 16);
        ((uint32_t*)clo)[(base + Dm) >> 1] = (uint32_t)l0 | ((uint32_t)l1 << 16);
        __syncwarp();
    }
}
#define CROSS_SMEM ((NPIXc*KS_STR + NPIXc*DKh + 16*NPIXc) * (int)sizeof(float))

// ---------------- LayerNorm(residual + bias) ----------------
__global__ __launch_bounds__(256)
void ln_residual_kernel(const float* __restrict__ y, const float* __restrict__ bias,
                        const float* __restrict__ xin, float* __restrict__ xout,
                        unsigned short* __restrict__ hi, unsigned short* __restrict__ lo) {
    int r = blockIdx.x, tid = threadIdx.x;
    __shared__ float red[256];
    size_t base = (size_t)r * Dm;
    float v0 = y[base + tid]       + bias[tid]       + xin[base + tid];
    float v1 = y[base + 256 + tid] + bias[256 + tid] + xin[base + 256 + tid];
    red[tid] = v0 + v1; __syncthreads();
    #pragma unroll
    for (int st = 128; st > 0; st >>= 1) {
        if (tid < st) red[tid] += red[tid + st];
        __syncthreads();
    }
    float m = red[0] * (1.f / Dm);
    __syncthreads();
    float d0 = v0 - m, d1 = v1 - m;
    red[tid] = d0 * d0 + d1 * d1; __syncthreads();
    #pragma unroll
    for (int st = 128; st > 0; st >>= 1) {
        if (tid < st) red[tid] += red[tid + st];
        __syncthreads();
    }
    float inv = rsqrtf(red[0] * (1.f / Dm) + 1e-5f);
    float o0 = d0 * inv, o1 = d1 * inv;
    xout[base + tid]       = o0;
    xout[base + 256 + tid] = o1;
    unsigned short h, l;
    bsplit(o0, h, l); hi[base + tid] = h;       lo[base + tid] = l;
    bsplit(o1, h, l); hi[base + 256 + tid] = h; lo[base + 256 + tid] = l;
}

// ---------------- host side ----------------
extern "C" void kernel_launch(void* const* d_in, const int* in_sizes, int n_in,
                              void* d_out, int out_size) {
    const float* encoder_out = (const float*)d_in[0];
    const int*   captions    = (const int*)d_in[1];
    const int*   lengths     = (const int*)d_in[2];
    const float* tgt_emb     = (const float*)d_in[3];
    const float* pos_emb     = (const float*)d_in[4];
    const float* sWq = (const float*)d_in[5];  const float* sbq = (const float*)d_in[6];
    const float* sWk = (const float*)d_in[7];  const float* sbk = (const float*)d_in[8];
    const float* sWv = (const float*)d_in[9];  const float* sbv = (const float*)d_in[10];
    const float* sWo = (const float*)d_in[11]; const float* sbo = (const float*)d_in[12];
    const float* eWq = (const float*)d_in[13]; const float* ebq = (const float*)d_in[14];
    const float* eWk = (const float*)d_in[15]; const float* ebk = (const float*)d_in[16];
    const float* eWv = (const float*)d_in[17]; const float* ebv = (const float*)d_in[18];
    const float* eWo = (const float*)d_in[19]; const float* ebo = (const float*)d_in[20];
    const float* fW1 = (const float*)d_in[21]; const float* fb1 = (const float*)d_in[22];
    const float* fW2 = (const float*)d_in[23]; const float* fb2 = (const float*)d_in[24];
    const float* pW  = (const float*)d_in[25];
    float* out = (float*)d_out;

    float *x, *y, *q, *qkv, *kv, *bqkv, *bkv;
    int *order, *caps;
    unsigned short *ahi, *alo, *chi, *clo, *hhi, *hlo;
    unsigned short *efp, *wekvf, *wpjf, *xf;
    unsigned short *wsqkv_h, *wsqkv_l, *wso_h, *wso_l, *weq_h, *weq_l;
    unsigned short *weo_h, *weo_l, *wf1_h, *wf1_l, *wf2_h, *wf2_l;
    cudaGetSymbolAddress((void**)&x, g_x);       cudaGetSymbolAddress((void**)&y, g_y);
    cudaGetSymbolAddress((void**)&q, g_q);       cudaGetSymbolAddress((void**)&qkv, g_qkv);
    cudaGetSymbolAddress((void**)&kv, g_kv);
    cudaGetSymbolAddress((void**)&order, g_order); cudaGetSymbolAddress((void**)&caps, g_caps);
    cudaGetSymbolAddress((void**)&ahi, g_ahi);   cudaGetSymbolAddress((void**)&alo, g_alo);
    cudaGetSymbolAddress((void**)&chi, g_chi);   cudaGetSymbolAddress((void**)&clo, g_clo);
    cudaGetSymbolAddress((void**)&hhi, g_hhi);   cudaGetSymbolAddress((void**)&hlo, g_hlo);
    cudaGetSymbolAddress((void**)&efp, g_efp);   cudaGetSymbolAddress((void**)&wekvf, g_wekvf);
    cudaGetSymbolAddress((void**)&wpjf, g_wpjf); cudaGetSymbolAddress((void**)&xf, g_xf);
    cudaGetSymbolAddress((void**)&wsqkv_h, g_wsqkv_h); cudaGetSymbolAddress((void**)&wsqkv_l, g_wsqkv_l);
    cudaGetSymbolAddress((void**)&wso_h, g_wso_h);     cudaGetSymbolAddress((void**)&wso_l, g_wso_l);
    cudaGetSymbolAddress((void**)&weq_h, g_weq_h);     cudaGetSymbolAddress((void**)&weq_l, g_weq_l);
    cudaGetSymbolAddress((void**)&weo_h, g_weo_h);     cudaGetSymbolAddress((void**)&weo_l, g_weo_l);
    cudaGetSymbolAddress((void**)&wf1_h, g_wf1_h);     cudaGetSymbolAddress((void**)&wf1_l, g_wf1_l);
    cudaGetSymbolAddress((void**)&wf2_h, g_wf2_h);     cudaGetSymbolAddress((void**)&wf2_l, g_wf2_l);
    cudaGetSymbolAddress((void**)&bqkv, g_bqkv);       cudaGetSymbolAddress((void**)&bkv, g_bkv);

    cudaFuncSetAttribute(cross_attn_kernel, cudaFuncAttributeMaxDynamicSharedMemorySize, CROSS_SMEM);
    cudaFuncSetAttribute(mgemm_kernel<128, false, true,  false>, cudaFuncAttributeMaxDynamicSharedMemorySize, SMEM_128);
    cudaFuncSetAttribute(mgemm_kernel<128, true,  true,  true>,  cudaFuncAttributeMaxDynamicSharedMemorySize, SMEM_128);
    cudaFuncSetAttribute(mgemm_kernel<64,  false, true,  false>, cudaFuncAttributeMaxDynamicSharedMemorySize, SMEM_64);
    cudaFuncSetAttribute(mgemm_kernel<64,  false, false, false>, cudaFuncAttributeMaxDynamicSharedMemorySize, SMEM_64);
    cudaFuncSetAttribute(hgemm_kernel<true>,  cudaFuncAttributeMaxDynamicSharedMemorySize, SMEM_H);
    cudaFuncSetAttribute(hgemm_kernel<false>, cudaFuncAttributeMaxDynamicSharedMemorySize, SMEM_H);

    // ---- weight prep ----
    const size_t DD = (size_t)Dm * Dm, ED = (size_t)ENCc * Dm;
    const dim3 tsb(32, 8);
    const dim3 gdd(Dm/32, Dm/64, NLc);
    tsplit_kernel<<<gdd, tsb>>>(sWq, wsqkv_h,        wsqkv_l,        Dm, Dm, DD, 3*DD);
    tsplit_kernel<<<gdd, tsb>>>(sWk, wsqkv_h + DD,   wsqkv_l + DD,   Dm, Dm, DD, 3*DD);
    tsplit_kernel<<<gdd, tsb>>>(sWv, wsqkv_h + 2*DD, wsqkv_l + 2*DD, Dm, Dm, DD, 3*DD);
    tsplit_kernel<<<gdd, tsb>>>(sWo, wso_h, wso_l, Dm, Dm, DD, DD);
    tsplit_kernel<<<gdd, tsb>>>(eWq, weq_h, weq_l, Dm, Dm, DD, DD);
    tsplit_kernel<<<gdd, tsb>>>(eWo, weo_h, weo_l, Dm, Dm, DD, DD);
    const dim3 gek(Dm/32, ENCc/64, NLc);
    tcvt_kernel<<<gek, tsb>>>(eWk, wekvf,      ENCc, Dm, ED, 2*ED);
    tcvt_kernel<<<gek, tsb>>>(eWv, wekvf + ED, ENCc, Dm, ED, 2*ED);
    tsplit_kernel<<<dim3(FFc/32, Dm/64, NLc), tsb>>>(fW1, wf1_h, wf1_l, Dm, FFc, ED, ED);
    tsplit_kernel<<<dim3(Dm/32, FFc/64, NLc), tsb>>>(fW2, wf2_h, wf2_l, FFc, Dm, ED, ED);
    cvt16_kernel<<<((VOC*Dm/4) + 255)/256, 256>>>(pW, wpjf, VOC*Dm/4);
    biascat3_kernel<<<(NLc*3*Dm + 255)/256, 256>>>(sbq, sbk, sbv, bqkv);
    biascat2_kernel<<<(NLc*2*Dm + 255)/256, 256>>>(ebk, ebv, bkv);

    // ---- prologue ----
    sort_kernel<<<1, Bz>>>(lengths, order);
    gather_caps_kernel<<<(MROW + 255) / 256, 256>>>(captions, order, caps);
    embed_kernel<<<(MROW * Dm + 255) / 256, 256>>>(caps, tgt_emb, pos_emb, x, ahi, alo);
    cvt16_kernel<<<(((size_t)EROW*ENCc/4) + 255)/256, 256>>>(encoder_out, efp, EROW*ENCc/4);

    const dim3 gQKV(12, 26);
    const dim3 gD64(4, 52);
    const dim3 gKV(8, 98);
    const dim3 gFF1(16, 26);
    const dim3 gPRJ(250, 26);

    for (int l = 0; l < NLc; l++) {
        // ---- self attention ----
        mgemm_kernel<128, false, true, false><<<gQKV, 256, SMEM_128>>>(ahi, alo,
            wsqkv_h + l*3*DD, wsqkv_l + l*3*DD, bqkv + l*3*Dm, qkv, nullptr, nullptr, MROW, 3*Dm, Dm);
        self_attn_kernel<<<Bz * NH, 256>>>(qkv, caps, chi, clo);
        mgemm_kernel<64, false, false, false><<<gD64, 256, SMEM_64>>>(chi, clo,
            wso_h + l*DD, wso_l + l*DD, nullptr, y, nullptr, nullptr, MROW, Dm, Dm);
        ln_residual_kernel<<<MROW, 256>>>(y, sbo + l*Dm, x, x, ahi, alo);

        // ---- cross attention ----
        mgemm_kernel<64, false, true, false><<<gD64, 256, SMEM_64>>>(ahi, alo,
            weq_h + l*DD, weq_l + l*DD, ebq + l*Dm, q, nullptr, nullptr, MROW, Dm, Dm);
        hgemm_kernel<true><<<gKV, 256, SMEM_H>>>(efp,
            wekvf + l*2*ED, bkv + l*2*Dm, kv, EROW, 2*Dm, ENCc);
        cross_attn_kernel<<<Bz * NH, 256, CROSS_SMEM>>>(q, kv, order, chi, clo);
        mgemm_kernel<64, false, false, false><<<gD64, 256, SMEM_64>>>(chi, clo,
            weo_h + l*DD, weo_l + l*DD, nullptr, y, nullptr, nullptr, MROW, Dm, Dm);
        ln_residual_kernel<<<MROW, 256>>>(y, ebo + l*Dm, x, x, ahi, alo);

        // ---- FFN ----
        mgemm_kernel<128, true, true, true><<<gFF1, 256, SMEM_128>>>(ahi, alo,
            wf1_h + l*ED, wf1_l + l*ED, fb1 + l*FFc, nullptr, hhi, hlo, MROW, FFc, Dm);
        mgemm_kernel<64, false, false, false><<<gD64, 256, SMEM_64>>>(hhi, hlo,
            wf2_h + l*ED, wf2_l + l*ED, nullptr, y, nullptr, nullptr, MROW, Dm, FFc);
        ln_residual_kernel<<<MROW, 256>>>(y, fb2 + l*Dm, x, x, ahi, alo);
    }

    // ---- vocab projection (fp16 single-pass) ----
    cvt16_kernel<<<((MROW*Dm/4) + 255)/256, 256>>>(x, xf, MROW*Dm/4);
    hgemm_kernel<false><<<gPRJ, 256, SMEM_H>>>(xf, wpjf, nullptr, out, MROW, VOC, Dm);
}

// round 11
// speedup vs baseline: 9.8061x; 1.2425x over previous
#include <cuda_runtime.h>
#include <cuda_fp16.h>
#include <math.h>
#include <stdint.h>

// ---------------- problem constants ----------------
#define Bz    64
#define LQ    52
#define Dm    512
#define NH    8
#define DKh   64
#define NPIXc 196
#define ENCc  2048
#define FFc   2048
#define NLc   6
#define MROW  (Bz*LQ)       // 3328
#define EROW  (Bz*NPIXc)    // 12544
#define VOC   32000

// ---------------- fp32 scratch ----------------
__device__ float g_x[MROW*Dm];
__device__ float g_y[MROW*Dm];
__device__ float g_q[MROW*Dm];
__device__ float g_qkv[MROW*3*Dm];
__device__ float g_kv[EROW*2*Dm];
__device__ int   g_order[Bz];
__device__ int   g_caps[MROW];

// ---------------- fp16 scratch: activations ----------------
__device__ unsigned short g_xf[MROW*Dm];       // x fp16
__device__ unsigned short g_cf[MROW*Dm];       // attention ctx fp16
__device__ unsigned short g_hf[MROW*FFc];      // FF1 output fp16
__device__ unsigned short g_efp[EROW*ENCc];    // encoder fp16

// ---------------- fp16 scratch: transposed weights [N,K] ----------------
__device__ unsigned short g_wsqkvf[NLc*3*Dm*Dm];
__device__ unsigned short g_wsof[NLc*Dm*Dm];
__device__ unsigned short g_weqf[NLc*Dm*Dm];
__device__ unsigned short g_wekvf[NLc*2*Dm*ENCc];
__device__ unsigned short g_weof[NLc*Dm*Dm];
__device__ unsigned short g_wf1f[NLc*FFc*Dm];
__device__ unsigned short g_wf2f[NLc*Dm*FFc];
__device__ unsigned short g_wpjf[VOC*Dm];
__device__ float g_bqkv[NLc*3*Dm];
__device__ float g_bkv[NLc*2*Dm];

extern __shared__ float csm[];

// ---------------- helpers ----------------
__device__ __forceinline__ uint32_t smem_u32(const void* p) {
    uint32_t a;
    asm("{ .reg .u64 t; cvta.to.shared.u64 t, %1; cvt.u32.u64 %0, t; }" : "=r"(a) : "l"(p));
    return a;
}
__device__ __forceinline__ void cpa16(uint32_t s, const void* g) {
    asm volatile("cp.async.cg.shared.global [%0], [%1], 16;" :: "r"(s), "l"(g));
}
#define CP_COMMIT() asm volatile("cp.async.commit_group;" ::: "memory")
#define CP_WAIT0()  asm volatile("cp.async.wait_group 0;" ::: "memory")
#define CP_WAIT1()  asm volatile("cp.async.wait_group 1;" ::: "memory")

#define MMAF16(c, a, b) \
    asm volatile("mma.sync.aligned.m16n8k16.row.col.f32.f16.f16.f32 " \
        "{%0,%1,%2,%3}, {%4,%5,%6,%7}, {%8,%9}, {%0,%1,%2,%3};" \
        : "+f"((c)[0]), "+f"((c)[1]), "+f"((c)[2]), "+f"((c)[3]) \
        : "r"((a)[0]), "r"((a)[1]), "r"((a)[2]), "r"((a)[3]), \
          "r"((b)[0]), "r"((b)[1]))

#define LDSM4(r0, r1, r2, r3, addr) \
    asm volatile("ldmatrix.sync.aligned.m8n8.x4.shared.b16 {%0,%1,%2,%3}, [%4];" \
        : "=r"(r0), "=r"(r1), "=r"(r2), "=r"(r3) : "r"(addr))

__device__ __forceinline__ uint32_t packh2(float a, float b) {
    __half2 h = __floats2half2_rn(a, b);
    return *(uint32_t*)&h;
}

// ============ fp16 GEMM: C[M,N] = A[M,K] * Bt[N,K]^T + bias ============
// ldmatrix.x4 fragment loads; 80B smem row stride; cp.async double buffer.
template<int BMt, bool RELU, bool HASBIAS, bool HOUT>
__global__ __launch_bounds__(256, 2)
void hgemm_kernel(const unsigned short* __restrict__ A, const unsigned short* __restrict__ B,
                  const float* __restrict__ bias, float* __restrict__ C,
                  unsigned short* __restrict__ Ch,
                  int M, int N, int K) {
    constexpr int BN = 128;
    constexpr int NWM = BMt / 32;
    constexpr int NWN = 8 / NWM;
    constexpr int NTN = BN / NWN;
    constexpr int NF  = NTN / 8;
    constexpr int ROWB = 80;
    constexpr int ASZ = BMt * ROWB;
    constexpr int BSZ = BN * ROWB;
    constexpr int STAGE = ASZ + BSZ;

    char* sm = (char*)csm;
    const int tid = threadIdx.x;
    const int wid = tid >> 5, lane = tid & 31;
    const int wm = wid / NWN, wn = wid % NWN;
    const int gr = lane >> 2, ck = lane & 3;
    const int m0 = blockIdx.y * BMt;
    const int n0 = blockIdx.x * BN;

    float acc[2][NF][4];
    #pragma unroll
    for (int mt = 0; mt < 2; mt++)
        #pragma unroll
        for (int nf = 0; nf < NF; nf++)
            #pragma unroll
            for (int j = 0; j < 4; j++) acc[mt][nf][j] = 0.f;

    const uint32_t smb = smem_u32(sm);

    uint32_t aoff[2], boff[NF / 2];
    #pragma unroll
    for (int mt = 0; mt < 2; mt++)
        aoff[mt] = (uint32_t)(wm * 32 + mt * 16 + (lane & 15)) * ROWB + (lane & 16);
    #pragma unroll
    for (int p = 0; p < NF / 2; p++)
        boff[p] = (uint32_t)(wn * NTN + p * 16 + (lane & 7) + ((lane & 16) >> 1)) * ROWB
                  + ((lane & 8) << 1);

    auto load_stage = [&](int s, int k0) {
        const uint32_t sb = smb + s * STAGE;
        #pragma unroll
        for (int p = 0; p < BMt * 4 / 1024 + 1; p++) {      // BMt=128 -> p<1? ensure exact below
        }
        #pragma unroll
        for (int p = 0; p < (BMt * 4) / 256; p++) {
            int id = tid + p * 256;
            int row = id >> 2, cc = id & 3;
            uint32_t so = row * ROWB + cc * 16;
            cpa16(sb + so, A + (size_t)(m0 + row) * K + k0 + cc * 8);
        }
        #pragma unroll
        for (int p = 0; p < 2; p++) {
            int id = tid + p * 256;
            int row = id >> 2, cc = id & 3;
            uint32_t so = row * ROWB + cc * 16;
            cpa16(sb + ASZ + so, B + (size_t)(n0 + row) * K + k0 + cc * 8);
        }
    };

    auto compute = [&](int s) {
        const uint32_t base = smb + s * STAGE;
        #pragma unroll
        for (int ks = 0; ks < 2; ks++) {
            const uint32_t kb = ks * 32;
            uint32_t ah[2][4], bh[NF][2];
            #pragma unroll
            for (int mt = 0; mt < 2; mt++)
                LDSM4(ah[mt][0], ah[mt][1], ah[mt][2], ah[mt][3], base + aoff[mt] + kb);
            #pragma unroll
            for (int p = 0; p < NF / 2; p++)
                LDSM4(bh[2*p][0], bh[2*p][1], bh[2*p+1][0], bh[2*p+1][1],
                      base + ASZ + boff[p] + kb);
            #pragma unroll
            for (int mt = 0; mt < 2; mt++)
                #pragma unroll
                for (int nf = 0; nf < NF; nf++)
                    MMAF16(acc[mt][nf], ah[mt], bh[nf]);
        }
    };

    load_stage(0, 0);
    CP_COMMIT();
    const int chunks = K >> 5;
    for (int c = 0; c < chunks; c++) {
        if (c + 1 < chunks) {
            load_stage((c + 1) & 1, (c + 1) << 5);
            CP_COMMIT();
            CP_WAIT1();
        } else {
            CP_WAIT0();
        }
        __syncthreads();
        compute(c & 1);
        __syncthreads();
    }

    #pragma unroll
    for (int mt = 0; mt < 2; mt++) {
        const int r = m0 + wm * 32 + mt * 16 + gr;
        #pragma unroll
        for (int nf = 0; nf < NF; nf++) {
            const int cc = n0 + wn * NTN + nf * 8 + ck * 2;
            float v0 = acc[mt][nf][0], v1 = acc[mt][nf][1];
            float v2 = acc[mt][nf][2], v3 = acc[mt][nf][3];
            if (HASBIAS) {
                float b0 = bias[cc], b1 = bias[cc + 1];
                v0 += b0; v1 += b1; v2 += b0; v3 += b1;
            }
            if (RELU) {
                v0 = fmaxf(v0, 0.f); v1 = fmaxf(v1, 0.f);
                v2 = fmaxf(v2, 0.f); v3 = fmaxf(v3, 0.f);
            }
            if (HOUT) {
                ((uint32_t*)Ch)[((size_t)r * N + cc) >> 1]       = packh2(v0, v1);
                ((uint32_t*)Ch)[((size_t)(r + 8) * N + cc) >> 1] = packh2(v2, v3);
            } else {
                float2 w0; w0.x = v0; w0.y = v1;
                float2 w1; w1.x = v2; w1.y = v3;
                *(float2*)(C + (size_t)r * N + cc)       = w0;
                *(float2*)(C + (size_t)(r + 8) * N + cc) = w1;
            }
        }
    }
}
#define SMEM_H128 (2 * (128*80 + 128*80))   // 40960
#define SMEM_H64  (2 * (64*80  + 128*80))   // 30720

// ================= converters =================
__global__ void cvt16_kernel(const float* __restrict__ in, unsigned short* __restrict__ out, int n4) {
    int i = blockIdx.x * 256 + threadIdx.x;
    if (i >= n4) return;
    float4 v = ((const float4*)in)[i];
    uint2 o;
    o.x = packh2(v.x, v.y); o.y = packh2(v.z, v.w);
    *(uint2*)(out + 4*(size_t)i) = o;
}

// transpose + fp16: src W[K,N] -> dst[N,K] fp16, batched over layers
__global__ void tcvt_kernel(const float* __restrict__ W, unsigned short* __restrict__ out,
                            int K, int N, size_t sstride, size_t dstride) {
    __shared__ float t[64][33];
    const int z = blockIdx.z;
    W   += (size_t)z * sstride;
    out += (size_t)z * dstride;
    const int nb = blockIdx.x * 32, kb = blockIdx.y * 64;
    const int tx = threadIdx.x, ty = threadIdx.y;
    for (int r = ty; r < 64; r += 8)
        t[r][tx] = W[(size_t)(kb + r) * N + nb + tx];
    __syncthreads();
    for (int n = ty; n < 32; n += 8)
        ((uint32_t*)out)[(((size_t)(nb + n) * K + kb) >> 1) + tx] =
            packh2(t[2*tx][n], t[2*tx + 1][n]);
}

__global__ void biascat3_kernel(const float* a, const float* b, const float* c, float* out) {
    int i = blockIdx.x * 256 + threadIdx.x;
    if (i >= NLc * 3 * Dm) return;
    int l = i / (3 * Dm), r = i % (3 * Dm);
    int w = r / Dm, j = r % Dm;
    const float* s = (w == 0) ? a : (w == 1) ? b : c;
    out[i] = s[l * Dm + j];
}
__global__ void biascat2_kernel(const float* a, const float* b, float* out) {
    int i = blockIdx.x * 256 + threadIdx.x;
    if (i >= NLc * 2 * Dm) return;
    int l = i / (2 * Dm), r = i % (2 * Dm);
    int w = r / Dm, j = r % Dm;
    const float* s = (w == 0) ? a : b;
    out[i] = s[l * Dm + j];
}

// ---------------- sort / gather / embed ----------------
__global__ void sort_kernel(const int* __restrict__ lens, int* __restrict__ order) {
    __shared__ int l[Bz];
    int b = threadIdx.x;
    l[b] = lens[b];
    __syncthreads();
    int myl = l[b], rank = 0;
    #pragma unroll
    for (int j = 0; j < Bz; j++)
        rank += (l[j] > myl) || (l[j] == myl && j < b);
    order[rank] = b;
}

__global__ void gather_caps_kernel(const int* __restrict__ caps, const int* __restrict__ order,
                                   int* __restrict__ out) {
    int idx = blockIdx.x * 256 + threadIdx.x;
    if (idx >= MROW) return;
    int b = idx / LQ, t = idx % LQ;
    out[idx] = caps[order[b] * LQ + t];
}

__global__ void embed_kernel(const int* __restrict__ caps, const float* __restrict__ tgt,
                             const float* __restrict__ pos, float* __restrict__ x,
                             unsigned short* __restrict__ xf) {
    int idx = blockIdx.x * 256 + threadIdx.x;
    if (idx >= MROW * Dm) return;
    int d = idx & (Dm - 1);
    int rt = idx >> 9;
    int t = rt % LQ;
    int cap = caps[rt];
    float v = tgt[(size_t)cap * Dm + d] + pos[t * Dm + d];
    x[idx] = v;
    __half h = __float2half_rn(v);
    xf[idx] = *(unsigned short*)&h;
}

// ---------------- self attention (fp16 ctx out) ----------------
__global__ __launch_bounds__(256)
void self_attn_kernel(const float* __restrict__ qkv, const int* __restrict__ caps,
                      unsigned short* __restrict__ cf) {
    __shared__ float Ks[64][65];
    __shared__ float Vs[64][64];
    __shared__ float ps[8][LQ];
    __shared__ int pad[64];
    const int b = blockIdx.x >> 3;
    const int h = blockIdx.x & 7;
    const int tid = threadIdx.x;
    const int lane = tid & 31, w = tid >> 5;

    for (int i = tid; i < 64 * 64; i += 256) {
        int t = i >> 6, d = i & 63;
        if (t < LQ) {
            size_t src = (size_t)(b * LQ + t) * (3 * Dm) + h * DKh + d;
            Ks[t][d] = qkv[src + Dm];
            Vs[t][d] = qkv[src + 2 * Dm];
        } else {
            Ks[t][d] = 0.f; Vs[t][d] = 0.f;
        }
    }
    if (tid < 64) pad[tid] = (tid < LQ) ? (caps[b * LQ + tid] == 0) : 1;
    __syncthreads();

    for (int q = w; q < LQ; q += 8) {
        const float* qp = qkv + (size_t)(b * LQ + q) * (3 * Dm) + h * DKh;
        float q0 = qp[lane], q1 = qp[lane + 32];
        float a0 = 0.f, a1 = 0.f;
        #pragma unroll
        for (int d = 0; d < 64; d++) {
            float qv = (d < 32) ? __shfl_sync(0xffffffffu, q0, d)
                                : __shfl_sync(0xffffffffu, q1, d - 32);
            a0 += qv * Ks[lane][d];
            a1 += qv * Ks[lane + 32][d];
        }
        const int k1 = lane + 32;
        float s0 = (lane > q || pad[lane]) ? -1e9f : a0 * 0.125f;
        float s1 = (k1 >= LQ) ? -1e30f : ((k1 > q || pad[k1]) ? -1e9f : a1 * 0.125f);
        float m = fmaxf(s0, s1);
        #pragma unroll
        for (int o = 16; o > 0; o >>= 1) m = fmaxf(m, __shfl_xor_sync(0xffffffffu, m, o));
        float e0 = __expf(s0 - m);
        float e1 = __expf(s1 - m);
        float sum = e0 + e1;
        #pragma unroll
        for (int o = 16; o > 0; o >>= 1) sum += __shfl_xor_sync(0xffffffffu, sum, o);
        float inv = 1.f / sum;
        ps[w][lane] = e0;
        if (k1 < LQ) ps[w][k1] = e1;
        __syncwarp();
        float c0 = 0.f, c1 = 0.f;
        #pragma unroll 4
        for (int k = 0; k < LQ; k++) {
            float p = ps[w][k];
            c0 += p * Vs[k][lane];
            c1 += p * Vs[k][lane + 32];
        }
        size_t base = (size_t)(b * LQ + q) * Dm + h * DKh;
        __half h0 = __float2half_rn(c0 * inv);
        __half h1 = __float2half_rn(c1 * inv);
        cf[base + lane]      = *(unsigned short*)&h0;
        cf[base + lane + 32] = *(unsigned short*)&h1;
        __syncwarp();
    }
}

// ---------------- cross attention (fp16 ctx out) ----------------
#define KS_STR 68
__global__ __launch_bounds__(256)
void cross_attn_kernel(const float* __restrict__ Q, const float* __restrict__ KV,
                       const int* __restrict__ order, unsigned short* __restrict__ cf) {
    float* Ks = csm;
    float* Vs = Ks + NPIXc * KS_STR;
    float* ps = Vs + NPIXc * DKh;
    const int b = blockIdx.x >> 3;
    const int h = blockIdx.x & 7;
    const int tid = threadIdx.x;
    const int lane = tid & 31, w = tid >> 5;
    const int ob = order[b];

    for (int i = tid; i < NPIXc * DKh; i += 256) {
        int t = i >> 6, d = i & 63;
        size_t src = (size_t)(ob * NPIXc + t) * (2 * Dm) + h * DKh + d;
        Ks[t * KS_STR + d] = KV[src];
        Vs[t * DKh + d]    = KV[src + Dm];
    }
    __syncthreads();

    for (int qi = w; qi < LQ / 2; qi += 8) {
        const int q0 = 2 * qi;
        const float* qp = Q + (size_t)(b * LQ + q0) * Dm + h * DKh;
        float qa0 = qp[lane], qb0 = qp[lane + 32];
        float qa1 = qp[Dm + lane], qb1 = qp[Dm + lane + 32];

        float s0[7], s1[7];
        #pragma unroll
        for (int kk = 0; kk < 7; kk++) { s0[kk] = 0.f; s1[kk] = 0.f; }

        #pragma unroll
        for (int d4 = 0; d4 < 16; d4++) {
            float qv0[4], qv1[4];
            #pragma unroll
            for (int j = 0; j < 4; j++) {
                int d = 4 * d4 + j;
                qv0[j] = (d < 32) ? __shfl_sync(0xffffffffu, qa0, d)
                                  : __shfl_sync(0xffffffffu, qb0, d - 32);
                qv1[j] = (d < 32) ? __shfl_sync(0xffffffffu, qa1, d)
                                  : __shfl_sync(0xffffffffu, qb1, d - 32);
            }
            #pragma unroll
            for (int kk = 0; kk < 7; kk++) {
                const int key = kk * 32 + lane;
                float4 kv4 = *(const float4*)(Ks + key * KS_STR + 4 * d4);
                s0[kk] += qv0[0]*kv4.x + qv0[1]*kv4.y + qv0[2]*kv4.z + qv0[3]*kv4.w;
                s1[kk] += qv1[0]*kv4.x + qv1[1]*kv4.y + qv1[2]*kv4.z + qv1[3]*kv4.w;
            }
        }
        float m0 = -1e30f, m1 = -1e30f;
        #pragma unroll
        for (int kk = 0; kk < 7; kk++) {
            const int key = kk * 32 + lane;
            s0[kk] = (key < NPIXc) ? s0[kk] * 0.125f : -1e30f;
            s1[kk] = (key < NPIXc) ? s1[kk] * 0.125f : -1e30f;
            m0 = fmaxf(m0, s0[kk]); m1 = fmaxf(m1, s1[kk]);
        }
        #pragma unroll
        for (int o = 16; o > 0; o >>= 1) {
            m0 = fmaxf(m0, __shfl_xor_sync(0xffffffffu, m0, o));
            m1 = fmaxf(m1, __shfl_xor_sync(0xffffffffu, m1, o));
        }
        float sum0 = 0.f, sum1 = 0.f;
        #pragma unroll
        for (int kk = 0; kk < 7; kk++) {
            const int key = kk * 32 + lane;
            float e0 = __expf(s0[kk] - m0);
            float e1 = __expf(s1[kk] - m1);
            sum0 += e0; sum1 += e1;
            if (key < NPIXc) {
                ps[(2 * w) * NPIXc + key]     = e0;
                ps[(2 * w + 1) * NPIXc + key] = e1;
            }
        }
        #pragma unroll
        for (int o = 16; o > 0; o >>= 1) {
            sum0 += __shfl_xor_sync(0xffffffffu, sum0, o);
            sum1 += __shfl_xor_sync(0xffffffffu, sum1, o);
        }
        float inv0 = 1.f / sum0, inv1 = 1.f / sum1;
        __syncwarp();

        float c00 = 0.f, c01 = 0.f, c10 = 0.f, c11 = 0.f;
        const float* p0p = ps + (2 * w) * NPIXc;
        const float* p1p = ps + (2 * w + 1) * NPIXc;
        #pragma unroll 4
        for (int k = 0; k < NPIXc; k++) {
            float2 vv = *(const float2*)(Vs + k * DKh + 2 * lane);
            float p0 = p0p[k], p1 = p1p[k];
            c00 += p0 * vv.x; c01 += p0 * vv.y;
            c10 += p1 * vv.x; c11 += p1 * vv.y;
        }
        size_t base = (size_t)(b * LQ + q0) * Dm + h * DKh + 2 * lane;
        ((uint32_t*)cf)[base >> 1]        = packh2(c00 * inv0, c01 * inv0);
        ((uint32_t*)cf)[(base + Dm) >> 1] = packh2(c10 * inv1, c11 * inv1);
        __syncwarp();
    }
}
#define CROSS_SMEM ((NPIXc*KS_STR + NPIXc*DKh + 16*NPIXc) * (int)sizeof(float))

// ---------------- LayerNorm(residual + bias), emits fp32 + fp16 ----------------
__global__ __launch_bounds__(256)
void ln_residual_kernel(const float* __restrict__ y, const float* __restrict__ bias,
                        const float* __restrict__ xin, float* __restrict__ xout,
                        unsigned short* __restrict__ xf) {
    int r = blockIdx.x, tid = threadIdx.x;
    __shared__ float red[256];
    size_t base = (size_t)r * Dm;
    float v0 = y[base + tid]       + bias[tid]       + xin[base + tid];
    float v1 = y[base + 256 + tid] + bias[256 + tid] + xin[base + 256 + tid];
    red[tid] = v0 + v1; __syncthreads();
    #pragma unroll
    for (int st = 128; st > 0; st >>= 1) {
        if (tid < st) red[tid] += red[tid + st];
        __syncthreads();
    }
    float m = red[0] * (1.f / Dm);
    __syncthreads();
    float d0 = v0 - m, d1 = v1 - m;
    red[tid] = d0 * d0 + d1 * d1; __syncthreads();
    #pragma unroll
    for (int st = 128; st > 0; st >>= 1) {
        if (tid < st) red[tid] += red[tid + st];
        __syncthreads();
    }
    float inv = rsqrtf(red[0] * (1.f / Dm) + 1e-5f);
    float o0 = d0 * inv, o1 = d1 * inv;
    xout[base + tid]       = o0;
    xout[base + 256 + tid] = o1;
    __half h0 = __float2half_rn(o0);
    __half h1 = __float2half_rn(o1);
    xf[base + tid]       = *(unsigned short*)&h0;
    xf[base + 256 + tid] = *(unsigned short*)&h1;
}

// ---------------- host side ----------------
extern "C" void kernel_launch(void* const* d_in, const int* in_sizes, int n_in,
                              void* d_out, int out_size) {
    const float* encoder_out = (const float*)d_in[0];
    const int*   captions    = (const int*)d_in[1];
    const int*   lengths     = (const int*)d_in[2];
    const float* tgt_emb     = (const float*)d_in[3];
    const float* pos_emb     = (const float*)d_in[4];
    const float* sWq = (const float*)d_in[5];  const float* sbq = (const float*)d_in[6];
    const float* sWk = (const float*)d_in[7];  const float* sbk = (const float*)d_in[8];
    const float* sWv = (const float*)d_in[9];  const float* sbv = (const float*)d_in[10];
    const float* sWo = (const float*)d_in[11]; const float* sbo = (const float*)d_in[12];
    const float* eWq = (const float*)d_in[13]; const float* ebq = (const float*)d_in[14];
    const float* eWk = (const float*)d_in[15]; const float* ebk = (const float*)d_in[16];
    const float* eWv = (const float*)d_in[17]; const float* ebv = (const float*)d_in[18];
    const float* eWo = (const float*)d_in[19]; const float* ebo = (const float*)d_in[20];
    const float* fW1 = (const float*)d_in[21]; const float* fb1 = (const float*)d_in[22];
    const float* fW2 = (const float*)d_in[23]; const float* fb2 = (const float*)d_in[24];
    const float* pW  = (const float*)d_in[25];
    float* out = (float*)d_out;

    float *x, *y, *q, *qkv, *kv, *bqkv, *bkv;
    int *order, *caps;
    unsigned short *xf, *cf, *hf, *efp;
    unsigned short *wsqkvf, *wsof, *weqf, *wekvf, *weof, *wf1f, *wf2f, *wpjf;
    cudaGetSymbolAddress((void**)&x, g_x);       cudaGetSymbolAddress((void**)&y, g_y);
    cudaGetSymbolAddress((void**)&q, g_q);       cudaGetSymbolAddress((void**)&qkv, g_qkv);
    cudaGetSymbolAddress((void**)&kv, g_kv);
    cudaGetSymbolAddress((void**)&order, g_order); cudaGetSymbolAddress((void**)&caps, g_caps);
    cudaGetSymbolAddress((void**)&xf, g_xf);     cudaGetSymbolAddress((void**)&cf, g_cf);
    cudaGetSymbolAddress((void**)&hf, g_hf);     cudaGetSymbolAddress((void**)&efp, g_efp);
    cudaGetSymbolAddress((void**)&wsqkvf, g_wsqkvf); cudaGetSymbolAddress((void**)&wsof, g_wsof);
    cudaGetSymbolAddress((void**)&weqf, g_weqf);     cudaGetSymbolAddress((void**)&wekvf, g_wekvf);
    cudaGetSymbolAddress((void**)&weof, g_weof);     cudaGetSymbolAddress((void**)&wf1f, g_wf1f);
    cudaGetSymbolAddress((void**)&wf2f, g_wf2f);     cudaGetSymbolAddress((void**)&wpjf, g_wpjf);
    cudaGetSymbolAddress((void**)&bqkv, g_bqkv);     cudaGetSymbolAddress((void**)&bkv, g_bkv);

    cudaFuncSetAttribute(cross_attn_kernel, cudaFuncAttributeMaxDynamicSharedMemorySize, CROSS_SMEM);
    cudaFuncSetAttribute(hgemm_kernel<128, false, true,  false>, cudaFuncAttributeMaxDynamicSharedMemorySize, SMEM_H128);
    cudaFuncSetAttribute(hgemm_kernel<128, true,  true,  true>,  cudaFuncAttributeMaxDynamicSharedMemorySize, SMEM_H128);
    cudaFuncSetAttribute(hgemm_kernel<128, false, false, false>, cudaFuncAttributeMaxDynamicSharedMemorySize, SMEM_H128);
    cudaFuncSetAttribute(hgemm_kernel<64,  false, true,  false>, cudaFuncAttributeMaxDynamicSharedMemorySize, SMEM_H64);
    cudaFuncSetAttribute(hgemm_kernel<64,  false, false, false>, cudaFuncAttributeMaxDynamicSharedMemorySize, SMEM_H64);

    // ---- weight prep: transpose + fp16, batched over layers ----
    const size_t DD = (size_t)Dm * Dm, ED = (size_t)ENCc * Dm;
    const dim3 tsb(32, 8);
    const dim3 gdd(Dm/32, Dm/64, NLc);
    tcvt_kernel<<<gdd, tsb>>>(sWq, wsqkvf,        Dm, Dm, DD, 3*DD);
    tcvt_kernel<<<gdd, tsb>>>(sWk, wsqkvf + DD,   Dm, Dm, DD, 3*DD);
    tcvt_kernel<<<gdd, tsb>>>(sWv, wsqkvf + 2*DD, Dm, Dm, DD, 3*DD);
    tcvt_kernel<<<gdd, tsb>>>(sWo, wsof, Dm, Dm, DD, DD);
    tcvt_kernel<<<gdd, tsb>>>(eWq, weqf, Dm, Dm, DD, DD);
    tcvt_kernel<<<gdd, tsb>>>(eWo, weof, Dm, Dm, DD, DD);
    const dim3 gek(Dm/32, ENCc/64, NLc);
    tcvt_kernel<<<gek, tsb>>>(eWk, wekvf,      ENCc, Dm, ED, 2*ED);
    tcvt_kernel<<<gek, tsb>>>(eWv, wekvf + ED, ENCc, Dm, ED, 2*ED);
    tcvt_kernel<<<dim3(FFc/32, Dm/64, NLc), tsb>>>(fW1, wf1f, Dm, FFc, ED, ED);
    tcvt_kernel<<<dim3(Dm/32, FFc/64, NLc), tsb>>>(fW2, wf2f, FFc, Dm, ED, ED);
    cvt16_kernel<<<((VOC*Dm/4) + 255)/256, 256>>>(pW, wpjf, VOC*Dm/4);
    biascat3_kernel<<<(NLc*3*Dm + 255)/256, 256>>>(sbq, sbk, sbv, bqkv);
    biascat2_kernel<<<(NLc*2*Dm + 255)/256, 256>>>(ebk, ebv, bkv);

    // ---- prologue ----
    sort_kernel<<<1, Bz>>>(lengths, order);
    gather_caps_kernel<<<(MROW + 255) / 256, 256>>>(captions, order, caps);
    embed_kernel<<<(MROW * Dm + 255) / 256, 256>>>(caps, tgt_emb, pos_emb, x, xf);
    cvt16_kernel<<<(((size_t)EROW*ENCc/4) + 255)/256, 256>>>(encoder_out, efp, EROW*ENCc/4);

    const dim3 gQKV(12, 26);    // M=3328, N=1536, BM=128
    const dim3 gD64(4, 52);     // M=3328, N=512,  BM=64
    const dim3 gKV(8, 98);      // M=12544, N=1024, BM=128
    const dim3 gFF1(16, 26);    // N=2048, BM=128
    const dim3 gPRJ(250, 26);   // N=32000, BM=128

    for (int l = 0; l < NLc; l++) {
        // ---- self attention ----
        hgemm_kernel<128, false, true, false><<<gQKV, 256, SMEM_H128>>>(xf,
            wsqkvf + l*3*DD, bqkv + l*3*Dm, qkv, nullptr, MROW, 3*Dm, Dm);
        self_attn_kernel<<<Bz * NH, 256>>>(qkv, caps, cf);
        hgemm_kernel<64, false, false, false><<<gD64, 256, SMEM_H64>>>(cf,
            wsof + l*DD, nullptr, y, nullptr, MROW, Dm, Dm);
        ln_residual_kernel<<<MROW, 256>>>(y, sbo + l*Dm, x, x, xf);

        // ---- cross attention ----
        hgemm_kernel<64, false, true, false><<<gD64, 256, SMEM_H64>>>(xf,
            weqf + l*DD, ebq + l*Dm, q, nullptr, MROW, Dm, Dm);
        hgemm_kernel<128, false, true, false><<<gKV, 256, SMEM_H128>>>(efp,
            wekvf + l*2*ED, bkv + l*2*Dm, kv, nullptr, EROW, 2*Dm, ENCc);
        cross_attn_kernel<<<Bz * NH, 256, CROSS_SMEM>>>(q, kv, order, cf);
        hgemm_kernel<64, false, false, false><<<gD64, 256, SMEM_H64>>>(cf,
            weof + l*DD, nullptr, y, nullptr, MROW, Dm, Dm);
        ln_residual_kernel<<<MROW, 256>>>(y, ebo + l*Dm, x, x, xf);

        // ---- FFN ----
        hgemm_kernel<128, true, true, true><<<gFF1, 256, SMEM_H128>>>(xf,
            wf1f + l*ED, fb1 + l*FFc, nullptr, hf, MROW, FFc, Dm);
        hgemm_kernel<64, false, false, false><<<gD64, 256, SMEM_H64>>>(hf,
            wf2f + l*ED, nullptr, y, nullptr, MROW, Dm, FFc);
        ln_residual_kernel<<<MROW, 256>>>(y, fb2 + l*Dm, x, x, xf);
    }

    // ---- vocab projection (x already fp16 in xf) ----
    hgemm_kernel<128, false, false, false><<<gPRJ, 256, SMEM_H128>>>(xf,
        wpjf, nullptr, out, nullptr, MROW, VOC, Dm);
}